// round 8
// baseline (speedup 1.0000x reference)
#include <cuda_runtime.h>
#include <cuda_bf16.h>
#include <cstdint>
#include <math.h>

#define BATCH 16
#define DIM 256
#define STATE 64
#define HIDDEN 1024
#define L 4096
#define NPIX (BATCH*L)
#define PIXBLK (NPIX/64)
#define NSEG 8

// ---------------- scratch ----------------
__device__ float g_t0[BATCH*DIM*L];
__device__ float g_x1[BATCH*DIM*L];
__device__ float g_xn[BATCH*DIM*L];
__device__ float g_x2[BATCH*DIM*L];
__device__ float g_x3[BATCH*DIM*L];
__device__ float g_bcdt[BATCH*192*L];
__device__ float g_bcdt2[BATCH*192*L];
__device__ float g_AB[BATCH*STATE*L];
__device__ float g_hpart[NSEG*BATCH*DIM*STATE];
__device__ float g_h[BATCH*DIM*STATE];
__device__ float g_hz[BATCH*2*DIM*STATE];
__device__ float g_hg[BATCH*DIM*STATE];
__device__ float g_ho[BATCH*DIM*STATE];
__device__ float g_f1t[(size_t)BATCH*L*HIDDEN];          // fc1 output, TRANSPOSED [b*L, 1024] fp32
__device__ __nv_bfloat16 g_x3th[BATCH*L*DIM];
__device__ __nv_bfloat16 g_x3tl[BATCH*L*DIM];
__device__ __nv_bfloat16 g_xnth[BATCH*L*DIM];
__device__ __nv_bfloat16 g_xntl[BATCH*L*DIM];
__device__ __nv_bfloat16 g_f1th[(size_t)BATCH*L*HIDDEN];
__device__ __nv_bfloat16 g_f1tl[(size_t)BATCH*L*HIDDEN];
__device__ __nv_bfloat16 g_w1h[HIDDEN*DIM];
__device__ __nv_bfloat16 g_w1l[HIDDEN*DIM];
__device__ __nv_bfloat16 g_w2h[DIM*HIDDEN];
__device__ __nv_bfloat16 g_w2l[DIM*HIDDEN];
__device__ __nv_bfloat16 g_wbch[256*DIM];                 // bcdt weights padded to 256 rows
__device__ __nv_bfloat16 g_wbcl[256*DIM];

// ---------------- helpers ----------------
__device__ __forceinline__ float2 ffma2(float2 a, float2 b, float2 c) {
    float2 d;
    asm("{\n\t.reg .b64 ra, rb, rc, rd;\n\t"
        "mov.b64 ra, {%2, %3};\n\tmov.b64 rb, {%4, %5};\n\tmov.b64 rc, {%6, %7};\n\t"
        "fma.rn.f32x2 rd, ra, rb, rc;\n\tmov.b64 {%0, %1}, rd;\n\t}"
        : "=f"(d.x), "=f"(d.y)
        : "f"(a.x), "f"(a.y), "f"(b.x), "f"(b.y), "f"(c.x), "f"(c.y));
    return d;
}
__device__ __forceinline__ float sigm(float v) { return 1.f / (1.f + __expf(-v)); }

#define CPA16(dst, src) asm volatile("cp.async.cg.shared.global [%0], [%1], 16;" :: "r"(dst), "l"(src))
#define SWZ(o) ((o) ^ (((o) >> 3) & 0x70u))

__device__ __forceinline__ uint32_t s2u(const void* p) {
    uint32_t a;
    asm("{ .reg .u64 t; cvta.to.shared.u64 t, %1; cvt.u32.u64 %0, t; }" : "=r"(a) : "l"(p));
    return a;
}

#define LDSM4(r, a) \
    asm volatile("ldmatrix.sync.aligned.m8n8.x4.shared.b16 {%0,%1,%2,%3}, [%4];" \
        : "=r"((r)[0]), "=r"((r)[1]), "=r"((r)[2]), "=r"((r)[3]) : "r"(a))

#define MMA16816(d, a, b) \
    asm volatile("mma.sync.aligned.m16n8k16.row.col.f32.bf16.bf16.f32 " \
        "{%0,%1,%2,%3},{%4,%5,%6,%7},{%8,%9},{%0,%1,%2,%3};" \
        : "+f"((d)[0]), "+f"((d)[1]), "+f"((d)[2]), "+f"((d)[3]) \
        : "r"((a)[0]), "r"((a)[1]), "r"((a)[2]), "r"((a)[3]), "r"((b)[0]), "r"((b)[1]))

// ---------------- tensor-core GEMM (mma.sync bf16 hi/lo) -------------------------------------
#define GSMEM 131072
template<int TRANS>
__global__ __launch_bounds__(256) void gemm_mma_kernel(
    const __nv_bfloat16* __restrict__ Wh, const __nv_bfloat16* __restrict__ Wl,
    const __nv_bfloat16* __restrict__ Xh, const __nv_bfloat16* __restrict__ Xl,
    float* __restrict__ Y, const float* __restrict__ bias, int O, int C)
{
    extern __shared__ char dsm[];
    uint32_t sb = s2u(dsm);
    int tid = threadIdx.x, warp = tid >> 5, lane = tid & 31;
    int wm = warp >> 2, wn = warp & 3;
    int bb = blockIdx.x >> 5;
    int l0 = (blockIdx.x & 31) << 7;
    int m0 = blockIdx.y << 7;
    int nchunk = C >> 6;
    size_t rowb = (size_t)bb * 4096 + l0;

    float acc[4][4][4];
#pragma unroll
    for (int i = 0; i < 4; ++i)
#pragma unroll
        for (int j = 0; j < 4; ++j)
#pragma unroll
            for (int q = 0; q < 4; ++q) acc[i][j][q] = 0.f;

    auto issue = [&](int cc, int buf) {
        int c0 = cc << 6;
        uint32_t base = sb + (uint32_t)buf * 65536u;
#pragma unroll
        for (int i = 0; i < 4; ++i) {
            int e = tid + i * 256;
            int row = e >> 3, c16 = e & 7;
            uint32_t sw = SWZ((uint32_t)(row * 128 + c16 * 16));
            CPA16(base + sw,           Wh + (size_t)(m0 + row) * C + c0 + c16 * 8);
            CPA16(base + 16384u + sw,  Wl + (size_t)(m0 + row) * C + c0 + c16 * 8);
            CPA16(base + 32768u + sw,  Xh + (rowb + row) * (size_t)C + c0 + c16 * 8);
            CPA16(base + 49152u + sw,  Xl + (rowb + row) * (size_t)C + c0 + c16 * 8);
        }
        asm volatile("cp.async.commit_group;");
    };

    issue(0, 0);
    for (int cc = 0; cc < nchunk; ++cc) {
        int buf = cc & 1;
        if (cc + 1 < nchunk) {
            issue(cc + 1, buf ^ 1);
            asm volatile("cp.async.wait_group 1;");
        } else {
            asm volatile("cp.async.wait_group 0;");
        }
        __syncthreads();
        uint32_t base = sb + (uint32_t)buf * 65536u;

        int lr = (lane & 7) + ((lane >> 3) & 1) * 8;
        int kb = (lane >> 4) * 8;
#pragma unroll
        for (int kt = 0; kt < 4; ++kt) {
            uint32_t ah[4][4], al[4][4];
#pragma unroll
            for (int mt = 0; mt < 4; ++mt) {
                int row = wm * 64 + mt * 16 + lr;
                uint32_t a = base + SWZ((uint32_t)(row * 128 + (kt * 16 + kb) * 2));
                LDSM4(ah[mt], a);
                LDSM4(al[mt], a + 16384u);
            }
            uint32_t bh[4][2], bl[4][2];
#pragma unroll
            for (int np = 0; np < 2; ++np) {
                int row = wn * 32 + np * 16 + lr;
                uint32_t a = base + 32768u + SWZ((uint32_t)(row * 128 + (kt * 16 + kb) * 2));
                uint32_t r[4], rl[4];
                LDSM4(r, a);
                LDSM4(rl, a + 16384u);
                bh[np * 2][0] = r[0]; bh[np * 2][1] = r[2];
                bh[np * 2 + 1][0] = r[1]; bh[np * 2 + 1][1] = r[3];
                bl[np * 2][0] = rl[0]; bl[np * 2][1] = rl[2];
                bl[np * 2 + 1][0] = rl[1]; bl[np * 2 + 1][1] = rl[3];
            }
#pragma unroll
            for (int mt = 0; mt < 4; ++mt)
#pragma unroll
                for (int nt = 0; nt < 4; ++nt) {
                    MMA16816(acc[mt][nt], ah[mt], bh[nt]);
                    MMA16816(acc[mt][nt], ah[mt], bl[nt]);
                    MMA16816(acc[mt][nt], al[mt], bh[nt]);
                }
        }
        __syncthreads();
    }

    int mrow = (lane >> 2);
    int ncol = (lane & 3) * 2;
    if (TRANS == 0) {
#pragma unroll
        for (int mt = 0; mt < 4; ++mt) {
            int o = m0 + wm * 64 + mt * 16 + mrow;
            float bv0 = (o < O && bias) ? bias[o] : 0.f;
            float bv1 = (o + 8 < O && bias) ? bias[o + 8] : 0.f;
            float* yp0 = Y + ((size_t)bb * O + o) * 4096 + l0 + wn * 32;
            float* yp1 = Y + ((size_t)bb * O + o + 8) * 4096 + l0 + wn * 32;
#pragma unroll
            for (int nt = 0; nt < 4; ++nt) {
                if (o < O)
                    *(float2*)(yp0 + nt * 8 + ncol) = make_float2(acc[mt][nt][0] + bv0, acc[mt][nt][1] + bv0);
                if (o + 8 < O)
                    *(float2*)(yp1 + nt * 8 + ncol) = make_float2(acc[mt][nt][2] + bv1, acc[mt][nt][3] + bv1);
            }
        }
    } else {
        float* st = (float*)dsm;
#pragma unroll
        for (int mt = 0; mt < 4; ++mt) {
            int ob = wm * 64 + mt * 16 + mrow;
#pragma unroll
            for (int nt = 0; nt < 4; ++nt) {
                int pxb = wn * 32 + nt * 8 + ncol;
                st[(size_t)pxb * 132 + ob] = acc[mt][nt][0];
                st[(size_t)(pxb + 1) * 132 + ob] = acc[mt][nt][1];
                st[(size_t)pxb * 132 + ob + 8] = acc[mt][nt][2];
                st[(size_t)(pxb + 1) * 132 + ob + 8] = acc[mt][nt][3];
            }
        }
        __syncthreads();
        int px = tid >> 1, hf = (tid & 1) * 64;
        float* dst = Y + (rowb + px) * (size_t)O + m0 + hf;
        const float* src = st + (size_t)px * 132 + hf;
#pragma unroll
        for (int j = 0; j < 16; ++j)
            *(float4*)(dst + j * 4) = *(const float4*)(src + j * 4);
    }
}

// ---------------- FUSED dwconv3x3 + channel-LN + gated residual (+2nd LN) + transposed split -
// One block = one image row (64 px) x 256 ch. MODE 0: split gated output. MODE 1: 2nd LN, split it.
#define DWSM (65536 + 2 * 64 * 258 * 2)
template<int MODE>
__global__ __launch_bounds__(256) void dwln_kernel(
    const float* __restrict__ in, const float* __restrict__ w9,
    const float* __restrict__ lnw, const float* __restrict__ lnb,
    const float* __restrict__ alpha_row,
    float* __restrict__ out_cm,
    const float* __restrict__ lnw2, const float* __restrict__ lnb2,
    float* __restrict__ out2_cm,
    __nv_bfloat16* __restrict__ oh, __nv_bfloat16* __restrict__ ol)
{
    extern __shared__ char sm[];
    float* convs = (float*)sm;
    __nv_bfloat16* sh = (__nv_bfloat16*)(sm + 65536);
    __nv_bfloat16* sl = (__nv_bfloat16*)(sm + 65536 + 64 * 258 * 2);
    __shared__ float r1[4][64], r2[4][64];
    int px = threadIdx.x, cg = threadIdx.y;
    int Pg = blockIdx.x * 64;
    int b = Pg >> 12, l0 = Pg & 4095, hh = l0 >> 6;
    size_t base = (size_t)(b * DIM) * L + l0 + px;

    // pass 1: depthwise conv + stats
    float s1 = 0.f, s2 = 0.f;
#pragma unroll 4
    for (int c = 0; c < 64; ++c) {
        int ch = cg * 64 + c;
        const float* ip = in + (size_t)(b * DIM + ch) * L;
        const float* wp = w9 + ch * 9;
        float acc = 0.f;
#pragma unroll
        for (int ky = 0; ky < 3; ++ky) {
            int y = hh + ky - 1;
            if ((unsigned)y < 64u) {
                const float* rp = ip + y * 64;
                float vl = (px > 0) ? __ldg(rp + px - 1) : 0.f;
                float vm = __ldg(rp + px);
                float vr = (px < 63) ? __ldg(rp + px + 1) : 0.f;
                acc += __ldg(wp + ky * 3) * vl + __ldg(wp + ky * 3 + 1) * vm + __ldg(wp + ky * 3 + 2) * vr;
            }
        }
        convs[ch * 64 + px] = acc;
        s1 += acc; s2 += acc * acc;
    }
    r1[cg][px] = s1; r2[cg][px] = s2;
    __syncthreads();
    float u = (r1[0][px] + r1[1][px] + r1[2][px] + r1[3][px]) * (1.f / 256.f);
    float rs = rsqrtf((r2[0][px] + r2[1][px] + r2[2][px] + r2[3][px]) * (1.f / 256.f) - u * u + 1e-5f);

    // pass 2: gated residual; MODE0 split xv, MODE1 save xv for 2nd LN
    float b1 = 0.f, b2 = 0.f;
#pragma unroll 4
    for (int c = 0; c < 64; ++c) {
        int ch = cg * 64 + c;
        size_t idx = base + (size_t)ch * L;
        float cv = convs[ch * 64 + px];
        float nv = lnw[ch] * (cv - u) * rs + lnb[ch];
        float a = sigm(alpha_row[ch]);
        float p = in[idx];
        float xv = fmaf(a, nv - p, p);
        out_cm[idx] = xv;
        if (MODE == 1) {
            convs[ch * 64 + px] = xv;
            b1 += xv; b2 += xv * xv;
        } else {
            __nv_bfloat16 hbf = __float2bfloat16(xv);
            sh[px * 258 + ch] = hbf;
            sl[px * 258 + ch] = __float2bfloat16(xv - __bfloat162float(hbf));
        }
    }
    if (MODE == 1) {
        __syncthreads();
        r1[cg][px] = b1; r2[cg][px] = b2;
        __syncthreads();
        float u1 = (r1[0][px] + r1[1][px] + r1[2][px] + r1[3][px]) * (1.f / 256.f);
        float rs2 = rsqrtf((r2[0][px] + r2[1][px] + r2[2][px] + r2[3][px]) * (1.f / 256.f) - u1 * u1 + 1e-5f);
#pragma unroll 4
        for (int c = 0; c < 64; ++c) {
            int ch = cg * 64 + c;
            float xv = convs[ch * 64 + px];
            float nv = lnw2[ch] * (xv - u1) * rs2 + lnb2[ch];
            out2_cm[base + (size_t)ch * L] = nv;
            __nv_bfloat16 hbf = __float2bfloat16(nv);
            sh[px * 258 + ch] = hbf;
            sl[px * 258 + ch] = __float2bfloat16(nv - __bfloat162float(hbf));
        }
    }
    __syncthreads();

    // transposed coalesced writeout: thread owns (row, seg) -> 64 channels = 128 B = 8 uint4
    int t = cg * 64 + px;
    int row = t >> 2, seg = t & 3;
    size_t rowg = ((size_t)b * L + l0 + row) * 256 + seg * 64;
    const uint32_t* s32h = (const uint32_t*)((const char*)sh + (row * 258 + seg * 64) * 2);
    const uint32_t* s32l = (const uint32_t*)((const char*)sl + (row * 258 + seg * 64) * 2);
    uint4* dh = (uint4*)(oh + rowg);
    uint4* dl = (uint4*)(ol + rowg);
#pragma unroll
    for (int j = 0; j < 8; ++j) {
        dh[j] = make_uint4(s32h[j * 4], s32h[j * 4 + 1], s32h[j * 4 + 2], s32h[j * 4 + 3]);
        dl[j] = make_uint4(s32l[j * 4], s32l[j * 4 + 1], s32l[j * 4 + 2], s32l[j * 4 + 3]);
    }
}

// ---------------- fused LN(1024) + SiLU + bf16 hi/lo split ----------------
__global__ __launch_bounds__(256) void ln_silu_split_kernel(
    const float* __restrict__ f1t, __nv_bfloat16* __restrict__ oh, __nv_bfloat16* __restrict__ ol,
    const float* __restrict__ lnw, const float* __restrict__ lnb)
{
    int warp = threadIdx.x >> 5, lane = threadIdx.x & 31;
    size_t px = (size_t)blockIdx.x * 8 + warp;
    const float4* row = (const float4*)(f1t + px * 1024);
    const float4* w4 = (const float4*)lnw;
    const float4* b4 = (const float4*)lnb;

    float4 v[8];
    float s1 = 0.f, s2 = 0.f;
#pragma unroll
    for (int i = 0; i < 8; ++i) {
        v[i] = row[lane + i * 32];
        s1 += v[i].x + v[i].y + v[i].z + v[i].w;
        s2 += v[i].x * v[i].x + v[i].y * v[i].y + v[i].z * v[i].z + v[i].w * v[i].w;
    }
#pragma unroll
    for (int st = 16; st; st >>= 1) {
        s1 += __shfl_xor_sync(0xFFFFFFFF, s1, st);
        s2 += __shfl_xor_sync(0xFFFFFFFF, s2, st);
    }
    float u = s1 * (1.f / 1024.f);
    float rs = rsqrtf(s2 * (1.f / 1024.f) - u * u + 1e-5f);

    uint2* oh2 = (uint2*)(oh + px * 1024);
    uint2* ol2 = (uint2*)(ol + px * 1024);
#pragma unroll
    for (int i = 0; i < 8; ++i) {
        int c4 = lane + i * 32;
        float4 wv = w4[c4], bv = b4[c4];
        float g[4];
        g[0] = wv.x * (v[i].x - u) * rs + bv.x;
        g[1] = wv.y * (v[i].y - u) * rs + bv.y;
        g[2] = wv.z * (v[i].z - u) * rs + bv.z;
        g[3] = wv.w * (v[i].w - u) * rs + bv.w;
#pragma unroll
        for (int j = 0; j < 4; ++j) g[j] = g[j] * sigm(g[j]);
        __nv_bfloat16 h0 = __float2bfloat16(g[0]), h1 = __float2bfloat16(g[1]);
        __nv_bfloat16 h2 = __float2bfloat16(g[2]), h3 = __float2bfloat16(g[3]);
        uint2 hp, lp;
        hp.x = (uint32_t)__bfloat16_as_ushort(h0) | ((uint32_t)__bfloat16_as_ushort(h1) << 16);
        hp.y = (uint32_t)__bfloat16_as_ushort(h2) | ((uint32_t)__bfloat16_as_ushort(h3) << 16);
        __nv_bfloat16 e0 = __float2bfloat16(g[0] - __bfloat162float(h0));
        __nv_bfloat16 e1 = __float2bfloat16(g[1] - __bfloat162float(h1));
        __nv_bfloat16 e2 = __float2bfloat16(g[2] - __bfloat162float(h2));
        __nv_bfloat16 e3 = __float2bfloat16(g[3] - __bfloat162float(h3));
        lp.x = (uint32_t)__bfloat16_as_ushort(e0) | ((uint32_t)__bfloat16_as_ushort(e1) << 16);
        lp.y = (uint32_t)__bfloat16_as_ushort(e2) | ((uint32_t)__bfloat16_as_ushort(e3) << 16);
        oh2[c4] = hp;
        ol2[c4] = lp;
    }
}

__global__ __launch_bounds__(256) void wsplit_kernel(
    const float* __restrict__ w, __nv_bfloat16* __restrict__ wh, __nv_bfloat16* __restrict__ wl)
{
    int i = blockIdx.x * 256 + threadIdx.x;
    float f = w[i];
    __nv_bfloat16 h = __float2bfloat16(f);
    wh[i] = h;
    wl[i] = __float2bfloat16(f - __bfloat162float(h));
}

__global__ __launch_bounds__(256) void wsplit_pad_kernel(
    const float* __restrict__ w, __nv_bfloat16* __restrict__ wh, __nv_bfloat16* __restrict__ wl)
{
    int i = blockIdx.x * 256 + threadIdx.x;
    int row = i >> 8;
    float f = (row < 192) ? w[i] : 0.f;
    __nv_bfloat16 h = __float2bfloat16(f);
    wh[i] = h;
    wl[i] = __float2bfloat16(f - __bfloat162float(h));
}

// ---------------- depthwise 3x3 conv (mixer path only) ----------------
__global__ __launch_bounds__(256) void dwconv8_kernel(
    const float* __restrict__ in, const float* __restrict__ w,
    const float* __restrict__ bias, float* __restrict__ out, int C)
{
    int t = blockIdx.x * 256 + threadIdx.x;
    int x0 = (t & 7) * 8;
    int r = t >> 3;
    int hh = r & 63;
    int bc = r >> 6;
    int c = bc - (bc / C) * C;
    const float* wp = w + c * 9;
    float wr[9];
#pragma unroll
    for (int i = 0; i < 9; ++i) wr[i] = wp[i];
    const float* ip = in + (long)bc * 4096;
    float bv = bias ? bias[c] : 0.f;
    float acc[8];
#pragma unroll
    for (int j = 0; j < 8; ++j) acc[j] = bv;
#pragma unroll
    for (int ky = 0; ky < 3; ++ky) {
        int y = hh + ky - 1;
        if ((unsigned)y < 64u) {
            const float* rp = ip + y * 64 + x0;
            float4 a = *(const float4*)rp;
            float4 b4 = *(const float4*)(rp + 4);
            float v[10];
            v[0] = (x0 > 0) ? rp[-1] : 0.f;
            v[1] = a.x; v[2] = a.y; v[3] = a.z; v[4] = a.w;
            v[5] = b4.x; v[6] = b4.y; v[7] = b4.z; v[8] = b4.w;
            v[9] = (x0 < 56) ? rp[8] : 0.f;
            float k0 = wr[ky * 3 + 0], k1 = wr[ky * 3 + 1], k2 = wr[ky * 3 + 2];
#pragma unroll
            for (int j = 0; j < 8; ++j)
                acc[j] += k0 * v[j] + k1 * v[j + 1] + k2 * v[j + 2];
        }
    }
    float* op = out + (long)bc * 4096 + hh * 64 + x0;
    *(float4*)op = make_float4(acc[0], acc[1], acc[2], acc[3]);
    *(float4*)(op + 4) = make_float4(acc[4], acc[5], acc[6], acc[7]);
}

// ---------------- plain channel-LN + gated residual (final FFN LN) ----------------
__global__ __launch_bounds__(256) void ln_gate_kernel(
    const float* __restrict__ t, const float* __restrict__ prev,
    const float* __restrict__ lnw, const float* __restrict__ lnb,
    const float* __restrict__ alpha_row, float* __restrict__ out)
{
    __shared__ float r1[4][64], r2[4][64];
    int px = threadIdx.x, cg = threadIdx.y;
    int Pg = blockIdx.x * 64;
    int b = Pg >> 12, l0 = Pg & 4095;
    int base = b * DIM * L + l0 + px;

    float s1 = 0.f, s2 = 0.f;
#pragma unroll 8
    for (int c = 0; c < 64; ++c) {
        float v = t[base + (cg * 64 + c) * L];
        s1 += v; s2 += v * v;
    }
    r1[cg][px] = s1; r2[cg][px] = s2;
    __syncthreads();
    float u = (r1[0][px] + r1[1][px] + r1[2][px] + r1[3][px]) * (1.f / 256.f);
    float rs = rsqrtf((r2[0][px] + r2[1][px] + r2[2][px] + r2[3][px]) * (1.f / 256.f) - u * u + 1e-5f);

#pragma unroll 8
    for (int c = 0; c < 64; ++c) {
        int ch = cg * 64 + c;
        int idx = base + ch * L;
        float v = t[idx];
        float nv = lnw[ch] * (v - u) * rs + lnb[ch];
        float a = sigm(alpha_row[ch]);
        float p = prev[idx];
        out[idx] = fmaf(a, nv - p, p);
    }
}

// ---------------- small GEMM for Ld=64 ----------------
template<int OT>
__global__ __launch_bounds__(256) void gemm1x1_kernel(
    const float* __restrict__ W, const float* __restrict__ bias,
    const float* __restrict__ X, float* __restrict__ Y,
    int O, int C, int Ld)
{
    constexpr int PT = OT / 8;
    constexpr int KC = 32;
    __shared__ float Ws[OT * KC];
    int tid = threadIdx.x;
    int pxl = tid & 31;
    int og = tid >> 5;
    int b = (blockIdx.x * 64) / Ld;
    int l0 = (blockIdx.x * 64) % Ld;
    int ob = blockIdx.y * OT;
    const float* Xb = X + (b * C) * Ld + l0 + pxl * 2;

    float2 acc[PT];
#pragma unroll
    for (int i = 0; i < PT; ++i) acc[i] = make_float2(0.f, 0.f);

    for (int c0 = 0; c0 < C; c0 += KC) {
        __syncthreads();
#pragma unroll
        for (int e = tid; e < OT * KC; e += 256) {
            int ol = e >> 5, k = e & 31;
            Ws[e] = W[(ob + ol) * C + c0 + k];
        }
        __syncthreads();
#pragma unroll 4
        for (int k = 0; k < KC; ++k) {
            float2 xv = *reinterpret_cast<const float2*>(Xb + (c0 + k) * Ld);
#pragma unroll
            for (int i = 0; i < PT; ++i) {
                float wv = Ws[(og * PT + i) * KC + k];
                acc[i] = ffma2(make_float2(wv, wv), xv, acc[i]);
            }
        }
    }
#pragma unroll
    for (int i = 0; i < PT; ++i) {
        int o = ob + og * PT + i;
        float bv = bias ? bias[o] : 0.f;
        float2 r = make_float2(acc[i].x + bv, acc[i].y + bv);
        *reinterpret_cast<float2*>(Y + (b * O + o) * Ld + l0 + pxl * 2) = r;
    }
}

// ---------------- softmax over L, AB = softmax(dt)*Bm ----------------
__global__ __launch_bounds__(256) void softmax_ab_kernel(
    const float* __restrict__ bcdt2, float* __restrict__ AB)
{
    int bs = blockIdx.x;
    int b = bs >> 6, s = bs & 63;
    const float* dt = bcdt2 + (b * 192 + 128 + s) * L;
    const float* Bm = bcdt2 + (b * 192 + s) * L;
    float* out = AB + (b * 64 + s) * L;
    __shared__ float e[L];
    __shared__ float red[256];
    int tid = threadIdx.x;

    float m = -1e30f;
    for (int l = tid; l < L; l += 256) { float v = dt[l]; e[l] = v; m = fmaxf(m, v); }
    red[tid] = m; __syncthreads();
    for (int st = 128; st; st >>= 1) { if (tid < st) red[tid] = fmaxf(red[tid], red[tid + st]); __syncthreads(); }
    m = red[0];
    __syncthreads();

    float sm = 0.f;
    for (int l = tid; l < L; l += 256) { float ev = __expf(e[l] - m); e[l] = ev; sm += ev; }
    red[tid] = sm; __syncthreads();
    for (int st = 128; st; st >>= 1) { if (tid < st) red[tid] += red[tid + st]; __syncthreads(); }
    float inv = 1.f / red[0];

    for (int l = tid; l < L; l += 256) out[l] = e[l] * inv * Bm[l];
}

// ---------------- h partials ----------------
__global__ __launch_bounds__(256) void hgemm_kernel(
    const float* __restrict__ xn, const float* __restrict__ AB, float* __restrict__ hpart)
{
    int b = blockIdx.x, dtile = blockIdx.y, seg = blockIdx.z;
    int d0 = dtile * 64;
    int lb = seg * (L / NSEG);
    __shared__ float xs[64][17], as[64][17];
    int tid = threadIdx.x, tx = tid & 15, ty = tid >> 4;
    float acc[4][4];
#pragma unroll
    for (int i = 0; i < 4; ++i)
#pragma unroll
        for (int j = 0; j < 4; ++j) acc[i][j] = 0.f;

    const float* xp = xn + (b * DIM + d0) * L + lb;
    const float* ap = AB + (b * 64) * L + lb;

    for (int k0 = 0; k0 < L / NSEG; k0 += 16) {
        __syncthreads();
#pragma unroll
        for (int e = tid; e < 1024; e += 256) {
            int r = e >> 4, c = e & 15;
            xs[r][c] = xp[r * L + k0 + c];
            as[r][c] = ap[r * L + k0 + c];
        }
        __syncthreads();
#pragma unroll
        for (int k = 0; k < 16; ++k) {
            float xa[4], bb[4];
#pragma unroll
            for (int i = 0; i < 4; ++i) xa[i] = xs[ty * 4 + i][k];
#pragma unroll
            for (int j = 0; j < 4; ++j) bb[j] = as[tx * 4 + j][k];
#pragma unroll
            for (int i = 0; i < 4; ++i)
#pragma unroll
                for (int j = 0; j < 4; ++j) acc[i][j] += xa[i] * bb[j];
        }
    }
    float* hp = hpart + seg * (BATCH * DIM * STATE);
#pragma unroll
    for (int i = 0; i < 4; ++i)
#pragma unroll
        for (int j = 0; j < 4; ++j)
            hp[(b * DIM + d0 + ty * 4 + i) * STATE + tx * 4 + j] = acc[i][j];
}

__global__ __launch_bounds__(256) void hreduce_kernel(
    const float* __restrict__ hpart, float* __restrict__ h)
{
    int idx = blockIdx.x * 256 + threadIdx.x;
    float s = 0.f;
#pragma unroll
    for (int g = 0; g < NSEG; ++g) s += hpart[g * (BATCH * DIM * STATE) + idx];
    h[idx] = s;
}

__global__ __launch_bounds__(256) void gate_kernel(
    const float* __restrict__ hz, float* __restrict__ hg)
{
    int idx = blockIdx.x * 256 + threadIdx.x;
    int s = idx & 63;
    int c = (idx >> 6) & 255;
    int b = idx >> 14;
    float hp = hz[(b * 512 + c) * 64 + s];
    float z = hz[(b * 512 + 256 + c) * 64 + s];
    hg[idx] = hp * z * sigm(z);
}

// ---------------- y = ho @ Cm ; x2 ----------------
__global__ __launch_bounds__(256) void y_fuse_kernel(
    const float* __restrict__ ho, const float* __restrict__ bcdt2,
    const float* __restrict__ xn, const float* __restrict__ x1,
    const float* __restrict__ Dp, const float* __restrict__ alpha1,
    float* __restrict__ x2)
{
    __shared__ float hos[16][257];
    int tid = threadIdx.x;
    int px = tid & 63, dg = tid >> 6;
    int Pg = blockIdx.x * 64;
    int b = Pg >> 12, l0 = Pg & 4095;
    const float* hob = ho + b * DIM * STATE;
    const float* cm = bcdt2 + (b * 192 + 64) * L + l0 + px;

    float acc[64];
#pragma unroll
    for (int j = 0; j < 64; ++j) acc[j] = 0.f;

    for (int sc = 0; sc < 4; ++sc) {
        __syncthreads();
#pragma unroll
        for (int e = tid; e < 4096; e += 256) {
            int d = e >> 4, s = e & 15;
            hos[s][d] = hob[d * 64 + sc * 16 + s];
        }
        __syncthreads();
#pragma unroll
        for (int s = 0; s < 16; ++s) {
            float cmv = cm[(sc * 16 + s) * L];
#pragma unroll
            for (int j = 0; j < 64; ++j)
                acc[j] += hos[s][dg * 64 + j] * cmv;
        }
    }
#pragma unroll
    for (int j = 0; j < 64; ++j) {
        int d = dg * 64 + j;
        int idx = (b * DIM + d) * L + l0 + px;
        float y = acc[j] + xn[idx] * Dp[d];
        float a = sigm(alpha1[d]);
        float p = x1[idx];
        x2[idx] = fmaf(a, y - p, p);
    }
}

__global__ __launch_bounds__(256) void copy_kernel(
    const float* __restrict__ src, float* __restrict__ dst)
{
    int idx = blockIdx.x * 256 + threadIdx.x;
    dst[idx] = src[idx];
}

// ---------------- host launcher ----------------
extern "C" void kernel_launch(void* const* d_in, const int* in_sizes, int n_in,
                              void* d_out, int out_size)
{
    const float* x        = (const float*)d_in[0];
    const float* alpha    = (const float*)d_in[1];
    const float* ln_w     = (const float*)d_in[2];
    const float* ln_b     = (const float*)d_in[3];
    const float* dw1_w    = (const float*)d_in[4];
    const float* dw1_ln_w = (const float*)d_in[5];
    const float* dw1_ln_b = (const float*)d_in[6];
    const float* dw2_w    = (const float*)d_in[7];
    const float* dw2_ln_w = (const float*)d_in[8];
    const float* dw2_ln_b = (const float*)d_in[9];
    const float* bcdt_w   = (const float*)d_in[10];
    const float* bcdt_b   = (const float*)d_in[11];
    const float* dwm_w    = (const float*)d_in[12];
    const float* dwm_b    = (const float*)d_in[13];
    const float* hz_w     = (const float*)d_in[14];
    const float* hz_b     = (const float*)d_in[15];
    const float* outp_w   = (const float*)d_in[16];
    const float* outp_b   = (const float*)d_in[17];
    const float* Dp       = (const float*)d_in[19];
    const float* fc1_w    = (const float*)d_in[20];
    const float* fc1_ln_w = (const float*)d_in[21];
    const float* fc1_ln_b = (const float*)d_in[22];
    const float* fc2_w    = (const float*)d_in[23];
    const float* fc2_ln_w = (const float*)d_in[24];
    const float* fc2_ln_b = (const float*)d_in[25];
    float* out = (float*)d_out;

    float *t0, *x1, *xn, *x2, *x3, *bc, *bc2, *ab, *hpart, *h, *hz, *hg, *ho, *f1t;
    __nv_bfloat16 *x3th, *x3tl, *xnth, *xntl, *f1th, *f1tl, *w1h, *w1l, *w2h, *w2l, *wbch, *wbcl;
    cudaGetSymbolAddress((void**)&t0, g_t0);
    cudaGetSymbolAddress((void**)&x1, g_x1);
    cudaGetSymbolAddress((void**)&xn, g_xn);
    cudaGetSymbolAddress((void**)&x2, g_x2);
    cudaGetSymbolAddress((void**)&x3, g_x3);
    cudaGetSymbolAddress((void**)&bc, g_bcdt);
    cudaGetSymbolAddress((void**)&bc2, g_bcdt2);
    cudaGetSymbolAddress((void**)&ab, g_AB);
    cudaGetSymbolAddress((void**)&hpart, g_hpart);
    cudaGetSymbolAddress((void**)&h, g_h);
    cudaGetSymbolAddress((void**)&hz, g_hz);
    cudaGetSymbolAddress((void**)&hg, g_hg);
    cudaGetSymbolAddress((void**)&ho, g_ho);
    cudaGetSymbolAddress((void**)&f1t, g_f1t);
    cudaGetSymbolAddress((void**)&x3th, g_x3th);
    cudaGetSymbolAddress((void**)&x3tl, g_x3tl);
    cudaGetSymbolAddress((void**)&xnth, g_xnth);
    cudaGetSymbolAddress((void**)&xntl, g_xntl);
    cudaGetSymbolAddress((void**)&f1th, g_f1th);
    cudaGetSymbolAddress((void**)&f1tl, g_f1tl);
    cudaGetSymbolAddress((void**)&w1h, g_w1h);
    cudaGetSymbolAddress((void**)&w1l, g_w1l);
    cudaGetSymbolAddress((void**)&w2h, g_w2h);
    cudaGetSymbolAddress((void**)&w2l, g_w2l);
    cudaGetSymbolAddress((void**)&wbch, g_wbch);
    cudaGetSymbolAddress((void**)&wbcl, g_wbcl);

    cudaFuncSetAttribute(gemm_mma_kernel<0>, cudaFuncAttributeMaxDynamicSharedMemorySize, GSMEM);
    cudaFuncSetAttribute(gemm_mma_kernel<1>, cudaFuncAttributeMaxDynamicSharedMemorySize, GSMEM);
    cudaFuncSetAttribute(dwln_kernel<0>, cudaFuncAttributeMaxDynamicSharedMemorySize, DWSM);
    cudaFuncSetAttribute(dwln_kernel<1>, cudaFuncAttributeMaxDynamicSharedMemorySize, DWSM);

    dim3 blk2(64, 4);

    // weight splits
    wsplit_kernel<<<HIDDEN * DIM / 256, 256>>>(fc1_w, w1h, w1l);
    wsplit_kernel<<<DIM * HIDDEN / 256, 256>>>(fc2_w, w2h, w2l);
    wsplit_pad_kernel<<<256 * DIM / 256, 256>>>(bcdt_w, wbch, wbcl);

    // sub-layer 1 (fused): x1, xn, xnth/xntl
    dwln_kernel<1><<<PIXBLK, blk2, DWSM>>>(x, dw1_w, dw1_ln_w, dw1_ln_b, alpha, x1,
                                           ln_w, ln_b, xn, xnth, xntl);

    // HSMSSD mixer
    gemm_mma_kernel<0><<<dim3(NPIX / 128, 2), 256, GSMEM>>>(wbch, wbcl, xnth, xntl, bc, bcdt_b, 192, 256);
    dwconv8_kernel<<<BATCH * 192 * L / 8 / 256, 256>>>(bc, dwm_w, dwm_b, bc2, 192);
    softmax_ab_kernel<<<BATCH * 64, 256>>>(bc2, ab);
    hgemm_kernel<<<dim3(BATCH, 4, NSEG), 256>>>(xn, ab, hpart);
    hreduce_kernel<<<BATCH * DIM * STATE / 256, 256>>>(hpart, h);
    gemm1x1_kernel<128><<<dim3(BATCH, 4), 256>>>(hz_w, hz_b, h, hz, 512, 256, 64);
    gate_kernel<<<BATCH * DIM * STATE / 256, 256>>>(hz, hg);
    gemm1x1_kernel<128><<<dim3(BATCH, 2), 256>>>(outp_w, outp_b, hg, ho, 256, 256, 64);
    y_fuse_kernel<<<PIXBLK, 256>>>(ho, bc2, xn, x1, Dp, alpha + 256, x2);

    // sub-layer 3 (fused): x3, x3th/x3tl
    dwln_kernel<0><<<PIXBLK, blk2, DWSM>>>(x2, dw2_w, dw2_ln_w, dw2_ln_b, alpha + 512, x3,
                                           nullptr, nullptr, nullptr, x3th, x3tl);

    // FFN: fc1 (transposed out) -> fused LN+SiLU+split -> fc2 -> final LN+gate
    gemm_mma_kernel<1><<<dim3(NPIX / 128, HIDDEN / 128), 256, GSMEM>>>(w1h, w1l, x3th, x3tl, f1t, nullptr, HIDDEN, 256);
    ln_silu_split_kernel<<<NPIX / 8, 256>>>(f1t, f1th, f1tl, fc1_ln_w, fc1_ln_b);
    gemm_mma_kernel<0><<<dim3(NPIX / 128, 2), 256, GSMEM>>>(w2h, w2l, f1th, f1tl, t0, nullptr, 256, 1024);
    ln_gate_kernel<<<PIXBLK, blk2>>>(t0, x3, fc2_ln_w, fc2_ln_b, alpha + 768, out);

    // second output: h
    if (out_size >= BATCH * DIM * L + BATCH * DIM * STATE)
        copy_kernel<<<BATCH * DIM * STATE / 256, 256>>>(h, out + BATCH * DIM * L);
}

// round 9
// speedup vs baseline: 1.3339x; 1.3339x over previous
#include <cuda_runtime.h>
#include <cuda_bf16.h>
#include <cstdint>
#include <math.h>

#define BATCH 16
#define DIM 256
#define STATE 64
#define HIDDEN 1024
#define L 4096
#define NPIX (BATCH*L)
#define PIXBLK (NPIX/64)
#define NSEG 8

// ---------------- scratch ----------------
__device__ float g_t0[BATCH*DIM*L];
__device__ float g_x1[BATCH*DIM*L];
__device__ float g_xn[BATCH*DIM*L];
__device__ float g_x2[BATCH*DIM*L];
__device__ float g_x3[BATCH*DIM*L];
__device__ float g_bcdt[BATCH*192*L];
__device__ float g_bcdt2[BATCH*192*L];
__device__ float g_AB[BATCH*STATE*L];
__device__ float g_hpart[NSEG*BATCH*DIM*STATE];
__device__ float g_h[BATCH*DIM*STATE];
__device__ float g_hz[BATCH*2*DIM*STATE];
__device__ float g_hg[BATCH*DIM*STATE];
__device__ float g_ho[BATCH*DIM*STATE];
__device__ float g_f1t[(size_t)BATCH*L*HIDDEN];          // fc1 output, TRANSPOSED [b*L, 1024] fp32
__device__ __nv_bfloat16 g_x3th[BATCH*L*DIM];
__device__ __nv_bfloat16 g_x3tl[BATCH*L*DIM];
__device__ __nv_bfloat16 g_xnth[BATCH*L*DIM];
__device__ __nv_bfloat16 g_xntl[BATCH*L*DIM];
__device__ __nv_bfloat16 g_f1th[(size_t)BATCH*L*HIDDEN];
__device__ __nv_bfloat16 g_f1tl[(size_t)BATCH*L*HIDDEN];
__device__ __nv_bfloat16 g_w1h[HIDDEN*DIM];
__device__ __nv_bfloat16 g_w1l[HIDDEN*DIM];
__device__ __nv_bfloat16 g_w2h[DIM*HIDDEN];
__device__ __nv_bfloat16 g_w2l[DIM*HIDDEN];
__device__ __nv_bfloat16 g_wbch[256*DIM];                 // bcdt weights padded to 256 rows
__device__ __nv_bfloat16 g_wbcl[256*DIM];

// ---------------- helpers ----------------
__device__ __forceinline__ float2 ffma2(float2 a, float2 b, float2 c) {
    float2 d;
    asm("{\n\t.reg .b64 ra, rb, rc, rd;\n\t"
        "mov.b64 ra, {%2, %3};\n\tmov.b64 rb, {%4, %5};\n\tmov.b64 rc, {%6, %7};\n\t"
        "fma.rn.f32x2 rd, ra, rb, rc;\n\tmov.b64 {%0, %1}, rd;\n\t}"
        : "=f"(d.x), "=f"(d.y)
        : "f"(a.x), "f"(a.y), "f"(b.x), "f"(b.y), "f"(c.x), "f"(c.y));
    return d;
}
__device__ __forceinline__ float sigm(float v) { return 1.f / (1.f + __expf(-v)); }

#define CPA16(dst, src) asm volatile("cp.async.cg.shared.global [%0], [%1], 16;" :: "r"(dst), "l"(src))
#define SWZ(o) ((o) ^ (((o) >> 3) & 0x70u))

__device__ __forceinline__ uint32_t s2u(const void* p) {
    uint32_t a;
    asm("{ .reg .u64 t; cvta.to.shared.u64 t, %1; cvt.u32.u64 %0, t; }" : "=r"(a) : "l"(p));
    return a;
}

#define LDSM4(r, a) \
    asm volatile("ldmatrix.sync.aligned.m8n8.x4.shared.b16 {%0,%1,%2,%3}, [%4];" \
        : "=r"((r)[0]), "=r"((r)[1]), "=r"((r)[2]), "=r"((r)[3]) : "r"(a))

#define MMA16816(d, a, b) \
    asm volatile("mma.sync.aligned.m16n8k16.row.col.f32.bf16.bf16.f32 " \
        "{%0,%1,%2,%3},{%4,%5,%6,%7},{%8,%9},{%0,%1,%2,%3};" \
        : "+f"((d)[0]), "+f"((d)[1]), "+f"((d)[2]), "+f"((d)[3]) \
        : "r"((a)[0]), "r"((a)[1]), "r"((a)[2]), "r"((a)[3]), "r"((b)[0]), "r"((b)[1]))

// ---------------- tensor-core GEMM (mma.sync bf16 hi/lo) -------------------------------------
#define GSMEM 131072
template<int TRANS>
__global__ __launch_bounds__(256) void gemm_mma_kernel(
    const __nv_bfloat16* __restrict__ Wh, const __nv_bfloat16* __restrict__ Wl,
    const __nv_bfloat16* __restrict__ Xh, const __nv_bfloat16* __restrict__ Xl,
    float* __restrict__ Y, const float* __restrict__ bias, int O, int C)
{
    extern __shared__ char dsm[];
    uint32_t sb = s2u(dsm);
    int tid = threadIdx.x, warp = tid >> 5, lane = tid & 31;
    int wm = warp >> 2, wn = warp & 3;
    int bb = blockIdx.x >> 5;
    int l0 = (blockIdx.x & 31) << 7;
    int m0 = blockIdx.y << 7;
    int nchunk = C >> 6;
    size_t rowb = (size_t)bb * 4096 + l0;

    float acc[4][4][4];
#pragma unroll
    for (int i = 0; i < 4; ++i)
#pragma unroll
        for (int j = 0; j < 4; ++j)
#pragma unroll
            for (int q = 0; q < 4; ++q) acc[i][j][q] = 0.f;

    auto issue = [&](int cc, int buf) {
        int c0 = cc << 6;
        uint32_t base = sb + (uint32_t)buf * 65536u;
#pragma unroll
        for (int i = 0; i < 4; ++i) {
            int e = tid + i * 256;
            int row = e >> 3, c16 = e & 7;
            uint32_t sw = SWZ((uint32_t)(row * 128 + c16 * 16));
            CPA16(base + sw,           Wh + (size_t)(m0 + row) * C + c0 + c16 * 8);
            CPA16(base + 16384u + sw,  Wl + (size_t)(m0 + row) * C + c0 + c16 * 8);
            CPA16(base + 32768u + sw,  Xh + (rowb + row) * (size_t)C + c0 + c16 * 8);
            CPA16(base + 49152u + sw,  Xl + (rowb + row) * (size_t)C + c0 + c16 * 8);
        }
        asm volatile("cp.async.commit_group;");
    };

    issue(0, 0);
    for (int cc = 0; cc < nchunk; ++cc) {
        int buf = cc & 1;
        if (cc + 1 < nchunk) {
            issue(cc + 1, buf ^ 1);
            asm volatile("cp.async.wait_group 1;");
        } else {
            asm volatile("cp.async.wait_group 0;");
        }
        __syncthreads();
        uint32_t base = sb + (uint32_t)buf * 65536u;

        int lr = (lane & 7) + ((lane >> 3) & 1) * 8;
        int kb = (lane >> 4) * 8;
#pragma unroll
        for (int kt = 0; kt < 4; ++kt) {
            uint32_t ah[4][4], al[4][4];
#pragma unroll
            for (int mt = 0; mt < 4; ++mt) {
                int row = wm * 64 + mt * 16 + lr;
                uint32_t a = base + SWZ((uint32_t)(row * 128 + (kt * 16 + kb) * 2));
                LDSM4(ah[mt], a);
                LDSM4(al[mt], a + 16384u);
            }
            uint32_t bh[4][2], bl[4][2];
#pragma unroll
            for (int np = 0; np < 2; ++np) {
                int row = wn * 32 + np * 16 + lr;
                uint32_t a = base + 32768u + SWZ((uint32_t)(row * 128 + (kt * 16 + kb) * 2));
                uint32_t r[4], rl[4];
                LDSM4(r, a);
                LDSM4(rl, a + 16384u);
                bh[np * 2][0] = r[0]; bh[np * 2][1] = r[2];
                bh[np * 2 + 1][0] = r[1]; bh[np * 2 + 1][1] = r[3];
                bl[np * 2][0] = rl[0]; bl[np * 2][1] = rl[2];
                bl[np * 2 + 1][0] = rl[1]; bl[np * 2 + 1][1] = rl[3];
            }
#pragma unroll
            for (int mt = 0; mt < 4; ++mt)
#pragma unroll
                for (int nt = 0; nt < 4; ++nt) {
                    MMA16816(acc[mt][nt], ah[mt], bh[nt]);
                    MMA16816(acc[mt][nt], ah[mt], bl[nt]);
                    MMA16816(acc[mt][nt], al[mt], bh[nt]);
                }
        }
        __syncthreads();
    }

    int mrow = (lane >> 2);
    int ncol = (lane & 3) * 2;
    if (TRANS == 0) {
#pragma unroll
        for (int mt = 0; mt < 4; ++mt) {
            int o = m0 + wm * 64 + mt * 16 + mrow;
            float bv0 = (o < O && bias) ? bias[o] : 0.f;
            float bv1 = (o + 8 < O && bias) ? bias[o + 8] : 0.f;
            float* yp0 = Y + ((size_t)bb * O + o) * 4096 + l0 + wn * 32;
            float* yp1 = Y + ((size_t)bb * O + o + 8) * 4096 + l0 + wn * 32;
#pragma unroll
            for (int nt = 0; nt < 4; ++nt) {
                if (o < O)
                    *(float2*)(yp0 + nt * 8 + ncol) = make_float2(acc[mt][nt][0] + bv0, acc[mt][nt][1] + bv0);
                if (o + 8 < O)
                    *(float2*)(yp1 + nt * 8 + ncol) = make_float2(acc[mt][nt][2] + bv1, acc[mt][nt][3] + bv1);
            }
        }
    } else {
        float* st = (float*)dsm;
#pragma unroll
        for (int mt = 0; mt < 4; ++mt) {
            int ob = wm * 64 + mt * 16 + mrow;
#pragma unroll
            for (int nt = 0; nt < 4; ++nt) {
                int pxb = wn * 32 + nt * 8 + ncol;
                st[(size_t)pxb * 132 + ob] = acc[mt][nt][0];
                st[(size_t)(pxb + 1) * 132 + ob] = acc[mt][nt][1];
                st[(size_t)pxb * 132 + ob + 8] = acc[mt][nt][2];
                st[(size_t)(pxb + 1) * 132 + ob + 8] = acc[mt][nt][3];
            }
        }
        __syncthreads();
        int px = tid >> 1, hf = (tid & 1) * 64;
        float* dst = Y + (rowb + px) * (size_t)O + m0 + hf;
        const float* src = st + (size_t)px * 132 + hf;
#pragma unroll
        for (int j = 0; j < 16; ++j)
            *(float4*)(dst + j * 4) = *(const float4*)(src + j * 4);
    }
}

// ---------------- FUSED channel-LN + gated residual (+2nd LN) + transposed bf16 split --------
// Input t = precomputed dwconv output (channel-major). One block = 64 px x 256 ch.
// MODE 0: split the gated output. MODE 1: compute 2nd LN (xn) and split that.
#define LNSM (2 * 64 * 258 * 2)
template<int MODE>
__global__ __launch_bounds__(256) void lngs_kernel(
    const float* __restrict__ t, const float* __restrict__ prev,
    const float* __restrict__ lnw, const float* __restrict__ lnb,
    const float* __restrict__ alpha_row,
    float* __restrict__ out_cm,
    const float* __restrict__ lnw2, const float* __restrict__ lnb2,
    float* __restrict__ out2_cm,
    __nv_bfloat16* __restrict__ oh, __nv_bfloat16* __restrict__ ol)
{
    extern __shared__ char sm[];
    __nv_bfloat16* sh = (__nv_bfloat16*)sm;
    __nv_bfloat16* sl = (__nv_bfloat16*)(sm + 64 * 258 * 2);
    __shared__ float r1[4][64], r2[4][64];
    int px = threadIdx.x, cg = threadIdx.y;
    int Pg = blockIdx.x * 64;
    int b = Pg >> 12, l0 = Pg & 4095;
    size_t base = (size_t)(b * DIM) * L + l0 + px;

    float s1 = 0.f, s2 = 0.f;
#pragma unroll 8
    for (int c = 0; c < 64; ++c) {
        float v = t[base + (size_t)(cg * 64 + c) * L];
        s1 += v; s2 += v * v;
    }
    r1[cg][px] = s1; r2[cg][px] = s2;
    __syncthreads();
    float u = (r1[0][px] + r1[1][px] + r1[2][px] + r1[3][px]) * (1.f / 256.f);
    float rs = rsqrtf((r2[0][px] + r2[1][px] + r2[2][px] + r2[3][px]) * (1.f / 256.f) - u * u + 1e-5f);

    float b1 = 0.f, b2 = 0.f;
#pragma unroll 8
    for (int c = 0; c < 64; ++c) {
        int ch = cg * 64 + c;
        size_t idx = base + (size_t)ch * L;
        float v = t[idx];
        float nv = lnw[ch] * (v - u) * rs + lnb[ch];
        float a = sigm(alpha_row[ch]);
        float p = prev[idx];
        float xv = fmaf(a, nv - p, p);
        out_cm[idx] = xv;
        if (MODE == 1) {
            b1 += xv; b2 += xv * xv;
        } else {
            __nv_bfloat16 hbf = __float2bfloat16(xv);
            sh[px * 258 + ch] = hbf;
            sl[px * 258 + ch] = __float2bfloat16(xv - __bfloat162float(hbf));
        }
    }
    if (MODE == 1) {
        __syncthreads();
        r1[cg][px] = b1; r2[cg][px] = b2;
        __syncthreads();
        float u1 = (r1[0][px] + r1[1][px] + r1[2][px] + r1[3][px]) * (1.f / 256.f);
        float rs2 = rsqrtf((r2[0][px] + r2[1][px] + r2[2][px] + r2[3][px]) * (1.f / 256.f) - u1 * u1 + 1e-5f);
#pragma unroll 8
        for (int c = 0; c < 64; ++c) {
            int ch = cg * 64 + c;
            size_t idx = base + (size_t)ch * L;
            float xv = out_cm[idx];            // L1-hot re-read, no spill
            float nv = lnw2[ch] * (xv - u1) * rs2 + lnb2[ch];
            out2_cm[idx] = nv;
            __nv_bfloat16 hbf = __float2bfloat16(nv);
            sh[px * 258 + ch] = hbf;
            sl[px * 258 + ch] = __float2bfloat16(nv - __bfloat162float(hbf));
        }
    }
    __syncthreads();

    // transposed coalesced writeout: thread owns (row, seg) -> 64 channels = 128 B = 8 uint4
    int tt = cg * 64 + px;
    int row = tt >> 2, seg = tt & 3;
    size_t rowg = ((size_t)b * L + l0 + row) * 256 + seg * 64;
    const uint32_t* s32h = (const uint32_t*)((const char*)sh + (row * 258 + seg * 64) * 2);
    const uint32_t* s32l = (const uint32_t*)((const char*)sl + (row * 258 + seg * 64) * 2);
    uint4* dh = (uint4*)(oh + rowg);
    uint4* dl = (uint4*)(ol + rowg);
#pragma unroll
    for (int j = 0; j < 8; ++j) {
        dh[j] = make_uint4(s32h[j * 4], s32h[j * 4 + 1], s32h[j * 4 + 2], s32h[j * 4 + 3]);
        dl[j] = make_uint4(s32l[j * 4], s32l[j * 4 + 1], s32l[j * 4 + 2], s32l[j * 4 + 3]);
    }
}

// ---------------- fused LN(1024) + SiLU + bf16 hi/lo split ----------------
__global__ __launch_bounds__(256) void ln_silu_split_kernel(
    const float* __restrict__ f1t, __nv_bfloat16* __restrict__ oh, __nv_bfloat16* __restrict__ ol,
    const float* __restrict__ lnw, const float* __restrict__ lnb)
{
    int warp = threadIdx.x >> 5, lane = threadIdx.x & 31;
    size_t px = (size_t)blockIdx.x * 8 + warp;
    const float4* row = (const float4*)(f1t + px * 1024);
    const float4* w4 = (const float4*)lnw;
    const float4* b4 = (const float4*)lnb;

    float4 v[8];
    float s1 = 0.f, s2 = 0.f;
#pragma unroll
    for (int i = 0; i < 8; ++i) {
        v[i] = row[lane + i * 32];
        s1 += v[i].x + v[i].y + v[i].z + v[i].w;
        s2 += v[i].x * v[i].x + v[i].y * v[i].y + v[i].z * v[i].z + v[i].w * v[i].w;
    }
#pragma unroll
    for (int st = 16; st; st >>= 1) {
        s1 += __shfl_xor_sync(0xFFFFFFFF, s1, st);
        s2 += __shfl_xor_sync(0xFFFFFFFF, s2, st);
    }
    float u = s1 * (1.f / 1024.f);
    float rs = rsqrtf(s2 * (1.f / 1024.f) - u * u + 1e-5f);

    uint2* oh2 = (uint2*)(oh + px * 1024);
    uint2* ol2 = (uint2*)(ol + px * 1024);
#pragma unroll
    for (int i = 0; i < 8; ++i) {
        int c4 = lane + i * 32;
        float4 wv = w4[c4], bv = b4[c4];
        float g[4];
        g[0] = wv.x * (v[i].x - u) * rs + bv.x;
        g[1] = wv.y * (v[i].y - u) * rs + bv.y;
        g[2] = wv.z * (v[i].z - u) * rs + bv.z;
        g[3] = wv.w * (v[i].w - u) * rs + bv.w;
#pragma unroll
        for (int j = 0; j < 4; ++j) g[j] = g[j] * sigm(g[j]);
        __nv_bfloat16 h0 = __float2bfloat16(g[0]), h1 = __float2bfloat16(g[1]);
        __nv_bfloat16 h2 = __float2bfloat16(g[2]), h3 = __float2bfloat16(g[3]);
        uint2 hp, lp;
        hp.x = (uint32_t)__bfloat16_as_ushort(h0) | ((uint32_t)__bfloat16_as_ushort(h1) << 16);
        hp.y = (uint32_t)__bfloat16_as_ushort(h2) | ((uint32_t)__bfloat16_as_ushort(h3) << 16);
        __nv_bfloat16 e0 = __float2bfloat16(g[0] - __bfloat162float(h0));
        __nv_bfloat16 e1 = __float2bfloat16(g[1] - __bfloat162float(h1));
        __nv_bfloat16 e2 = __float2bfloat16(g[2] - __bfloat162float(h2));
        __nv_bfloat16 e3 = __float2bfloat16(g[3] - __bfloat162float(h3));
        lp.x = (uint32_t)__bfloat16_as_ushort(e0) | ((uint32_t)__bfloat16_as_ushort(e1) << 16);
        lp.y = (uint32_t)__bfloat16_as_ushort(e2) | ((uint32_t)__bfloat16_as_ushort(e3) << 16);
        oh2[c4] = hp;
        ol2[c4] = lp;
    }
}

__global__ __launch_bounds__(256) void wsplit_kernel(
    const float* __restrict__ w, __nv_bfloat16* __restrict__ wh, __nv_bfloat16* __restrict__ wl)
{
    int i = blockIdx.x * 256 + threadIdx.x;
    float f = w[i];
    __nv_bfloat16 h = __float2bfloat16(f);
    wh[i] = h;
    wl[i] = __float2bfloat16(f - __bfloat162float(h));
}

__global__ __launch_bounds__(256) void wsplit_pad_kernel(
    const float* __restrict__ w, __nv_bfloat16* __restrict__ wh, __nv_bfloat16* __restrict__ wl)
{
    int i = blockIdx.x * 256 + threadIdx.x;
    int row = i >> 8;
    float f = (row < 192) ? w[i] : 0.f;
    __nv_bfloat16 h = __float2bfloat16(f);
    wh[i] = h;
    wl[i] = __float2bfloat16(f - __bfloat162float(h));
}

// ---------------- depthwise 3x3 conv ----------------
__global__ __launch_bounds__(256) void dwconv8_kernel(
    const float* __restrict__ in, const float* __restrict__ w,
    const float* __restrict__ bias, float* __restrict__ out, int C)
{
    int t = blockIdx.x * 256 + threadIdx.x;
    int x0 = (t & 7) * 8;
    int r = t >> 3;
    int hh = r & 63;
    int bc = r >> 6;
    int c = bc - (bc / C) * C;
    const float* wp = w + c * 9;
    float wr[9];
#pragma unroll
    for (int i = 0; i < 9; ++i) wr[i] = wp[i];
    const float* ip = in + (long)bc * 4096;
    float bv = bias ? bias[c] : 0.f;
    float acc[8];
#pragma unroll
    for (int j = 0; j < 8; ++j) acc[j] = bv;
#pragma unroll
    for (int ky = 0; ky < 3; ++ky) {
        int y = hh + ky - 1;
        if ((unsigned)y < 64u) {
            const float* rp = ip + y * 64 + x0;
            float4 a = *(const float4*)rp;
            float4 b4 = *(const float4*)(rp + 4);
            float v[10];
            v[0] = (x0 > 0) ? rp[-1] : 0.f;
            v[1] = a.x; v[2] = a.y; v[3] = a.z; v[4] = a.w;
            v[5] = b4.x; v[6] = b4.y; v[7] = b4.z; v[8] = b4.w;
            v[9] = (x0 < 56) ? rp[8] : 0.f;
            float k0 = wr[ky * 3 + 0], k1 = wr[ky * 3 + 1], k2 = wr[ky * 3 + 2];
#pragma unroll
            for (int j = 0; j < 8; ++j)
                acc[j] += k0 * v[j] + k1 * v[j + 1] + k2 * v[j + 2];
        }
    }
    float* op = out + (long)bc * 4096 + hh * 64 + x0;
    *(float4*)op = make_float4(acc[0], acc[1], acc[2], acc[3]);
    *(float4*)(op + 4) = make_float4(acc[4], acc[5], acc[6], acc[7]);
}

// ---------------- plain channel-LN + gated residual (final FFN LN) ----------------
__global__ __launch_bounds__(256) void ln_gate_kernel(
    const float* __restrict__ t, const float* __restrict__ prev,
    const float* __restrict__ lnw, const float* __restrict__ lnb,
    const float* __restrict__ alpha_row, float* __restrict__ out)
{
    __shared__ float r1[4][64], r2[4][64];
    int px = threadIdx.x, cg = threadIdx.y;
    int Pg = blockIdx.x * 64;
    int b = Pg >> 12, l0 = Pg & 4095;
    int base = b * DIM * L + l0 + px;

    float s1 = 0.f, s2 = 0.f;
#pragma unroll 8
    for (int c = 0; c < 64; ++c) {
        float v = t[base + (cg * 64 + c) * L];
        s1 += v; s2 += v * v;
    }
    r1[cg][px] = s1; r2[cg][px] = s2;
    __syncthreads();
    float u = (r1[0][px] + r1[1][px] + r1[2][px] + r1[3][px]) * (1.f / 256.f);
    float rs = rsqrtf((r2[0][px] + r2[1][px] + r2[2][px] + r2[3][px]) * (1.f / 256.f) - u * u + 1e-5f);

#pragma unroll 8
    for (int c = 0; c < 64; ++c) {
        int ch = cg * 64 + c;
        int idx = base + ch * L;
        float v = t[idx];
        float nv = lnw[ch] * (v - u) * rs + lnb[ch];
        float a = sigm(alpha_row[ch]);
        float p = prev[idx];
        out[idx] = fmaf(a, nv - p, p);
    }
}

// ---------------- small GEMM for Ld=64 ----------------
template<int OT>
__global__ __launch_bounds__(256) void gemm1x1_kernel(
    const float* __restrict__ W, const float* __restrict__ bias,
    const float* __restrict__ X, float* __restrict__ Y,
    int O, int C, int Ld)
{
    constexpr int PT = OT / 8;
    constexpr int KC = 32;
    __shared__ float Ws[OT * KC];
    int tid = threadIdx.x;
    int pxl = tid & 31;
    int og = tid >> 5;
    int b = (blockIdx.x * 64) / Ld;
    int l0 = (blockIdx.x * 64) % Ld;
    int ob = blockIdx.y * OT;
    const float* Xb = X + (b * C) * Ld + l0 + pxl * 2;

    float2 acc[PT];
#pragma unroll
    for (int i = 0; i < PT; ++i) acc[i] = make_float2(0.f, 0.f);

    for (int c0 = 0; c0 < C; c0 += KC) {
        __syncthreads();
#pragma unroll
        for (int e = tid; e < OT * KC; e += 256) {
            int ol = e >> 5, k = e & 31;
            Ws[e] = W[(ob + ol) * C + c0 + k];
        }
        __syncthreads();
#pragma unroll 4
        for (int k = 0; k < KC; ++k) {
            float2 xv = *reinterpret_cast<const float2*>(Xb + (c0 + k) * Ld);
#pragma unroll
            for (int i = 0; i < PT; ++i) {
                float wv = Ws[(og * PT + i) * KC + k];
                acc[i] = ffma2(make_float2(wv, wv), xv, acc[i]);
            }
        }
    }
#pragma unroll
    for (int i = 0; i < PT; ++i) {
        int o = ob + og * PT + i;
        float bv = bias ? bias[o] : 0.f;
        float2 r = make_float2(acc[i].x + bv, acc[i].y + bv);
        *reinterpret_cast<float2*>(Y + (b * O + o) * Ld + l0 + pxl * 2) = r;
    }
}

// ---------------- softmax over L, AB = softmax(dt)*Bm ----------------
__global__ __launch_bounds__(256) void softmax_ab_kernel(
    const float* __restrict__ bcdt2, float* __restrict__ AB)
{
    int bs = blockIdx.x;
    int b = bs >> 6, s = bs & 63;
    const float* dt = bcdt2 + (b * 192 + 128 + s) * L;
    const float* Bm = bcdt2 + (b * 192 + s) * L;
    float* out = AB + (b * 64 + s) * L;
    __shared__ float e[L];
    __shared__ float red[256];
    int tid = threadIdx.x;

    float m = -1e30f;
    for (int l = tid; l < L; l += 256) { float v = dt[l]; e[l] = v; m = fmaxf(m, v); }
    red[tid] = m; __syncthreads();
    for (int st = 128; st; st >>= 1) { if (tid < st) red[tid] = fmaxf(red[tid], red[tid + st]); __syncthreads(); }
    m = red[0];
    __syncthreads();

    float sm = 0.f;
    for (int l = tid; l < L; l += 256) { float ev = __expf(e[l] - m); e[l] = ev; sm += ev; }
    red[tid] = sm; __syncthreads();
    for (int st = 128; st; st >>= 1) { if (tid < st) red[tid] += red[tid + st]; __syncthreads(); }
    float inv = 1.f / red[0];

    for (int l = tid; l < L; l += 256) out[l] = e[l] * inv * Bm[l];
}

// ---------------- h partials ----------------
__global__ __launch_bounds__(256) void hgemm_kernel(
    const float* __restrict__ xn, const float* __restrict__ AB, float* __restrict__ hpart)
{
    int b = blockIdx.x, dtile = blockIdx.y, seg = blockIdx.z;
    int d0 = dtile * 64;
    int lb = seg * (L / NSEG);
    __shared__ float xs[64][17], as[64][17];
    int tid = threadIdx.x, tx = tid & 15, ty = tid >> 4;
    float acc[4][4];
#pragma unroll
    for (int i = 0; i < 4; ++i)
#pragma unroll
        for (int j = 0; j < 4; ++j) acc[i][j] = 0.f;

    const float* xp = xn + (b * DIM + d0) * L + lb;
    const float* ap = AB + (b * 64) * L + lb;

    for (int k0 = 0; k0 < L / NSEG; k0 += 16) {
        __syncthreads();
#pragma unroll
        for (int e = tid; e < 1024; e += 256) {
            int r = e >> 4, c = e & 15;
            xs[r][c] = xp[r * L + k0 + c];
            as[r][c] = ap[r * L + k0 + c];
        }
        __syncthreads();
#pragma unroll
        for (int k = 0; k < 16; ++k) {
            float xa[4], bb[4];
#pragma unroll
            for (int i = 0; i < 4; ++i) xa[i] = xs[ty * 4 + i][k];
#pragma unroll
            for (int j = 0; j < 4; ++j) bb[j] = as[tx * 4 + j][k];
#pragma unroll
            for (int i = 0; i < 4; ++i)
#pragma unroll
                for (int j = 0; j < 4; ++j) acc[i][j] += xa[i] * bb[j];
        }
    }
    float* hp = hpart + seg * (BATCH * DIM * STATE);
#pragma unroll
    for (int i = 0; i < 4; ++i)
#pragma unroll
        for (int j = 0; j < 4; ++j)
            hp[(b * DIM + d0 + ty * 4 + i) * STATE + tx * 4 + j] = acc[i][j];
}

__global__ __launch_bounds__(256) void hreduce_kernel(
    const float* __restrict__ hpart, float* __restrict__ h)
{
    int idx = blockIdx.x * 256 + threadIdx.x;
    float s = 0.f;
#pragma unroll
    for (int g = 0; g < NSEG; ++g) s += hpart[g * (BATCH * DIM * STATE) + idx];
    h[idx] = s;
}

__global__ __launch_bounds__(256) void gate_kernel(
    const float* __restrict__ hz, float* __restrict__ hg)
{
    int idx = blockIdx.x * 256 + threadIdx.x;
    int s = idx & 63;
    int c = (idx >> 6) & 255;
    int b = idx >> 14;
    float hp = hz[(b * 512 + c) * 64 + s];
    float z = hz[(b * 512 + 256 + c) * 64 + s];
    hg[idx] = hp * z * sigm(z);
}

// ---------------- y = ho @ Cm ; x2 ----------------
__global__ __launch_bounds__(256) void y_fuse_kernel(
    const float* __restrict__ ho, const float* __restrict__ bcdt2,
    const float* __restrict__ xn, const float* __restrict__ x1,
    const float* __restrict__ Dp, const float* __restrict__ alpha1,
    float* __restrict__ x2)
{
    __shared__ float hos[16][257];
    int tid = threadIdx.x;
    int px = tid & 63, dg = tid >> 6;
    int Pg = blockIdx.x * 64;
    int b = Pg >> 12, l0 = Pg & 4095;
    const float* hob = ho + b * DIM * STATE;
    const float* cm = bcdt2 + (b * 192 + 64) * L + l0 + px;

    float acc[64];
#pragma unroll
    for (int j = 0; j < 64; ++j) acc[j] = 0.f;

    for (int sc = 0; sc < 4; ++sc) {
        __syncthreads();
#pragma unroll
        for (int e = tid; e < 4096; e += 256) {
            int d = e >> 4, s = e & 15;
            hos[s][d] = hob[d * 64 + sc * 16 + s];
        }
        __syncthreads();
#pragma unroll
        for (int s = 0; s < 16; ++s) {
            float cmv = cm[(sc * 16 + s) * L];
#pragma unroll
            for (int j = 0; j < 64; ++j)
                acc[j] += hos[s][dg * 64 + j] * cmv;
        }
    }
#pragma unroll
    for (int j = 0; j < 64; ++j) {
        int d = dg * 64 + j;
        int idx = (b * DIM + d) * L + l0 + px;
        float y = acc[j] + xn[idx] * Dp[d];
        float a = sigm(alpha1[d]);
        float p = x1[idx];
        x2[idx] = fmaf(a, y - p, p);
    }
}

__global__ __launch_bounds__(256) void copy_kernel(
    const float* __restrict__ src, float* __restrict__ dst)
{
    int idx = blockIdx.x * 256 + threadIdx.x;
    dst[idx] = src[idx];
}

// ---------------- host launcher ----------------
extern "C" void kernel_launch(void* const* d_in, const int* in_sizes, int n_in,
                              void* d_out, int out_size)
{
    const float* x        = (const float*)d_in[0];
    const float* alpha    = (const float*)d_in[1];
    const float* ln_w     = (const float*)d_in[2];
    const float* ln_b     = (const float*)d_in[3];
    const float* dw1_w    = (const float*)d_in[4];
    const float* dw1_ln_w = (const float*)d_in[5];
    const float* dw1_ln_b = (const float*)d_in[6];
    const float* dw2_w    = (const float*)d_in[7];
    const float* dw2_ln_w = (const float*)d_in[8];
    const float* dw2_ln_b = (const float*)d_in[9];
    const float* bcdt_w   = (const float*)d_in[10];
    const float* bcdt_b   = (const float*)d_in[11];
    const float* dwm_w    = (const float*)d_in[12];
    const float* dwm_b    = (const float*)d_in[13];
    const float* hz_w     = (const float*)d_in[14];
    const float* hz_b     = (const float*)d_in[15];
    const float* outp_w   = (const float*)d_in[16];
    const float* outp_b   = (const float*)d_in[17];
    const float* Dp       = (const float*)d_in[19];
    const float* fc1_w    = (const float*)d_in[20];
    const float* fc1_ln_w = (const float*)d_in[21];
    const float* fc1_ln_b = (const float*)d_in[22];
    const float* fc2_w    = (const float*)d_in[23];
    const float* fc2_ln_w = (const float*)d_in[24];
    const float* fc2_ln_b = (const float*)d_in[25];
    float* out = (float*)d_out;

    float *t0, *x1, *xn, *x2, *x3, *bc, *bc2, *ab, *hpart, *h, *hz, *hg, *ho, *f1t;
    __nv_bfloat16 *x3th, *x3tl, *xnth, *xntl, *f1th, *f1tl, *w1h, *w1l, *w2h, *w2l, *wbch, *wbcl;
    cudaGetSymbolAddress((void**)&t0, g_t0);
    cudaGetSymbolAddress((void**)&x1, g_x1);
    cudaGetSymbolAddress((void**)&xn, g_xn);
    cudaGetSymbolAddress((void**)&x2, g_x2);
    cudaGetSymbolAddress((void**)&x3, g_x3);
    cudaGetSymbolAddress((void**)&bc, g_bcdt);
    cudaGetSymbolAddress((void**)&bc2, g_bcdt2);
    cudaGetSymbolAddress((void**)&ab, g_AB);
    cudaGetSymbolAddress((void**)&hpart, g_hpart);
    cudaGetSymbolAddress((void**)&h, g_h);
    cudaGetSymbolAddress((void**)&hz, g_hz);
    cudaGetSymbolAddress((void**)&hg, g_hg);
    cudaGetSymbolAddress((void**)&ho, g_ho);
    cudaGetSymbolAddress((void**)&f1t, g_f1t);
    cudaGetSymbolAddress((void**)&x3th, g_x3th);
    cudaGetSymbolAddress((void**)&x3tl, g_x3tl);
    cudaGetSymbolAddress((void**)&xnth, g_xnth);
    cudaGetSymbolAddress((void**)&xntl, g_xntl);
    cudaGetSymbolAddress((void**)&f1th, g_f1th);
    cudaGetSymbolAddress((void**)&f1tl, g_f1tl);
    cudaGetSymbolAddress((void**)&w1h, g_w1h);
    cudaGetSymbolAddress((void**)&w1l, g_w1l);
    cudaGetSymbolAddress((void**)&w2h, g_w2h);
    cudaGetSymbolAddress((void**)&w2l, g_w2l);
    cudaGetSymbolAddress((void**)&wbch, g_wbch);
    cudaGetSymbolAddress((void**)&wbcl, g_wbcl);

    cudaFuncSetAttribute(gemm_mma_kernel<0>, cudaFuncAttributeMaxDynamicSharedMemorySize, GSMEM);
    cudaFuncSetAttribute(gemm_mma_kernel<1>, cudaFuncAttributeMaxDynamicSharedMemorySize, GSMEM);
    cudaFuncSetAttribute(lngs_kernel<0>, cudaFuncAttributeMaxDynamicSharedMemorySize, LNSM);
    cudaFuncSetAttribute(lngs_kernel<1>, cudaFuncAttributeMaxDynamicSharedMemorySize, LNSM);

    dim3 blk2(64, 4);

    // weight splits
    wsplit_kernel<<<HIDDEN * DIM / 256, 256>>>(fc1_w, w1h, w1l);
    wsplit_kernel<<<DIM * HIDDEN / 256, 256>>>(fc2_w, w2h, w2l);
    wsplit_pad_kernel<<<256 * DIM / 256, 256>>>(bcdt_w, wbch, wbcl);

    // sub-layer 1: dwconv, then fused LN+gate+2ndLN+split
    dwconv8_kernel<<<BATCH * DIM * L / 8 / 256, 256>>>(x, dw1_w, nullptr, t0, DIM);
    lngs_kernel<1><<<PIXBLK, blk2, LNSM>>>(t0, x, dw1_ln_w, dw1_ln_b, alpha, x1,
                                           ln_w, ln_b, xn, xnth, xntl);

    // HSMSSD mixer
    gemm_mma_kernel<0><<<dim3(NPIX / 128, 2), 256, GSMEM>>>(wbch, wbcl, xnth, xntl, bc, bcdt_b, 192, 256);
    dwconv8_kernel<<<BATCH * 192 * L / 8 / 256, 256>>>(bc, dwm_w, dwm_b, bc2, 192);
    softmax_ab_kernel<<<BATCH * 64, 256>>>(bc2, ab);
    hgemm_kernel<<<dim3(BATCH, 4, NSEG), 256>>>(xn, ab, hpart);
    hreduce_kernel<<<BATCH * DIM * STATE / 256, 256>>>(hpart, h);
    gemm1x1_kernel<128><<<dim3(BATCH, 4), 256>>>(hz_w, hz_b, h, hz, 512, 256, 64);
    gate_kernel<<<BATCH * DIM * STATE / 256, 256>>>(hz, hg);
    gemm1x1_kernel<128><<<dim3(BATCH, 2), 256>>>(outp_w, outp_b, hg, ho, 256, 256, 64);
    y_fuse_kernel<<<PIXBLK, 256>>>(ho, bc2, xn, x1, Dp, alpha + 256, x2);

    // sub-layer 3: dwconv, then fused LN+gate+split
    dwconv8_kernel<<<BATCH * DIM * L / 8 / 256, 256>>>(x2, dw2_w, nullptr, t0, DIM);
    lngs_kernel<0><<<PIXBLK, blk2, LNSM>>>(t0, x2, dw2_ln_w, dw2_ln_b, alpha + 512, x3,
                                           nullptr, nullptr, nullptr, x3th, x3tl);

    // FFN: fc1 (transposed out) -> fused LN+SiLU+split -> fc2 -> final LN+gate
    gemm_mma_kernel<1><<<dim3(NPIX / 128, HIDDEN / 128), 256, GSMEM>>>(w1h, w1l, x3th, x3tl, f1t, nullptr, HIDDEN, 256);
    ln_silu_split_kernel<<<NPIX / 8, 256>>>(f1t, f1th, f1tl, fc1_ln_w, fc1_ln_b);
    gemm_mma_kernel<0><<<dim3(NPIX / 128, 2), 256, GSMEM>>>(w2h, w2l, f1th, f1tl, t0, nullptr, 256, 1024);
    ln_gate_kernel<<<PIXBLK, blk2>>>(t0, x3, fc2_ln_w, fc2_ln_b, alpha + 768, out);

    // second output: h
    if (out_size >= BATCH * DIM * L + BATCH * DIM * STATE)
        copy_kernel<<<BATCH * DIM * STATE / 256, 256>>>(h, out + BATCH * DIM * L);
}

// round 10
// speedup vs baseline: 1.4394x; 1.0791x over previous
#include <cuda_runtime.h>
#include <cuda_bf16.h>
#include <cstdint>
#include <math.h>

#define BATCH 16
#define DIM 256
#define STATE 64
#define HIDDEN 1024
#define L 4096
#define NPIX (BATCH*L)
#define PIXBLK (NPIX/64)
#define NSEG 8

// ---------------- scratch ----------------
__device__ float g_t0[BATCH*DIM*L];
__device__ float g_x1[BATCH*DIM*L];
__device__ float g_xn[BATCH*DIM*L];
__device__ float g_x2[BATCH*DIM*L];
__device__ float g_x3[BATCH*DIM*L];
__device__ float g_bcdt[BATCH*192*L];
__device__ float g_bcdt2[BATCH*192*L];
__device__ float g_AB[BATCH*STATE*L];
__device__ float g_hpart[NSEG*BATCH*DIM*STATE];
__device__ float g_h[BATCH*DIM*STATE];
__device__ float g_hz[BATCH*2*DIM*STATE];
__device__ float g_hg[BATCH*DIM*STATE];
__device__ float g_ho[BATCH*DIM*STATE];
__device__ float g_f1t[(size_t)BATCH*L*HIDDEN];          // fc1 output, TRANSPOSED [b*L, 1024] fp32
__device__ __nv_bfloat16 g_x3th[BATCH*L*DIM];
__device__ __nv_bfloat16 g_x3tl[BATCH*L*DIM];
__device__ __nv_bfloat16 g_xnth[BATCH*L*DIM];
__device__ __nv_bfloat16 g_xntl[BATCH*L*DIM];
__device__ __nv_bfloat16 g_f1th[(size_t)BATCH*L*HIDDEN];
__device__ __nv_bfloat16 g_f1tl[(size_t)BATCH*L*HIDDEN];
__device__ __nv_bfloat16 g_w1h[HIDDEN*DIM];
__device__ __nv_bfloat16 g_w1l[HIDDEN*DIM];
__device__ __nv_bfloat16 g_w2h[DIM*HIDDEN];
__device__ __nv_bfloat16 g_w2l[DIM*HIDDEN];
__device__ __nv_bfloat16 g_wbch[256*DIM];                 // bcdt weights padded to 256 rows
__device__ __nv_bfloat16 g_wbcl[256*DIM];

// ---------------- helpers ----------------
__device__ __forceinline__ float2 ffma2(float2 a, float2 b, float2 c) {
    float2 d;
    asm("{\n\t.reg .b64 ra, rb, rc, rd;\n\t"
        "mov.b64 ra, {%2, %3};\n\tmov.b64 rb, {%4, %5};\n\tmov.b64 rc, {%6, %7};\n\t"
        "fma.rn.f32x2 rd, ra, rb, rc;\n\tmov.b64 {%0, %1}, rd;\n\t}"
        : "=f"(d.x), "=f"(d.y)
        : "f"(a.x), "f"(a.y), "f"(b.x), "f"(b.y), "f"(c.x), "f"(c.y));
    return d;
}
__device__ __forceinline__ float sigm(float v) { return 1.f / (1.f + __expf(-v)); }

#define CPA16(dst, src) asm volatile("cp.async.cg.shared.global [%0], [%1], 16;" :: "r"(dst), "l"(src))
#define SWZ(o) ((o) ^ (((o) >> 3) & 0x70u))

__device__ __forceinline__ uint32_t s2u(const void* p) {
    uint32_t a;
    asm("{ .reg .u64 t; cvta.to.shared.u64 t, %1; cvt.u32.u64 %0, t; }" : "=r"(a) : "l"(p));
    return a;
}

#define LDSM4(r, a) \
    asm volatile("ldmatrix.sync.aligned.m8n8.x4.shared.b16 {%0,%1,%2,%3}, [%4];" \
        : "=r"((r)[0]), "=r"((r)[1]), "=r"((r)[2]), "=r"((r)[3]) : "r"(a))

#define MMA16816(d, a, b) \
    asm volatile("mma.sync.aligned.m16n8k16.row.col.f32.bf16.bf16.f32 " \
        "{%0,%1,%2,%3},{%4,%5,%6,%7},{%8,%9},{%0,%1,%2,%3};" \
        : "+f"((d)[0]), "+f"((d)[1]), "+f"((d)[2]), "+f"((d)[3]) \
        : "r"((a)[0]), "r"((a)[1]), "r"((a)[2]), "r"((a)[3]), "r"((b)[0]), "r"((b)[1]))

// ---------------- tensor-core GEMM (mma.sync bf16 hi/lo), tile M128 x N256 -------------------
// A = W split [O,C] K-major; B = Xt split [B*L, C] K-major. Kc=64, double buffered.
// 8 warps = 2(M) x 4(N); warp tile 64M x 64N. acc[4][8][4].
#define GSMEM 196608
template<int TRANS>
__global__ __launch_bounds__(256) void gemm_mma_kernel(
    const __nv_bfloat16* __restrict__ Wh, const __nv_bfloat16* __restrict__ Wl,
    const __nv_bfloat16* __restrict__ Xh, const __nv_bfloat16* __restrict__ Xl,
    float* __restrict__ Y, const float* __restrict__ bias, int O, int C)
{
    extern __shared__ char dsm[];
    uint32_t sb = s2u(dsm);
    int tid = threadIdx.x, warp = tid >> 5, lane = tid & 31;
    int wm = warp >> 2, wn = warp & 3;
    int bb = blockIdx.x >> 4;
    int l0 = (blockIdx.x & 15) << 8;
    int m0 = blockIdx.y << 7;
    int nchunk = C >> 6;
    size_t rowb = (size_t)bb * 4096 + l0;

    float acc[4][8][4];
#pragma unroll
    for (int i = 0; i < 4; ++i)
#pragma unroll
        for (int j = 0; j < 8; ++j)
#pragma unroll
            for (int q = 0; q < 4; ++q) acc[i][j][q] = 0.f;

    // per buffer: A hi 16K @0, A lo 16K @16384, B hi 32K @32768, B lo 32K @65536 (98304 total)
    auto issue = [&](int cc, int buf) {
        int c0 = cc << 6;
        uint32_t base = sb + (uint32_t)buf * 98304u;
#pragma unroll
        for (int i = 0; i < 4; ++i) {                 // A: 128 rows x 8 sectors
            int e = tid + i * 256;
            int row = e >> 3, c16 = e & 7;
            uint32_t sw = SWZ((uint32_t)(row * 128 + c16 * 16));
            CPA16(base + sw,           Wh + (size_t)(m0 + row) * C + c0 + c16 * 8);
            CPA16(base + 16384u + sw,  Wl + (size_t)(m0 + row) * C + c0 + c16 * 8);
        }
#pragma unroll
        for (int i = 0; i < 8; ++i) {                 // B: 256 rows x 8 sectors
            int e = tid + i * 256;
            int row = e >> 3, c16 = e & 7;
            uint32_t sw = SWZ((uint32_t)(row * 128 + c16 * 16));
            CPA16(base + 32768u + sw,  Xh + (rowb + row) * (size_t)C + c0 + c16 * 8);
            CPA16(base + 65536u + sw,  Xl + (rowb + row) * (size_t)C + c0 + c16 * 8);
        }
        asm volatile("cp.async.commit_group;");
    };

    issue(0, 0);
    for (int cc = 0; cc < nchunk; ++cc) {
        int buf = cc & 1;
        if (cc + 1 < nchunk) {
            issue(cc + 1, buf ^ 1);
            asm volatile("cp.async.wait_group 1;");
        } else {
            asm volatile("cp.async.wait_group 0;");
        }
        __syncthreads();
        uint32_t base = sb + (uint32_t)buf * 98304u;

        int lr = (lane & 7) + ((lane >> 3) & 1) * 8;
        int kb = (lane >> 4) * 8;
#pragma unroll
        for (int kt = 0; kt < 4; ++kt) {
            uint32_t ah[4][4], al[4][4];
#pragma unroll
            for (int mt = 0; mt < 4; ++mt) {
                int row = wm * 64 + mt * 16 + lr;
                uint32_t a = base + SWZ((uint32_t)(row * 128 + (kt * 16 + kb) * 2));
                LDSM4(ah[mt], a);
                LDSM4(al[mt], a + 16384u);
            }
            uint32_t bh[8][2], bl[8][2];
#pragma unroll
            for (int np = 0; np < 4; ++np) {
                int row = wn * 64 + np * 16 + lr;
                uint32_t a = base + 32768u + SWZ((uint32_t)(row * 128 + (kt * 16 + kb) * 2));
                uint32_t r[4], rl[4];
                LDSM4(r, a);
                LDSM4(rl, a + 32768u);
                bh[np * 2][0] = r[0]; bh[np * 2][1] = r[2];
                bh[np * 2 + 1][0] = r[1]; bh[np * 2 + 1][1] = r[3];
                bl[np * 2][0] = rl[0]; bl[np * 2][1] = rl[2];
                bl[np * 2 + 1][0] = rl[1]; bl[np * 2 + 1][1] = rl[3];
            }
#pragma unroll
            for (int mt = 0; mt < 4; ++mt)
#pragma unroll
                for (int nt = 0; nt < 8; ++nt) {
                    MMA16816(acc[mt][nt], ah[mt], bh[nt]);
                    MMA16816(acc[mt][nt], ah[mt], bl[nt]);
                    MMA16816(acc[mt][nt], al[mt], bh[nt]);
                }
        }
        __syncthreads();
    }

    int mrow = (lane >> 2);
    int ncol = (lane & 3) * 2;
    if (TRANS == 0) {
#pragma unroll
        for (int mt = 0; mt < 4; ++mt) {
            int o = m0 + wm * 64 + mt * 16 + mrow;
            float bv0 = (o < O && bias) ? bias[o] : 0.f;
            float bv1 = (o + 8 < O && bias) ? bias[o + 8] : 0.f;
            float* yp0 = Y + ((size_t)bb * O + o) * 4096 + l0 + wn * 64;
            float* yp1 = Y + ((size_t)bb * O + o + 8) * 4096 + l0 + wn * 64;
#pragma unroll
            for (int nt = 0; nt < 8; ++nt) {
                if (o < O)
                    *(float2*)(yp0 + nt * 8 + ncol) = make_float2(acc[mt][nt][0] + bv0, acc[mt][nt][1] + bv0);
                if (o + 8 < O)
                    *(float2*)(yp1 + nt * 8 + ncol) = make_float2(acc[mt][nt][2] + bv1, acc[mt][nt][3] + bv1);
            }
        }
    } else {
        // stage [256 px][128 o] (stride 132) in dsm, then row-major writeout
        float* st = (float*)dsm;
#pragma unroll
        for (int mt = 0; mt < 4; ++mt) {
            int ob = wm * 64 + mt * 16 + mrow;
#pragma unroll
            for (int nt = 0; nt < 8; ++nt) {
                int pxb = wn * 64 + nt * 8 + ncol;
                st[(size_t)pxb * 132 + ob] = acc[mt][nt][0];
                st[(size_t)(pxb + 1) * 132 + ob] = acc[mt][nt][1];
                st[(size_t)pxb * 132 + ob + 8] = acc[mt][nt][2];
                st[(size_t)(pxb + 1) * 132 + ob + 8] = acc[mt][nt][3];
            }
        }
        __syncthreads();
        int px = tid;
        float* dst = Y + (rowb + px) * (size_t)O + m0;
        const float* src = st + (size_t)px * 132;
#pragma unroll
        for (int j = 0; j < 32; ++j)
            *(float4*)(dst + j * 4) = *(const float4*)(src + j * 4);
    }
}

// ---------------- transpose + bf16 hi/lo split: [b,C,L] f32 -> [b*L, C] bf16 x2 --------------
__global__ __launch_bounds__(256) void convt_kernel(
    const float* __restrict__ in, __nv_bfloat16* __restrict__ oh,
    __nv_bfloat16* __restrict__ ol, int C)
{
    __shared__ float s[64][33];
    int tid = threadIdx.x;
    int lx = tid & 31, cy = tid >> 5;
    int l0 = blockIdx.x * 32;
    int c0 = blockIdx.y * 64;
    int b = blockIdx.z;
    const float* ip = in + ((size_t)b * C + c0) * L + l0;
#pragma unroll
    for (int i = 0; i < 8; ++i)
        s[cy + i * 8][lx] = ip[(size_t)(cy + i * 8) * L + lx];
    __syncthreads();
    int cp = tid & 31, ly = tid >> 5;
#pragma unroll
    for (int i = 0; i < 4; ++i) {
        int lrow = ly + i * 8;
        float f0 = s[2 * cp][lrow], f1 = s[2 * cp + 1][lrow];
        __nv_bfloat16 h0 = __float2bfloat16(f0);
        __nv_bfloat16 h1 = __float2bfloat16(f1);
        __nv_bfloat16 e0 = __float2bfloat16(f0 - __bfloat162float(h0));
        __nv_bfloat16 e1 = __float2bfloat16(f1 - __bfloat162float(h1));
        uint32_t hp = (uint32_t)__bfloat16_as_ushort(h0) | ((uint32_t)__bfloat16_as_ushort(h1) << 16);
        uint32_t lp = (uint32_t)__bfloat16_as_ushort(e0) | ((uint32_t)__bfloat16_as_ushort(e1) << 16);
        size_t o32 = (((size_t)b * L + l0 + lrow) * C + c0) / 2 + cp;
        ((uint32_t*)oh)[o32] = hp;
        ((uint32_t*)ol)[o32] = lp;
    }
}

// ---------------- fused LN(1024) + SiLU + bf16 hi/lo split ----------------
__global__ __launch_bounds__(256) void ln_silu_split_kernel(
    const float* __restrict__ f1t, __nv_bfloat16* __restrict__ oh, __nv_bfloat16* __restrict__ ol,
    const float* __restrict__ lnw, const float* __restrict__ lnb)
{
    int warp = threadIdx.x >> 5, lane = threadIdx.x & 31;
    size_t px = (size_t)blockIdx.x * 8 + warp;
    const float4* row = (const float4*)(f1t + px * 1024);
    const float4* w4 = (const float4*)lnw;
    const float4* b4 = (const float4*)lnb;

    float4 v[8];
    float s1 = 0.f, s2 = 0.f;
#pragma unroll
    for (int i = 0; i < 8; ++i) {
        v[i] = row[lane + i * 32];
        s1 += v[i].x + v[i].y + v[i].z + v[i].w;
        s2 += v[i].x * v[i].x + v[i].y * v[i].y + v[i].z * v[i].z + v[i].w * v[i].w;
    }
#pragma unroll
    for (int st = 16; st; st >>= 1) {
        s1 += __shfl_xor_sync(0xFFFFFFFF, s1, st);
        s2 += __shfl_xor_sync(0xFFFFFFFF, s2, st);
    }
    float u = s1 * (1.f / 1024.f);
    float rs = rsqrtf(s2 * (1.f / 1024.f) - u * u + 1e-5f);

    uint2* oh2 = (uint2*)(oh + px * 1024);
    uint2* ol2 = (uint2*)(ol + px * 1024);
#pragma unroll
    for (int i = 0; i < 8; ++i) {
        int c4 = lane + i * 32;
        float4 wv = w4[c4], bv = b4[c4];
        float g[4];
        g[0] = wv.x * (v[i].x - u) * rs + bv.x;
        g[1] = wv.y * (v[i].y - u) * rs + bv.y;
        g[2] = wv.z * (v[i].z - u) * rs + bv.z;
        g[3] = wv.w * (v[i].w - u) * rs + bv.w;
#pragma unroll
        for (int j = 0; j < 4; ++j) g[j] = g[j] * sigm(g[j]);
        __nv_bfloat16 h0 = __float2bfloat16(g[0]), h1 = __float2bfloat16(g[1]);
        __nv_bfloat16 h2 = __float2bfloat16(g[2]), h3 = __float2bfloat16(g[3]);
        uint2 hp, lp;
        hp.x = (uint32_t)__bfloat16_as_ushort(h0) | ((uint32_t)__bfloat16_as_ushort(h1) << 16);
        hp.y = (uint32_t)__bfloat16_as_ushort(h2) | ((uint32_t)__bfloat16_as_ushort(h3) << 16);
        __nv_bfloat16 e0 = __float2bfloat16(g[0] - __bfloat162float(h0));
        __nv_bfloat16 e1 = __float2bfloat16(g[1] - __bfloat162float(h1));
        __nv_bfloat16 e2 = __float2bfloat16(g[2] - __bfloat162float(h2));
        __nv_bfloat16 e3 = __float2bfloat16(g[3] - __bfloat162float(h3));
        lp.x = (uint32_t)__bfloat16_as_ushort(e0) | ((uint32_t)__bfloat16_as_ushort(e1) << 16);
        lp.y = (uint32_t)__bfloat16_as_ushort(e2) | ((uint32_t)__bfloat16_as_ushort(e3) << 16);
        oh2[c4] = hp;
        ol2[c4] = lp;
    }
}

__global__ __launch_bounds__(256) void wsplit_kernel(
    const float* __restrict__ w, __nv_bfloat16* __restrict__ wh, __nv_bfloat16* __restrict__ wl)
{
    int i = blockIdx.x * 256 + threadIdx.x;
    float f = w[i];
    __nv_bfloat16 h = __float2bfloat16(f);
    wh[i] = h;
    wl[i] = __float2bfloat16(f - __bfloat162float(h));
}

__global__ __launch_bounds__(256) void wsplit_pad_kernel(
    const float* __restrict__ w, __nv_bfloat16* __restrict__ wh, __nv_bfloat16* __restrict__ wl)
{
    int i = blockIdx.x * 256 + threadIdx.x;
    int row = i >> 8;
    float f = (row < 192) ? w[i] : 0.f;
    __nv_bfloat16 h = __float2bfloat16(f);
    wh[i] = h;
    wl[i] = __float2bfloat16(f - __bfloat162float(h));
}

// ---------------- depthwise 3x3 conv ----------------
__global__ __launch_bounds__(256) void dwconv8_kernel(
    const float* __restrict__ in, const float* __restrict__ w,
    const float* __restrict__ bias, float* __restrict__ out, int C)
{
    int t = blockIdx.x * 256 + threadIdx.x;
    int x0 = (t & 7) * 8;
    int r = t >> 3;
    int hh = r & 63;
    int bc = r >> 6;
    int c = bc - (bc / C) * C;
    const float* wp = w + c * 9;
    float wr[9];
#pragma unroll
    for (int i = 0; i < 9; ++i) wr[i] = wp[i];
    const float* ip = in + (long)bc * 4096;
    float bv = bias ? bias[c] : 0.f;
    float acc[8];
#pragma unroll
    for (int j = 0; j < 8; ++j) acc[j] = bv;
#pragma unroll
    for (int ky = 0; ky < 3; ++ky) {
        int y = hh + ky - 1;
        if ((unsigned)y < 64u) {
            const float* rp = ip + y * 64 + x0;
            float4 a = *(const float4*)rp;
            float4 b4 = *(const float4*)(rp + 4);
            float v[10];
            v[0] = (x0 > 0) ? rp[-1] : 0.f;
            v[1] = a.x; v[2] = a.y; v[3] = a.z; v[4] = a.w;
            v[5] = b4.x; v[6] = b4.y; v[7] = b4.z; v[8] = b4.w;
            v[9] = (x0 < 56) ? rp[8] : 0.f;
            float k0 = wr[ky * 3 + 0], k1 = wr[ky * 3 + 1], k2 = wr[ky * 3 + 2];
#pragma unroll
            for (int j = 0; j < 8; ++j)
                acc[j] += k0 * v[j] + k1 * v[j + 1] + k2 * v[j + 2];
        }
    }
    float* op = out + (long)bc * 4096 + hh * 64 + x0;
    *(float4*)op = make_float4(acc[0], acc[1], acc[2], acc[3]);
    *(float4*)(op + 4) = make_float4(acc[4], acc[5], acc[6], acc[7]);
}

// ---------------- fused channel-LN + gated residual (+optional 2nd LN) ----------------
template<bool HAS2>
__global__ __launch_bounds__(256) void ln_gate_kernel(
    const float* __restrict__ t, const float* __restrict__ prev,
    const float* __restrict__ lnw, const float* __restrict__ lnb,
    const float* __restrict__ alpha_row, float* __restrict__ out,
    const float* __restrict__ lnw2, const float* __restrict__ lnb2,
    float* __restrict__ out2)
{
    __shared__ float r1[4][64], r2[4][64];
    int px = threadIdx.x, cg = threadIdx.y;
    int Pg = blockIdx.x * 64;
    int b = Pg >> 12, l0 = Pg & 4095;
    int base = b * DIM * L + l0 + px;

    float s1 = 0.f, s2 = 0.f;
#pragma unroll 8
    for (int c = 0; c < 64; ++c) {
        float v = t[base + (cg * 64 + c) * L];
        s1 += v; s2 += v * v;
    }
    r1[cg][px] = s1; r2[cg][px] = s2;
    __syncthreads();
    float u = (r1[0][px] + r1[1][px] + r1[2][px] + r1[3][px]) * (1.f / 256.f);
    float rs = rsqrtf((r2[0][px] + r2[1][px] + r2[2][px] + r2[3][px]) * (1.f / 256.f) - u * u + 1e-5f);

    float b1 = 0.f, b2 = 0.f;
#pragma unroll 8
    for (int c = 0; c < 64; ++c) {
        int ch = cg * 64 + c;
        int idx = base + ch * L;
        float v = t[idx];
        float nv = lnw[ch] * (v - u) * rs + lnb[ch];
        float a = sigm(alpha_row[ch]);
        float p = prev[idx];
        float xv = fmaf(a, nv - p, p);
        out[idx] = xv;
        if (HAS2) { b1 += xv; b2 += xv * xv; }
    }
    if (HAS2) {
        __syncthreads();
        r1[cg][px] = b1; r2[cg][px] = b2;
        __syncthreads();
        float u1 = (r1[0][px] + r1[1][px] + r1[2][px] + r1[3][px]) * (1.f / 256.f);
        float v1 = (r2[0][px] + r2[1][px] + r2[2][px] + r2[3][px]) * (1.f / 256.f) - u1 * u1;
        float rs2 = rsqrtf(v1 + 1e-5f);
#pragma unroll 8
        for (int c = 0; c < 64; ++c) {
            int ch = cg * 64 + c;
            int idx = base + ch * L;
            float xv = out[idx];
            out2[idx] = lnw2[ch] * (xv - u1) * rs2 + lnb2[ch];
        }
    }
}

// ---------------- small GEMM for Ld=64 ----------------
template<int OT>
__global__ __launch_bounds__(256) void gemm1x1_kernel(
    const float* __restrict__ W, const float* __restrict__ bias,
    const float* __restrict__ X, float* __restrict__ Y,
    int O, int C, int Ld)
{
    constexpr int PT = OT / 8;
    constexpr int KC = 32;
    __shared__ float Ws[OT * KC];
    int tid = threadIdx.x;
    int pxl = tid & 31;
    int og = tid >> 5;
    int b = (blockIdx.x * 64) / Ld;
    int l0 = (blockIdx.x * 64) % Ld;
    int ob = blockIdx.y * OT;
    const float* Xb = X + (b * C) * Ld + l0 + pxl * 2;

    float2 acc[PT];
#pragma unroll
    for (int i = 0; i < PT; ++i) acc[i] = make_float2(0.f, 0.f);

    for (int c0 = 0; c0 < C; c0 += KC) {
        __syncthreads();
#pragma unroll
        for (int e = tid; e < OT * KC; e += 256) {
            int ol = e >> 5, k = e & 31;
            Ws[e] = W[(ob + ol) * C + c0 + k];
        }
        __syncthreads();
#pragma unroll 4
        for (int k = 0; k < KC; ++k) {
            float2 xv = *reinterpret_cast<const float2*>(Xb + (c0 + k) * Ld);
#pragma unroll
            for (int i = 0; i < PT; ++i) {
                float wv = Ws[(og * PT + i) * KC + k];
                acc[i] = ffma2(make_float2(wv, wv), xv, acc[i]);
            }
        }
    }
#pragma unroll
    for (int i = 0; i < PT; ++i) {
        int o = ob + og * PT + i;
        float bv = bias ? bias[o] : 0.f;
        float2 r = make_float2(acc[i].x + bv, acc[i].y + bv);
        *reinterpret_cast<float2*>(Y + (b * O + o) * Ld + l0 + pxl * 2) = r;
    }
}

// ---------------- softmax over L, AB = softmax(dt)*Bm ----------------
__global__ __launch_bounds__(256) void softmax_ab_kernel(
    const float* __restrict__ bcdt2, float* __restrict__ AB)
{
    int bs = blockIdx.x;
    int b = bs >> 6, s = bs & 63;
    const float* dt = bcdt2 + (b * 192 + 128 + s) * L;
    const float* Bm = bcdt2 + (b * 192 + s) * L;
    float* out = AB + (b * 64 + s) * L;
    __shared__ float e[L];
    __shared__ float red[256];
    int tid = threadIdx.x;

    float m = -1e30f;
    for (int l = tid; l < L; l += 256) { float v = dt[l]; e[l] = v; m = fmaxf(m, v); }
    red[tid] = m; __syncthreads();
    for (int st = 128; st; st >>= 1) { if (tid < st) red[tid] = fmaxf(red[tid], red[tid + st]); __syncthreads(); }
    m = red[0];
    __syncthreads();

    float sm = 0.f;
    for (int l = tid; l < L; l += 256) { float ev = __expf(e[l] - m); e[l] = ev; sm += ev; }
    red[tid] = sm; __syncthreads();
    for (int st = 128; st; st >>= 1) { if (tid < st) red[tid] += red[tid + st]; __syncthreads(); }
    float inv = 1.f / red[0];

    for (int l = tid; l < L; l += 256) out[l] = e[l] * inv * Bm[l];
}

// ---------------- h partials ----------------
__global__ __launch_bounds__(256) void hgemm_kernel(
    const float* __restrict__ xn, const float* __restrict__ AB, float* __restrict__ hpart)
{
    int b = blockIdx.x, dtile = blockIdx.y, seg = blockIdx.z;
    int d0 = dtile * 64;
    int lb = seg * (L / NSEG);
    __shared__ float xs[64][17], as[64][17];
    int tid = threadIdx.x, tx = tid & 15, ty = tid >> 4;
    float acc[4][4];
#pragma unroll
    for (int i = 0; i < 4; ++i)
#pragma unroll
        for (int j = 0; j < 4; ++j) acc[i][j] = 0.f;

    const float* xp = xn + (b * DIM + d0) * L + lb;
    const float* ap = AB + (b * 64) * L + lb;

    for (int k0 = 0; k0 < L / NSEG; k0 += 16) {
        __syncthreads();
#pragma unroll
        for (int e = tid; e < 1024; e += 256) {
            int r = e >> 4, c = e & 15;
            xs[r][c] = xp[r * L + k0 + c];
            as[r][c] = ap[r * L + k0 + c];
        }
        __syncthreads();
#pragma unroll
        for (int k = 0; k < 16; ++k) {
            float xa[4], bb[4];
#pragma unroll
            for (int i = 0; i < 4; ++i) xa[i] = xs[ty * 4 + i][k];
#pragma unroll
            for (int j = 0; j < 4; ++j) bb[j] = as[tx * 4 + j][k];
#pragma unroll
            for (int i = 0; i < 4; ++i)
#pragma unroll
                for (int j = 0; j < 4; ++j) acc[i][j] += xa[i] * bb[j];
        }
    }
    float* hp = hpart + seg * (BATCH * DIM * STATE);
#pragma unroll
    for (int i = 0; i < 4; ++i)
#pragma unroll
        for (int j = 0; j < 4; ++j)
            hp[(b * DIM + d0 + ty * 4 + i) * STATE + tx * 4 + j] = acc[i][j];
}

__global__ __launch_bounds__(256) void hreduce_kernel(
    const float* __restrict__ hpart, float* __restrict__ h)
{
    int idx = blockIdx.x * 256 + threadIdx.x;
    float s = 0.f;
#pragma unroll
    for (int g = 0; g < NSEG; ++g) s += hpart[g * (BATCH * DIM * STATE) + idx];
    h[idx] = s;
}

__global__ __launch_bounds__(256) void gate_kernel(
    const float* __restrict__ hz, float* __restrict__ hg)
{
    int idx = blockIdx.x * 256 + threadIdx.x;
    int s = idx & 63;
    int c = (idx >> 6) & 255;
    int b = idx >> 14;
    float hp = hz[(b * 512 + c) * 64 + s];
    float z = hz[(b * 512 + 256 + c) * 64 + s];
    hg[idx] = hp * z * sigm(z);
}

// ---------------- y = ho @ Cm ; x2 ----------------
__global__ __launch_bounds__(256) void y_fuse_kernel(
    const float* __restrict__ ho, const float* __restrict__ bcdt2,
    const float* __restrict__ xn, const float* __restrict__ x1,
    const float* __restrict__ Dp, const float* __restrict__ alpha1,
    float* __restrict__ x2)
{
    __shared__ float hos[16][257];
    int tid = threadIdx.x;
    int px = tid & 63, dg = tid >> 6;
    int Pg = blockIdx.x * 64;
    int b = Pg >> 12, l0 = Pg & 4095;
    const float* hob = ho + b * DIM * STATE;
    const float* cm = bcdt2 + (b * 192 + 64) * L + l0 + px;

    float acc[64];
#pragma unroll
    for (int j = 0; j < 64; ++j) acc[j] = 0.f;

    for (int sc = 0; sc < 4; ++sc) {
        __syncthreads();
#pragma unroll
        for (int e = tid; e < 4096; e += 256) {
            int d = e >> 4, s = e & 15;
            hos[s][d] = hob[d * 64 + sc * 16 + s];
        }
        __syncthreads();
#pragma unroll
        for (int s = 0; s < 16; ++s) {
            float cmv = cm[(sc * 16 + s) * L];
#pragma unroll
            for (int j = 0; j < 64; ++j)
                acc[j] += hos[s][dg * 64 + j] * cmv;
        }
    }
#pragma unroll
    for (int j = 0; j < 64; ++j) {
        int d = dg * 64 + j;
        int idx = (b * DIM + d) * L + l0 + px;
        float y = acc[j] + xn[idx] * Dp[d];
        float a = sigm(alpha1[d]);
        float p = x1[idx];
        x2[idx] = fmaf(a, y - p, p);
    }
}

__global__ __launch_bounds__(256) void copy_kernel(
    const float* __restrict__ src, float* __restrict__ dst)
{
    int idx = blockIdx.x * 256 + threadIdx.x;
    dst[idx] = src[idx];
}

// ---------------- host launcher ----------------
extern "C" void kernel_launch(void* const* d_in, const int* in_sizes, int n_in,
                              void* d_out, int out_size)
{
    const float* x        = (const float*)d_in[0];
    const float* alpha    = (const float*)d_in[1];
    const float* ln_w     = (const float*)d_in[2];
    const float* ln_b     = (const float*)d_in[3];
    const float* dw1_w    = (const float*)d_in[4];
    const float* dw1_ln_w = (const float*)d_in[5];
    const float* dw1_ln_b = (const float*)d_in[6];
    const float* dw2_w    = (const float*)d_in[7];
    const float* dw2_ln_w = (const float*)d_in[8];
    const float* dw2_ln_b = (const float*)d_in[9];
    const float* bcdt_w   = (const float*)d_in[10];
    const float* bcdt_b   = (const float*)d_in[11];
    const float* dwm_w    = (const float*)d_in[12];
    const float* dwm_b    = (const float*)d_in[13];
    const float* hz_w     = (const float*)d_in[14];
    const float* hz_b     = (const float*)d_in[15];
    const float* outp_w   = (const float*)d_in[16];
    const float* outp_b   = (const float*)d_in[17];
    const float* Dp       = (const float*)d_in[19];
    const float* fc1_w    = (const float*)d_in[20];
    const float* fc1_ln_w = (const float*)d_in[21];
    const float* fc1_ln_b = (const float*)d_in[22];
    const float* fc2_w    = (const float*)d_in[23];
    const float* fc2_ln_w = (const float*)d_in[24];
    const float* fc2_ln_b = (const float*)d_in[25];
    float* out = (float*)d_out;

    float *t0, *x1, *xn, *x2, *x3, *bc, *bc2, *ab, *hpart, *h, *hz, *hg, *ho, *f1t;
    __nv_bfloat16 *x3th, *x3tl, *xnth, *xntl, *f1th, *f1tl, *w1h, *w1l, *w2h, *w2l, *wbch, *wbcl;
    cudaGetSymbolAddress((void**)&t0, g_t0);
    cudaGetSymbolAddress((void**)&x1, g_x1);
    cudaGetSymbolAddress((void**)&xn, g_xn);
    cudaGetSymbolAddress((void**)&x2, g_x2);
    cudaGetSymbolAddress((void**)&x3, g_x3);
    cudaGetSymbolAddress((void**)&bc, g_bcdt);
    cudaGetSymbolAddress((void**)&bc2, g_bcdt2);
    cudaGetSymbolAddress((void**)&ab, g_AB);
    cudaGetSymbolAddress((void**)&hpart, g_hpart);
    cudaGetSymbolAddress((void**)&h, g_h);
    cudaGetSymbolAddress((void**)&hz, g_hz);
    cudaGetSymbolAddress((void**)&hg, g_hg);
    cudaGetSymbolAddress((void**)&ho, g_ho);
    cudaGetSymbolAddress((void**)&f1t, g_f1t);
    cudaGetSymbolAddress((void**)&x3th, g_x3th);
    cudaGetSymbolAddress((void**)&x3tl, g_x3tl);
    cudaGetSymbolAddress((void**)&xnth, g_xnth);
    cudaGetSymbolAddress((void**)&xntl, g_xntl);
    cudaGetSymbolAddress((void**)&f1th, g_f1th);
    cudaGetSymbolAddress((void**)&f1tl, g_f1tl);
    cudaGetSymbolAddress((void**)&w1h, g_w1h);
    cudaGetSymbolAddress((void**)&w1l, g_w1l);
    cudaGetSymbolAddress((void**)&w2h, g_w2h);
    cudaGetSymbolAddress((void**)&w2l, g_w2l);
    cudaGetSymbolAddress((void**)&wbch, g_wbch);
    cudaGetSymbolAddress((void**)&wbcl, g_wbcl);

    cudaFuncSetAttribute(gemm_mma_kernel<0>, cudaFuncAttributeMaxDynamicSharedMemorySize, GSMEM);
    cudaFuncSetAttribute(gemm_mma_kernel<1>, cudaFuncAttributeMaxDynamicSharedMemorySize, GSMEM);

    dim3 blk2(64, 4);

    // weight splits
    wsplit_kernel<<<HIDDEN * DIM / 256, 256>>>(fc1_w, w1h, w1l);
    wsplit_kernel<<<DIM * HIDDEN / 256, 256>>>(fc2_w, w2h, w2l);
    wsplit_pad_kernel<<<256 * DIM / 256, 256>>>(bcdt_w, wbch, wbcl);

    // sub-layer 1: dwconv + LN+gate (+2nd LN), then transpose+split xn
    dwconv8_kernel<<<BATCH * DIM * L / 8 / 256, 256>>>(x, dw1_w, nullptr, t0, DIM);
    ln_gate_kernel<true><<<PIXBLK, blk2>>>(t0, x, dw1_ln_w, dw1_ln_b, alpha, x1,
                                           ln_w, ln_b, xn);
    convt_kernel<<<dim3(L / 32, DIM / 64, BATCH), 256>>>(xn, xnth, xntl, DIM);

    // HSMSSD mixer
    gemm_mma_kernel<0><<<dim3(NPIX / 256, 2), 256, GSMEM>>>(wbch, wbcl, xnth, xntl, bc, bcdt_b, 192, 256);
    dwconv8_kernel<<<BATCH * 192 * L / 8 / 256, 256>>>(bc, dwm_w, dwm_b, bc2, 192);
    softmax_ab_kernel<<<BATCH * 64, 256>>>(bc2, ab);
    hgemm_kernel<<<dim3(BATCH, 4, NSEG), 256>>>(xn, ab, hpart);
    hreduce_kernel<<<BATCH * DIM * STATE / 256, 256>>>(hpart, h);
    gemm1x1_kernel<128><<<dim3(BATCH, 4), 256>>>(hz_w, hz_b, h, hz, 512, 256, 64);
    gate_kernel<<<BATCH * DIM * STATE / 256, 256>>>(hz, hg);
    gemm1x1_kernel<128><<<dim3(BATCH, 2), 256>>>(outp_w, outp_b, hg, ho, 256, 256, 64);
    y_fuse_kernel<<<PIXBLK, 256>>>(ho, bc2, xn, x1, Dp, alpha + 256, x2);

    // sub-layer 3: dwconv + LN+gate, then transpose+split x3
    dwconv8_kernel<<<BATCH * DIM * L / 8 / 256, 256>>>(x2, dw2_w, nullptr, t0, DIM);
    ln_gate_kernel<false><<<PIXBLK, blk2>>>(t0, x2, dw2_ln_w, dw2_ln_b, alpha + 512, x3,
                                            nullptr, nullptr, nullptr);
    convt_kernel<<<dim3(L / 32, DIM / 64, BATCH), 256>>>(x3, x3th, x3tl, DIM);

    // FFN: fc1 (transposed out) -> fused LN+SiLU+split -> fc2 -> final LN+gate
    gemm_mma_kernel<1><<<dim3(NPIX / 256, HIDDEN / 128), 256, GSMEM>>>(w1h, w1l, x3th, x3tl, f1t, nullptr, HIDDEN, 256);
    ln_silu_split_kernel<<<NPIX / 8, 256>>>(f1t, f1th, f1tl, fc1_ln_w, fc1_ln_b);
    gemm_mma_kernel<0><<<dim3(NPIX / 256, 2), 256, GSMEM>>>(w2h, w2l, f1th, f1tl, t0, nullptr, 256, 1024);
    ln_gate_kernel<false><<<PIXBLK, blk2>>>(t0, x3, fc2_ln_w, fc2_ln_b, alpha + 768, out,
                                            nullptr, nullptr, nullptr);

    // second output: h
    if (out_size >= BATCH * DIM * L + BATCH * DIM * STATE)
        copy_kernel<<<BATCH * DIM * STATE / 256, 256>>>(h, out + BATCH * DIM * L);
}

// round 11
// speedup vs baseline: 1.4682x; 1.0200x over previous
#include <cuda_runtime.h>
#include <cuda_bf16.h>
#include <cstdint>
#include <math.h>

#define BATCH 16
#define DIM 256
#define STATE 64
#define HIDDEN 1024
#define L 4096
#define NPIX (BATCH*L)
#define PIXBLK (NPIX/64)
#define NSEG 8

// ---------------- scratch ----------------
__device__ float g_t0[BATCH*DIM*L];
__device__ float g_x1[BATCH*DIM*L];
__device__ float g_xn[BATCH*DIM*L];
__device__ float g_x2[BATCH*DIM*L];
__device__ float g_x3[BATCH*DIM*L];
__device__ float g_bcdt[BATCH*192*L];
__device__ float g_bcdt2[BATCH*192*L];
__device__ float g_AB[BATCH*STATE*L];
__device__ float g_hpart[NSEG*BATCH*DIM*STATE];
__device__ float g_h[BATCH*DIM*STATE];
__device__ float g_hz[BATCH*2*DIM*STATE];
__device__ float g_hg[BATCH*DIM*STATE];
__device__ float g_ho[BATCH*DIM*STATE];
__device__ float g_f1t[(size_t)BATCH*L*HIDDEN];          // fc1 output, TRANSPOSED [b*L, 1024] fp32
__device__ __nv_bfloat16 g_x3th[BATCH*L*DIM];
__device__ __nv_bfloat16 g_x3tl[BATCH*L*DIM];
__device__ __nv_bfloat16 g_xnth[BATCH*L*DIM];
__device__ __nv_bfloat16 g_xntl[BATCH*L*DIM];
__device__ __nv_bfloat16 g_f1th[(size_t)BATCH*L*HIDDEN];
__device__ __nv_bfloat16 g_f1tl[(size_t)BATCH*L*HIDDEN];
__device__ __nv_bfloat16 g_w1h[HIDDEN*DIM];
__device__ __nv_bfloat16 g_w1l[HIDDEN*DIM];
__device__ __nv_bfloat16 g_w2h[DIM*HIDDEN];
__device__ __nv_bfloat16 g_w2l[DIM*HIDDEN];
__device__ __nv_bfloat16 g_wbch[256*DIM];                 // bcdt weights padded to 256 rows
__device__ __nv_bfloat16 g_wbcl[256*DIM];

// ---------------- helpers ----------------
__device__ __forceinline__ float2 ffma2(float2 a, float2 b, float2 c) {
    float2 d;
    asm("{\n\t.reg .b64 ra, rb, rc, rd;\n\t"
        "mov.b64 ra, {%2, %3};\n\tmov.b64 rb, {%4, %5};\n\tmov.b64 rc, {%6, %7};\n\t"
        "fma.rn.f32x2 rd, ra, rb, rc;\n\tmov.b64 {%0, %1}, rd;\n\t}"
        : "=f"(d.x), "=f"(d.y)
        : "f"(a.x), "f"(a.y), "f"(b.x), "f"(b.y), "f"(c.x), "f"(c.y));
    return d;
}
__device__ __forceinline__ float sigm(float v) { return 1.f / (1.f + __expf(-v)); }
__device__ __forceinline__ float4 f4add(float4 a, float4 b) {
    return make_float4(a.x + b.x, a.y + b.y, a.z + b.z, a.w + b.w);
}

#define CPA16(dst, src) asm volatile("cp.async.cg.shared.global [%0], [%1], 16;" :: "r"(dst), "l"(src))
#define SWZ(o) ((o) ^ (((o) >> 3) & 0x70u))

__device__ __forceinline__ uint32_t s2u(const void* p) {
    uint32_t a;
    asm("{ .reg .u64 t; cvta.to.shared.u64 t, %1; cvt.u32.u64 %0, t; }" : "=r"(a) : "l"(p));
    return a;
}

#define LDSM4(r, a) \
    asm volatile("ldmatrix.sync.aligned.m8n8.x4.shared.b16 {%0,%1,%2,%3}, [%4];" \
        : "=r"((r)[0]), "=r"((r)[1]), "=r"((r)[2]), "=r"((r)[3]) : "r"(a))

#define MMA16816(d, a, b) \
    asm volatile("mma.sync.aligned.m16n8k16.row.col.f32.bf16.bf16.f32 " \
        "{%0,%1,%2,%3},{%4,%5,%6,%7},{%8,%9},{%0,%1,%2,%3};" \
        : "+f"((d)[0]), "+f"((d)[1]), "+f"((d)[2]), "+f"((d)[3]) \
        : "r"((a)[0]), "r"((a)[1]), "r"((a)[2]), "r"((a)[3]), "r"((b)[0]), "r"((b)[1]))

// ---------------- tensor-core GEMM (mma.sync bf16 hi/lo), tile M128 x N256 -------------------
#define GSMEM 196608
template<int TRANS>
__global__ __launch_bounds__(256) void gemm_mma_kernel(
    const __nv_bfloat16* __restrict__ Wh, const __nv_bfloat16* __restrict__ Wl,
    const __nv_bfloat16* __restrict__ Xh, const __nv_bfloat16* __restrict__ Xl,
    float* __restrict__ Y, const float* __restrict__ bias, int O, int C)
{
    extern __shared__ char dsm[];
    uint32_t sb = s2u(dsm);
    int tid = threadIdx.x, warp = tid >> 5, lane = tid & 31;
    int wm = warp >> 2, wn = warp & 3;
    int bb = blockIdx.x >> 4;
    int l0 = (blockIdx.x & 15) << 8;
    int m0 = blockIdx.y << 7;
    int nchunk = C >> 6;
    size_t rowb = (size_t)bb * 4096 + l0;

    float acc[4][8][4];
#pragma unroll
    for (int i = 0; i < 4; ++i)
#pragma unroll
        for (int j = 0; j < 8; ++j)
#pragma unroll
            for (int q = 0; q < 4; ++q) acc[i][j][q] = 0.f;

    auto issue = [&](int cc, int buf) {
        int c0 = cc << 6;
        uint32_t base = sb + (uint32_t)buf * 98304u;
#pragma unroll
        for (int i = 0; i < 4; ++i) {
            int e = tid + i * 256;
            int row = e >> 3, c16 = e & 7;
            uint32_t sw = SWZ((uint32_t)(row * 128 + c16 * 16));
            CPA16(base + sw,           Wh + (size_t)(m0 + row) * C + c0 + c16 * 8);
            CPA16(base + 16384u + sw,  Wl + (size_t)(m0 + row) * C + c0 + c16 * 8);
        }
#pragma unroll
        for (int i = 0; i < 8; ++i) {
            int e = tid + i * 256;
            int row = e >> 3, c16 = e & 7;
            uint32_t sw = SWZ((uint32_t)(row * 128 + c16 * 16));
            CPA16(base + 32768u + sw,  Xh + (rowb + row) * (size_t)C + c0 + c16 * 8);
            CPA16(base + 65536u + sw,  Xl + (rowb + row) * (size_t)C + c0 + c16 * 8);
        }
        asm volatile("cp.async.commit_group;");
    };

    issue(0, 0);
    for (int cc = 0; cc < nchunk; ++cc) {
        int buf = cc & 1;
        if (cc + 1 < nchunk) {
            issue(cc + 1, buf ^ 1);
            asm volatile("cp.async.wait_group 1;");
        } else {
            asm volatile("cp.async.wait_group 0;");
        }
        __syncthreads();
        uint32_t base = sb + (uint32_t)buf * 98304u;

        int lr = (lane & 7) + ((lane >> 3) & 1) * 8;
        int kb = (lane >> 4) * 8;
#pragma unroll
        for (int kt = 0; kt < 4; ++kt) {
            uint32_t ah[4][4], al[4][4];
#pragma unroll
            for (int mt = 0; mt < 4; ++mt) {
                int row = wm * 64 + mt * 16 + lr;
                uint32_t a = base + SWZ((uint32_t)(row * 128 + (kt * 16 + kb) * 2));
                LDSM4(ah[mt], a);
                LDSM4(al[mt], a + 16384u);
            }
            uint32_t bh[8][2], bl[8][2];
#pragma unroll
            for (int np = 0; np < 4; ++np) {
                int row = wn * 64 + np * 16 + lr;
                uint32_t a = base + 32768u + SWZ((uint32_t)(row * 128 + (kt * 16 + kb) * 2));
                uint32_t r[4], rl[4];
                LDSM4(r, a);
                LDSM4(rl, a + 32768u);
                bh[np * 2][0] = r[0]; bh[np * 2][1] = r[2];
                bh[np * 2 + 1][0] = r[1]; bh[np * 2 + 1][1] = r[3];
                bl[np * 2][0] = rl[0]; bl[np * 2][1] = rl[2];
                bl[np * 2 + 1][0] = rl[1]; bl[np * 2 + 1][1] = rl[3];
            }
#pragma unroll
            for (int mt = 0; mt < 4; ++mt)
#pragma unroll
                for (int nt = 0; nt < 8; ++nt) {
                    MMA16816(acc[mt][nt], ah[mt], bh[nt]);
                    MMA16816(acc[mt][nt], ah[mt], bl[nt]);
                    MMA16816(acc[mt][nt], al[mt], bh[nt]);
                }
        }
        __syncthreads();
    }

    int mrow = (lane >> 2);
    int ncol = (lane & 3) * 2;
    if (TRANS == 0) {
#pragma unroll
        for (int mt = 0; mt < 4; ++mt) {
            int o = m0 + wm * 64 + mt * 16 + mrow;
            float bv0 = (o < O && bias) ? bias[o] : 0.f;
            float bv1 = (o + 8 < O && bias) ? bias[o + 8] : 0.f;
            float* yp0 = Y + ((size_t)bb * O + o) * 4096 + l0 + wn * 64;
            float* yp1 = Y + ((size_t)bb * O + o + 8) * 4096 + l0 + wn * 64;
#pragma unroll
            for (int nt = 0; nt < 8; ++nt) {
                if (o < O)
                    *(float2*)(yp0 + nt * 8 + ncol) = make_float2(acc[mt][nt][0] + bv0, acc[mt][nt][1] + bv0);
                if (o + 8 < O)
                    *(float2*)(yp1 + nt * 8 + ncol) = make_float2(acc[mt][nt][2] + bv1, acc[mt][nt][3] + bv1);
            }
        }
    } else {
        float* st = (float*)dsm;
#pragma unroll
        for (int mt = 0; mt < 4; ++mt) {
            int ob = wm * 64 + mt * 16 + mrow;
#pragma unroll
            for (int nt = 0; nt < 8; ++nt) {
                int pxb = wn * 64 + nt * 8 + ncol;
                st[(size_t)pxb * 132 + ob] = acc[mt][nt][0];
                st[(size_t)(pxb + 1) * 132 + ob] = acc[mt][nt][1];
                st[(size_t)pxb * 132 + ob + 8] = acc[mt][nt][2];
                st[(size_t)(pxb + 1) * 132 + ob + 8] = acc[mt][nt][3];
            }
        }
        __syncthreads();
        int px = tid;
        float* dst = Y + (rowb + px) * (size_t)O + m0;
        const float* src = st + (size_t)px * 132;
#pragma unroll
        for (int j = 0; j < 32; ++j)
            *(float4*)(dst + j * 4) = *(const float4*)(src + j * 4);
    }
}

// ---------------- transpose + bf16 hi/lo split: [b,C,L] f32 -> [b*L, C] bf16 x2 --------------
__global__ __launch_bounds__(256) void convt_kernel(
    const float* __restrict__ in, __nv_bfloat16* __restrict__ oh,
    __nv_bfloat16* __restrict__ ol, int C)
{
    __shared__ float s[64][33];
    int tid = threadIdx.x;
    int lx = tid & 31, cy = tid >> 5;
    int l0 = blockIdx.x * 32;
    int c0 = blockIdx.y * 64;
    int b = blockIdx.z;
    const float* ip = in + ((size_t)b * C + c0) * L + l0;
#pragma unroll
    for (int i = 0; i < 8; ++i)
        s[cy + i * 8][lx] = ip[(size_t)(cy + i * 8) * L + lx];
    __syncthreads();
    int cp = tid & 31, ly = tid >> 5;
#pragma unroll
    for (int i = 0; i < 4; ++i) {
        int lrow = ly + i * 8;
        float f0 = s[2 * cp][lrow], f1 = s[2 * cp + 1][lrow];
        __nv_bfloat16 h0 = __float2bfloat16(f0);
        __nv_bfloat16 h1 = __float2bfloat16(f1);
        __nv_bfloat16 e0 = __float2bfloat16(f0 - __bfloat162float(h0));
        __nv_bfloat16 e1 = __float2bfloat16(f1 - __bfloat162float(h1));
        uint32_t hp = (uint32_t)__bfloat16_as_ushort(h0) | ((uint32_t)__bfloat16_as_ushort(h1) << 16);
        uint32_t lp = (uint32_t)__bfloat16_as_ushort(e0) | ((uint32_t)__bfloat16_as_ushort(e1) << 16);
        size_t o32 = (((size_t)b * L + l0 + lrow) * C + c0) / 2 + cp;
        ((uint32_t*)oh)[o32] = hp;
        ((uint32_t*)ol)[o32] = lp;
    }
}

// ---------------- fused LN(1024) + SiLU + bf16 hi/lo split ----------------
__global__ __launch_bounds__(256) void ln_silu_split_kernel(
    const float* __restrict__ f1t, __nv_bfloat16* __restrict__ oh, __nv_bfloat16* __restrict__ ol,
    const float* __restrict__ lnw, const float* __restrict__ lnb)
{
    int warp = threadIdx.x >> 5, lane = threadIdx.x & 31;
    size_t px = (size_t)blockIdx.x * 8 + warp;
    const float4* row = (const float4*)(f1t + px * 1024);
    const float4* w4 = (const float4*)lnw;
    const float4* b4 = (const float4*)lnb;

    float4 v[8];
    float s1 = 0.f, s2 = 0.f;
#pragma unroll
    for (int i = 0; i < 8; ++i) {
        v[i] = row[lane + i * 32];
        s1 += v[i].x + v[i].y + v[i].z + v[i].w;
        s2 += v[i].x * v[i].x + v[i].y * v[i].y + v[i].z * v[i].z + v[i].w * v[i].w;
    }
#pragma unroll
    for (int st = 16; st; st >>= 1) {
        s1 += __shfl_xor_sync(0xFFFFFFFF, s1, st);
        s2 += __shfl_xor_sync(0xFFFFFFFF, s2, st);
    }
    float u = s1 * (1.f / 1024.f);
    float rs = rsqrtf(s2 * (1.f / 1024.f) - u * u + 1e-5f);

    uint2* oh2 = (uint2*)(oh + px * 1024);
    uint2* ol2 = (uint2*)(ol + px * 1024);
#pragma unroll
    for (int i = 0; i < 8; ++i) {
        int c4 = lane + i * 32;
        float4 wv = w4[c4], bv = b4[c4];
        float g[4];
        g[0] = wv.x * (v[i].x - u) * rs + bv.x;
        g[1] = wv.y * (v[i].y - u) * rs + bv.y;
        g[2] = wv.z * (v[i].z - u) * rs + bv.z;
        g[3] = wv.w * (v[i].w - u) * rs + bv.w;
#pragma unroll
        for (int j = 0; j < 4; ++j) g[j] = g[j] * sigm(g[j]);
        __nv_bfloat16 h0 = __float2bfloat16(g[0]), h1 = __float2bfloat16(g[1]);
        __nv_bfloat16 h2 = __float2bfloat16(g[2]), h3 = __float2bfloat16(g[3]);
        uint2 hp, lp;
        hp.x = (uint32_t)__bfloat16_as_ushort(h0) | ((uint32_t)__bfloat16_as_ushort(h1) << 16);
        hp.y = (uint32_t)__bfloat16_as_ushort(h2) | ((uint32_t)__bfloat16_as_ushort(h3) << 16);
        __nv_bfloat16 e0 = __float2bfloat16(g[0] - __bfloat162float(h0));
        __nv_bfloat16 e1 = __float2bfloat16(g[1] - __bfloat162float(h1));
        __nv_bfloat16 e2 = __float2bfloat16(g[2] - __bfloat162float(h2));
        __nv_bfloat16 e3 = __float2bfloat16(g[3] - __bfloat162float(h3));
        lp.x = (uint32_t)__bfloat16_as_ushort(e0) | ((uint32_t)__bfloat16_as_ushort(e1) << 16);
        lp.y = (uint32_t)__bfloat16_as_ushort(e2) | ((uint32_t)__bfloat16_as_ushort(e3) << 16);
        oh2[c4] = hp;
        ol2[c4] = lp;
    }
}

__global__ __launch_bounds__(256) void wsplit_kernel(
    const float* __restrict__ w, __nv_bfloat16* __restrict__ wh, __nv_bfloat16* __restrict__ wl)
{
    int i = blockIdx.x * 256 + threadIdx.x;
    float f = w[i];
    __nv_bfloat16 h = __float2bfloat16(f);
    wh[i] = h;
    wl[i] = __float2bfloat16(f - __bfloat162float(h));
}

__global__ __launch_bounds__(256) void wsplit_pad_kernel(
    const float* __restrict__ w, __nv_bfloat16* __restrict__ wh, __nv_bfloat16* __restrict__ wl)
{
    int i = blockIdx.x * 256 + threadIdx.x;
    int row = i >> 8;
    float f = (row < 192) ? w[i] : 0.f;
    __nv_bfloat16 h = __float2bfloat16(f);
    wh[i] = h;
    wl[i] = __float2bfloat16(f - __bfloat162float(h));
}

// ---------------- depthwise 3x3 conv ----------------
__global__ __launch_bounds__(256) void dwconv8_kernel(
    const float* __restrict__ in, const float* __restrict__ w,
    const float* __restrict__ bias, float* __restrict__ out, int C)
{
    int t = blockIdx.x * 256 + threadIdx.x;
    int x0 = (t & 7) * 8;
    int r = t >> 3;
    int hh = r & 63;
    int bc = r >> 6;
    int c = bc - (bc / C) * C;
    const float* wp = w + c * 9;
    float wr[9];
#pragma unroll
    for (int i = 0; i < 9; ++i) wr[i] = wp[i];
    const float* ip = in + (long)bc * 4096;
    float bv = bias ? bias[c] : 0.f;
    float acc[8];
#pragma unroll
    for (int j = 0; j < 8; ++j) acc[j] = bv;
#pragma unroll
    for (int ky = 0; ky < 3; ++ky) {
        int y = hh + ky - 1;
        if ((unsigned)y < 64u) {
            const float* rp = ip + y * 64 + x0;
            float4 a = *(const float4*)rp;
            float4 b4 = *(const float4*)(rp + 4);
            float v[10];
            v[0] = (x0 > 0) ? rp[-1] : 0.f;
            v[1] = a.x; v[2] = a.y; v[3] = a.z; v[4] = a.w;
            v[5] = b4.x; v[6] = b4.y; v[7] = b4.z; v[8] = b4.w;
            v[9] = (x0 < 56) ? rp[8] : 0.f;
            float k0 = wr[ky * 3 + 0], k1 = wr[ky * 3 + 1], k2 = wr[ky * 3 + 2];
#pragma unroll
            for (int j = 0; j < 8; ++j)
                acc[j] += k0 * v[j] + k1 * v[j + 1] + k2 * v[j + 2];
        }
    }
    float* op = out + (long)bc * 4096 + hh * 64 + x0;
    *(float4*)op = make_float4(acc[0], acc[1], acc[2], acc[3]);
    *(float4*)(op + 4) = make_float4(acc[4], acc[5], acc[6], acc[7]);
}

// ---------------- fused channel-LN + gated residual (+optional 2nd LN), float4 over px -------
// block (64,4): threadIdx.x = px-quad (64 quads = 256 px), threadIdx.y = channel group.
template<bool HAS2>
__global__ __launch_bounds__(256) void ln_gate_kernel(
    const float* __restrict__ t, const float* __restrict__ prev,
    const float* __restrict__ lnw, const float* __restrict__ lnb,
    const float* __restrict__ alpha_row, float* __restrict__ out,
    const float* __restrict__ lnw2, const float* __restrict__ lnb2,
    float* __restrict__ out2)
{
    __shared__ float4 r1[4][64], r2[4][64];
    int qx = threadIdx.x, cg = threadIdx.y;
    int Pg = blockIdx.x * 256;
    int b = Pg >> 12, l0 = Pg & 4095;
    size_t base = ((size_t)(b * DIM) * L + l0 + qx * 4) >> 2;   // float4 index

    const float4* t4 = (const float4*)t;
    const float4* p4 = (const float4*)prev;
    float4* o4 = (float4*)out;
    float4* o24 = (float4*)out2;
    const size_t L4 = L / 4;

    float4 s1 = make_float4(0.f, 0.f, 0.f, 0.f), s2 = s1;
#pragma unroll 8
    for (int c = 0; c < 64; ++c) {
        float4 v = t4[base + (size_t)(cg * 64 + c) * L4];
        s1 = f4add(s1, v);
        s2 = f4add(s2, make_float4(v.x * v.x, v.y * v.y, v.z * v.z, v.w * v.w));
    }
    r1[cg][qx] = s1; r2[cg][qx] = s2;
    __syncthreads();
    float4 ts1 = f4add(f4add(r1[0][qx], r1[1][qx]), f4add(r1[2][qx], r1[3][qx]));
    float4 ts2 = f4add(f4add(r2[0][qx], r2[1][qx]), f4add(r2[2][qx], r2[3][qx]));
    float4 u = make_float4(ts1.x * (1.f / 256.f), ts1.y * (1.f / 256.f),
                           ts1.z * (1.f / 256.f), ts1.w * (1.f / 256.f));
    float4 rs = make_float4(
        rsqrtf(ts2.x * (1.f / 256.f) - u.x * u.x + 1e-5f),
        rsqrtf(ts2.y * (1.f / 256.f) - u.y * u.y + 1e-5f),
        rsqrtf(ts2.z * (1.f / 256.f) - u.z * u.z + 1e-5f),
        rsqrtf(ts2.w * (1.f / 256.f) - u.w * u.w + 1e-5f));

    float4 b1 = make_float4(0.f, 0.f, 0.f, 0.f), b2 = b1;
#pragma unroll 8
    for (int c = 0; c < 64; ++c) {
        int ch = cg * 64 + c;
        size_t idx = base + (size_t)ch * L4;
        float4 v = t4[idx];
        float4 p = p4[idx];
        float w = lnw[ch], bb = lnb[ch];
        float a = sigm(alpha_row[ch]);
        float4 xv;
        xv.x = fmaf(a, fmaf(w, (v.x - u.x) * rs.x, bb) - p.x, p.x);
        xv.y = fmaf(a, fmaf(w, (v.y - u.y) * rs.y, bb) - p.y, p.y);
        xv.z = fmaf(a, fmaf(w, (v.z - u.z) * rs.z, bb) - p.z, p.z);
        xv.w = fmaf(a, fmaf(w, (v.w - u.w) * rs.w, bb) - p.w, p.w);
        o4[idx] = xv;
        if (HAS2) {
            b1 = f4add(b1, xv);
            b2 = f4add(b2, make_float4(xv.x * xv.x, xv.y * xv.y, xv.z * xv.z, xv.w * xv.w));
        }
    }
    if (HAS2) {
        __syncthreads();
        r1[cg][qx] = b1; r2[cg][qx] = b2;
        __syncthreads();
        float4 q1 = f4add(f4add(r1[0][qx], r1[1][qx]), f4add(r1[2][qx], r1[3][qx]));
        float4 q2 = f4add(f4add(r2[0][qx], r2[1][qx]), f4add(r2[2][qx], r2[3][qx]));
        float4 u1 = make_float4(q1.x * (1.f / 256.f), q1.y * (1.f / 256.f),
                                q1.z * (1.f / 256.f), q1.w * (1.f / 256.f));
        float4 rs2 = make_float4(
            rsqrtf(q2.x * (1.f / 256.f) - u1.x * u1.x + 1e-5f),
            rsqrtf(q2.y * (1.f / 256.f) - u1.y * u1.y + 1e-5f),
            rsqrtf(q2.z * (1.f / 256.f) - u1.z * u1.z + 1e-5f),
            rsqrtf(q2.w * (1.f / 256.f) - u1.w * u1.w + 1e-5f));
#pragma unroll 8
        for (int c = 0; c < 64; ++c) {
            int ch = cg * 64 + c;
            size_t idx = base + (size_t)ch * L4;
            float4 xv = o4[idx];
            float w = lnw2[ch], bb = lnb2[ch];
            float4 nv;
            nv.x = fmaf(w, (xv.x - u1.x) * rs2.x, bb);
            nv.y = fmaf(w, (xv.y - u1.y) * rs2.y, bb);
            nv.z = fmaf(w, (xv.z - u1.z) * rs2.z, bb);
            nv.w = fmaf(w, (xv.w - u1.w) * rs2.w, bb);
            o24[idx] = nv;
        }
    }
}

// ---------------- small GEMM for Ld=64 ----------------
template<int OT>
__global__ __launch_bounds__(256) void gemm1x1_kernel(
    const float* __restrict__ W, const float* __restrict__ bias,
    const float* __restrict__ X, float* __restrict__ Y,
    int O, int C, int Ld)
{
    constexpr int PT = OT / 8;
    constexpr int KC = 32;
    __shared__ float Ws[OT * KC];
    int tid = threadIdx.x;
    int pxl = tid & 31;
    int og = tid >> 5;
    int b = (blockIdx.x * 64) / Ld;
    int l0 = (blockIdx.x * 64) % Ld;
    int ob = blockIdx.y * OT;
    const float* Xb = X + (b * C) * Ld + l0 + pxl * 2;

    float2 acc[PT];
#pragma unroll
    for (int i = 0; i < PT; ++i) acc[i] = make_float2(0.f, 0.f);

    for (int c0 = 0; c0 < C; c0 += KC) {
        __syncthreads();
#pragma unroll
        for (int e = tid; e < OT * KC; e += 256) {
            int ol = e >> 5, k = e & 31;
            Ws[e] = W[(ob + ol) * C + c0 + k];
        }
        __syncthreads();
#pragma unroll 4
        for (int k = 0; k < KC; ++k) {
            float2 xv = *reinterpret_cast<const float2*>(Xb + (c0 + k) * Ld);
#pragma unroll
            for (int i = 0; i < PT; ++i) {
                float wv = Ws[(og * PT + i) * KC + k];
                acc[i] = ffma2(make_float2(wv, wv), xv, acc[i]);
            }
        }
    }
#pragma unroll
    for (int i = 0; i < PT; ++i) {
        int o = ob + og * PT + i;
        float bv = bias ? bias[o] : 0.f;
        float2 r = make_float2(acc[i].x + bv, acc[i].y + bv);
        *reinterpret_cast<float2*>(Y + (b * O + o) * Ld + l0 + pxl * 2) = r;
    }
}

// ---------------- softmax over L, AB = softmax(dt)*Bm ----------------
__global__ __launch_bounds__(256) void softmax_ab_kernel(
    const float* __restrict__ bcdt2, float* __restrict__ AB)
{
    int bs = blockIdx.x;
    int b = bs >> 6, s = bs & 63;
    const float* dt = bcdt2 + (b * 192 + 128 + s) * L;
    const float* Bm = bcdt2 + (b * 192 + s) * L;
    float* out = AB + (b * 64 + s) * L;
    __shared__ float e[L];
    __shared__ float red[256];
    int tid = threadIdx.x;

    float m = -1e30f;
    for (int l = tid; l < L; l += 256) { float v = dt[l]; e[l] = v; m = fmaxf(m, v); }
    red[tid] = m; __syncthreads();
    for (int st = 128; st; st >>= 1) { if (tid < st) red[tid] = fmaxf(red[tid], red[tid + st]); __syncthreads(); }
    m = red[0];
    __syncthreads();

    float sm = 0.f;
    for (int l = tid; l < L; l += 256) { float ev = __expf(e[l] - m); e[l] = ev; sm += ev; }
    red[tid] = sm; __syncthreads();
    for (int st = 128; st; st >>= 1) { if (tid < st) red[tid] += red[tid + st]; __syncthreads(); }
    float inv = 1.f / red[0];

    for (int l = tid; l < L; l += 256) out[l] = e[l] * inv * Bm[l];
}

// ---------------- h partials ----------------
__global__ __launch_bounds__(256) void hgemm_kernel(
    const float* __restrict__ xn, const float* __restrict__ AB, float* __restrict__ hpart)
{
    int b = blockIdx.x, dtile = blockIdx.y, seg = blockIdx.z;
    int d0 = dtile * 64;
    int lb = seg * (L / NSEG);
    __shared__ float xs[64][17], as[64][17];
    int tid = threadIdx.x, tx = tid & 15, ty = tid >> 4;
    float acc[4][4];
#pragma unroll
    for (int i = 0; i < 4; ++i)
#pragma unroll
        for (int j = 0; j < 4; ++j) acc[i][j] = 0.f;

    const float* xp = xn + (b * DIM + d0) * L + lb;
    const float* ap = AB + (b * 64) * L + lb;

    for (int k0 = 0; k0 < L / NSEG; k0 += 16) {
        __syncthreads();
#pragma unroll
        for (int e = tid; e < 1024; e += 256) {
            int r = e >> 4, c = e & 15;
            xs[r][c] = xp[r * L + k0 + c];
            as[r][c] = ap[r * L + k0 + c];
        }
        __syncthreads();
#pragma unroll
        for (int k = 0; k < 16; ++k) {
            float xa[4], bb[4];
#pragma unroll
            for (int i = 0; i < 4; ++i) xa[i] = xs[ty * 4 + i][k];
#pragma unroll
            for (int j = 0; j < 4; ++j) bb[j] = as[tx * 4 + j][k];
#pragma unroll
            for (int i = 0; i < 4; ++i)
#pragma unroll
                for (int j = 0; j < 4; ++j) acc[i][j] += xa[i] * bb[j];
        }
    }
    float* hp = hpart + seg * (BATCH * DIM * STATE);
#pragma unroll
    for (int i = 0; i < 4; ++i)
#pragma unroll
        for (int j = 0; j < 4; ++j)
            hp[(b * DIM + d0 + ty * 4 + i) * STATE + tx * 4 + j] = acc[i][j];
}

__global__ __launch_bounds__(256) void hreduce_kernel(
    const float* __restrict__ hpart, float* __restrict__ h)
{
    int idx = blockIdx.x * 256 + threadIdx.x;
    float s = 0.f;
#pragma unroll
    for (int g = 0; g < NSEG; ++g) s += hpart[g * (BATCH * DIM * STATE) + idx];
    h[idx] = s;
}

__global__ __launch_bounds__(256) void gate_kernel(
    const float* __restrict__ hz, float* __restrict__ hg)
{
    int idx = blockIdx.x * 256 + threadIdx.x;
    int s = idx & 63;
    int c = (idx >> 6) & 255;
    int b = idx >> 14;
    float hp = hz[(b * 512 + c) * 64 + s];
    float z = hz[(b * 512 + 256 + c) * 64 + s];
    hg[idx] = hp * z * sigm(z);
}

// ---------------- y = ho @ Cm ; x2 ----------------
__global__ __launch_bounds__(256) void y_fuse_kernel(
    const float* __restrict__ ho, const float* __restrict__ bcdt2,
    const float* __restrict__ xn, const float* __restrict__ x1,
    const float* __restrict__ Dp, const float* __restrict__ alpha1,
    float* __restrict__ x2)
{
    __shared__ float hos[16][257];
    int tid = threadIdx.x;
    int px = tid & 63, dg = tid >> 6;
    int Pg = blockIdx.x * 64;
    int b = Pg >> 12, l0 = Pg & 4095;
    const float* hob = ho + b * DIM * STATE;
    const float* cm = bcdt2 + (b * 192 + 64) * L + l0 + px;

    float acc[64];
#pragma unroll
    for (int j = 0; j < 64; ++j) acc[j] = 0.f;

    for (int sc = 0; sc < 4; ++sc) {
        __syncthreads();
#pragma unroll
        for (int e = tid; e < 4096; e += 256) {
            int d = e >> 4, s = e & 15;
            hos[s][d] = hob[d * 64 + sc * 16 + s];
        }
        __syncthreads();
#pragma unroll
        for (int s = 0; s < 16; ++s) {
            float cmv = cm[(sc * 16 + s) * L];
#pragma unroll
            for (int j = 0; j < 64; ++j)
                acc[j] += hos[s][dg * 64 + j] * cmv;
        }
    }
#pragma unroll
    for (int j = 0; j < 64; ++j) {
        int d = dg * 64 + j;
        int idx = (b * DIM + d) * L + l0 + px;
        float y = acc[j] + xn[idx] * Dp[d];
        float a = sigm(alpha1[d]);
        float p = x1[idx];
        x2[idx] = fmaf(a, y - p, p);
    }
}

__global__ __launch_bounds__(256) void copy_kernel(
    const float* __restrict__ src, float* __restrict__ dst)
{
    int idx = blockIdx.x * 256 + threadIdx.x;
    dst[idx] = src[idx];
}

// ---------------- host launcher ----------------
extern "C" void kernel_launch(void* const* d_in, const int* in_sizes, int n_in,
                              void* d_out, int out_size)
{
    const float* x        = (const float*)d_in[0];
    const float* alpha    = (const float*)d_in[1];
    const float* ln_w     = (const float*)d_in[2];
    const float* ln_b     = (const float*)d_in[3];
    const float* dw1_w    = (const float*)d_in[4];
    const float* dw1_ln_w = (const float*)d_in[5];
    const float* dw1_ln_b = (const float*)d_in[6];
    const float* dw2_w    = (const float*)d_in[7];
    const float* dw2_ln_w = (const float*)d_in[8];
    const float* dw2_ln_b = (const float*)d_in[9];
    const float* bcdt_w   = (const float*)d_in[10];
    const float* bcdt_b   = (const float*)d_in[11];
    const float* dwm_w    = (const float*)d_in[12];
    const float* dwm_b    = (const float*)d_in[13];
    const float* hz_w     = (const float*)d_in[14];
    const float* hz_b     = (const float*)d_in[15];
    const float* outp_w   = (const float*)d_in[16];
    const float* outp_b   = (const float*)d_in[17];
    const float* Dp       = (const float*)d_in[19];
    const float* fc1_w    = (const float*)d_in[20];
    const float* fc1_ln_w = (const float*)d_in[21];
    const float* fc1_ln_b = (const float*)d_in[22];
    const float* fc2_w    = (const float*)d_in[23];
    const float* fc2_ln_w = (const float*)d_in[24];
    const float* fc2_ln_b = (const float*)d_in[25];
    float* out = (float*)d_out;

    float *t0, *x1, *xn, *x2, *x3, *bc, *bc2, *ab, *hpart, *h, *hz, *hg, *ho, *f1t;
    __nv_bfloat16 *x3th, *x3tl, *xnth, *xntl, *f1th, *f1tl, *w1h, *w1l, *w2h, *w2l, *wbch, *wbcl;
    cudaGetSymbolAddress((void**)&t0, g_t0);
    cudaGetSymbolAddress((void**)&x1, g_x1);
    cudaGetSymbolAddress((void**)&xn, g_xn);
    cudaGetSymbolAddress((void**)&x2, g_x2);
    cudaGetSymbolAddress((void**)&x3, g_x3);
    cudaGetSymbolAddress((void**)&bc, g_bcdt);
    cudaGetSymbolAddress((void**)&bc2, g_bcdt2);
    cudaGetSymbolAddress((void**)&ab, g_AB);
    cudaGetSymbolAddress((void**)&hpart, g_hpart);
    cudaGetSymbolAddress((void**)&h, g_h);
    cudaGetSymbolAddress((void**)&hz, g_hz);
    cudaGetSymbolAddress((void**)&hg, g_hg);
    cudaGetSymbolAddress((void**)&ho, g_ho);
    cudaGetSymbolAddress((void**)&f1t, g_f1t);
    cudaGetSymbolAddress((void**)&x3th, g_x3th);
    cudaGetSymbolAddress((void**)&x3tl, g_x3tl);
    cudaGetSymbolAddress((void**)&xnth, g_xnth);
    cudaGetSymbolAddress((void**)&xntl, g_xntl);
    cudaGetSymbolAddress((void**)&f1th, g_f1th);
    cudaGetSymbolAddress((void**)&f1tl, g_f1tl);
    cudaGetSymbolAddress((void**)&w1h, g_w1h);
    cudaGetSymbolAddress((void**)&w1l, g_w1l);
    cudaGetSymbolAddress((void**)&w2h, g_w2h);
    cudaGetSymbolAddress((void**)&w2l, g_w2l);
    cudaGetSymbolAddress((void**)&wbch, g_wbch);
    cudaGetSymbolAddress((void**)&wbcl, g_wbcl);

    cudaFuncSetAttribute(gemm_mma_kernel<0>, cudaFuncAttributeMaxDynamicSharedMemorySize, GSMEM);
    cudaFuncSetAttribute(gemm_mma_kernel<1>, cudaFuncAttributeMaxDynamicSharedMemorySize, GSMEM);

    dim3 blk2(64, 4);

    // weight splits
    wsplit_kernel<<<HIDDEN * DIM / 256, 256>>>(fc1_w, w1h, w1l);
    wsplit_kernel<<<DIM * HIDDEN / 256, 256>>>(fc2_w, w2h, w2l);
    wsplit_pad_kernel<<<256 * DIM / 256, 256>>>(bcdt_w, wbch, wbcl);

    // sub-layer 1: dwconv + LN+gate (+2nd LN), then transpose+split xn
    dwconv8_kernel<<<BATCH * DIM * L / 8 / 256, 256>>>(x, dw1_w, nullptr, t0, DIM);
    ln_gate_kernel<true><<<NPIX / 256, blk2>>>(t0, x, dw1_ln_w, dw1_ln_b, alpha, x1,
                                               ln_w, ln_b, xn);
    convt_kernel<<<dim3(L / 32, DIM / 64, BATCH), 256>>>(xn, xnth, xntl, DIM);

    // HSMSSD mixer
    gemm_mma_kernel<0><<<dim3(NPIX / 256, 2), 256, GSMEM>>>(wbch, wbcl, xnth, xntl, bc, bcdt_b, 192, 256);
    dwconv8_kernel<<<BATCH * 192 * L / 8 / 256, 256>>>(bc, dwm_w, dwm_b, bc2, 192);
    softmax_ab_kernel<<<BATCH * 64, 256>>>(bc2, ab);
    hgemm_kernel<<<dim3(BATCH, 4, NSEG), 256>>>(xn, ab, hpart);
    hreduce_kernel<<<BATCH * DIM * STATE / 256, 256>>>(hpart, h);
    gemm1x1_kernel<128><<<dim3(BATCH, 4), 256>>>(hz_w, hz_b, h, hz, 512, 256, 64);
    gate_kernel<<<BATCH * DIM * STATE / 256, 256>>>(hz, hg);
    gemm1x1_kernel<128><<<dim3(BATCH, 2), 256>>>(outp_w, outp_b, hg, ho, 256, 256, 64);
    y_fuse_kernel<<<PIXBLK, 256>>>(ho, bc2, xn, x1, Dp, alpha + 256, x2);

    // sub-layer 3: dwconv + LN+gate, then transpose+split x3
    dwconv8_kernel<<<BATCH * DIM * L / 8 / 256, 256>>>(x2, dw2_w, nullptr, t0, DIM);
    ln_gate_kernel<false><<<NPIX / 256, blk2>>>(t0, x2, dw2_ln_w, dw2_ln_b, alpha + 512, x3,
                                                nullptr, nullptr, nullptr);
    convt_kernel<<<dim3(L / 32, DIM / 64, BATCH), 256>>>(x3, x3th, x3tl, DIM);

    // FFN: fc1 (transposed out) -> fused LN+SiLU+split -> fc2 -> final LN+gate
    gemm_mma_kernel<1><<<dim3(NPIX / 256, HIDDEN / 128), 256, GSMEM>>>(w1h, w1l, x3th, x3tl, f1t, nullptr, HIDDEN, 256);
    ln_silu_split_kernel<<<NPIX / 8, 256>>>(f1t, f1th, f1tl, fc1_ln_w, fc1_ln_b);
    gemm_mma_kernel<0><<<dim3(NPIX / 256, 2), 256, GSMEM>>>(w2h, w2l, f1th, f1tl, t0, nullptr, 256, 1024);
    ln_gate_kernel<false><<<NPIX / 256, blk2>>>(t0, x3, fc2_ln_w, fc2_ln_b, alpha + 768, out,
                                                nullptr, nullptr, nullptr);

    // second output: h
    if (out_size >= BATCH * DIM * L + BATCH * DIM * STATE)
        copy_kernel<<<BATCH * DIM * STATE / 256, 256>>>(h, out + BATCH * DIM * L);
}

// round 12
// speedup vs baseline: 1.6185x; 1.1024x over previous
#include <cuda_runtime.h>
#include <cuda_bf16.h>
#include <cstdint>
#include <math.h>

#define BATCH 16
#define DIM 256
#define STATE 64
#define HIDDEN 1024
#define L 4096
#define NPIX (BATCH*L)
#define PIXBLK (NPIX/64)
#define NSEG 8

// ---------------- scratch ----------------
__device__ float g_t0[BATCH*DIM*L];
__device__ float g_x1[BATCH*DIM*L];
__device__ float g_xn[BATCH*DIM*L];
__device__ float g_x2[BATCH*DIM*L];
__device__ float g_x3[BATCH*DIM*L];
__device__ float g_bcdt[BATCH*192*L];
__device__ float g_bcdt2[BATCH*192*L];
__device__ float g_AB[BATCH*STATE*L];
__device__ float g_hpart[NSEG*BATCH*DIM*STATE];
__device__ float g_h[BATCH*DIM*STATE];
__device__ float g_hz[BATCH*2*DIM*STATE];
__device__ float g_hg[BATCH*DIM*STATE];
__device__ float g_ho[BATCH*DIM*STATE];
__device__ float g_f1t[(size_t)BATCH*L*HIDDEN];
__device__ __nv_bfloat16 g_x3th[BATCH*L*DIM];
__device__ __nv_bfloat16 g_x3tl[BATCH*L*DIM];
__device__ __nv_bfloat16 g_xnth[BATCH*L*DIM];
__device__ __nv_bfloat16 g_xntl[BATCH*L*DIM];
__device__ __nv_bfloat16 g_f1th[(size_t)BATCH*L*HIDDEN];
__device__ __nv_bfloat16 g_f1tl[(size_t)BATCH*L*HIDDEN];
__device__ __nv_bfloat16 g_w1h[HIDDEN*DIM];
__device__ __nv_bfloat16 g_w1l[HIDDEN*DIM];
__device__ __nv_bfloat16 g_w2h[DIM*HIDDEN];
__device__ __nv_bfloat16 g_w2l[DIM*HIDDEN];
__device__ __nv_bfloat16 g_wbch[256*DIM];
__device__ __nv_bfloat16 g_wbcl[256*DIM];

// ---------------- helpers ----------------
__device__ __forceinline__ float2 ffma2(float2 a, float2 b, float2 c) {
    float2 d;
    asm("{\n\t.reg .b64 ra, rb, rc, rd;\n\t"
        "mov.b64 ra, {%2, %3};\n\tmov.b64 rb, {%4, %5};\n\tmov.b64 rc, {%6, %7};\n\t"
        "fma.rn.f32x2 rd, ra, rb, rc;\n\tmov.b64 {%0, %1}, rd;\n\t}"
        : "=f"(d.x), "=f"(d.y)
        : "f"(a.x), "f"(a.y), "f"(b.x), "f"(b.y), "f"(c.x), "f"(c.y));
    return d;
}
__device__ __forceinline__ float sigm(float v) { return 1.f / (1.f + __expf(-v)); }
__device__ __forceinline__ float4 f4add(float4 a, float4 b) {
    return make_float4(a.x + b.x, a.y + b.y, a.z + b.z, a.w + b.w);
}

#define CPA16(dst, src) asm volatile("cp.async.cg.shared.global [%0], [%1], 16;" :: "r"(dst), "l"(src))
#define SWZ(o) ((o) ^ (((o) >> 3) & 0x70u))

__device__ __forceinline__ uint32_t s2u(const void* p) {
    uint32_t a;
    asm("{ .reg .u64 t; cvta.to.shared.u64 t, %1; cvt.u32.u64 %0, t; }" : "=r"(a) : "l"(p));
    return a;
}

#define LDSM4(r, a) \
    asm volatile("ldmatrix.sync.aligned.m8n8.x4.shared.b16 {%0,%1,%2,%3}, [%4];" \
        : "=r"((r)[0]), "=r"((r)[1]), "=r"((r)[2]), "=r"((r)[3]) : "r"(a))

#define MMA16816(d, a, b) \
    asm volatile("mma.sync.aligned.m16n8k16.row.col.f32.bf16.bf16.f32 " \
        "{%0,%1,%2,%3},{%4,%5,%6,%7},{%8,%9},{%0,%1,%2,%3};" \
        : "+f"((d)[0]), "+f"((d)[1]), "+f"((d)[2]), "+f"((d)[3]) \
        : "r"((a)[0]), "r"((a)[1]), "r"((a)[2]), "r"((a)[3]), "r"((b)[0]), "r"((b)[1]))

// ---------------- tensor-core GEMM (mma.sync bf16 hi/lo), tile M128 x N256 -------------------
#define GSMEM 196608
template<int TRANS>
__global__ __launch_bounds__(256) void gemm_mma_kernel(
    const __nv_bfloat16* __restrict__ Wh, const __nv_bfloat16* __restrict__ Wl,
    const __nv_bfloat16* __restrict__ Xh, const __nv_bfloat16* __restrict__ Xl,
    float* __restrict__ Y, const float* __restrict__ bias, int O, int C)
{
    extern __shared__ char dsm[];
    uint32_t sb = s2u(dsm);
    int tid = threadIdx.x, warp = tid >> 5, lane = tid & 31;
    int wm = warp >> 2, wn = warp & 3;
    int bb = blockIdx.x >> 4;
    int l0 = (blockIdx.x & 15) << 8;
    int m0 = blockIdx.y << 7;
    int nchunk = C >> 6;
    size_t rowb = (size_t)bb * 4096 + l0;

    float acc[4][8][4];
#pragma unroll
    for (int i = 0; i < 4; ++i)
#pragma unroll
        for (int j = 0; j < 8; ++j)
#pragma unroll
            for (int q = 0; q < 4; ++q) acc[i][j][q] = 0.f;

    auto issue = [&](int cc, int buf) {
        int c0 = cc << 6;
        uint32_t base = sb + (uint32_t)buf * 98304u;
#pragma unroll
        for (int i = 0; i < 4; ++i) {
            int e = tid + i * 256;
            int row = e >> 3, c16 = e & 7;
            uint32_t sw = SWZ((uint32_t)(row * 128 + c16 * 16));
            CPA16(base + sw,           Wh + (size_t)(m0 + row) * C + c0 + c16 * 8);
            CPA16(base + 16384u + sw,  Wl + (size_t)(m0 + row) * C + c0 + c16 * 8);
        }
#pragma unroll
        for (int i = 0; i < 8; ++i) {
            int e = tid + i * 256;
            int row = e >> 3, c16 = e & 7;
            uint32_t sw = SWZ((uint32_t)(row * 128 + c16 * 16));
            CPA16(base + 32768u + sw,  Xh + (rowb + row) * (size_t)C + c0 + c16 * 8);
            CPA16(base + 65536u + sw,  Xl + (rowb + row) * (size_t)C + c0 + c16 * 8);
        }
        asm volatile("cp.async.commit_group;");
    };

    issue(0, 0);
    for (int cc = 0; cc < nchunk; ++cc) {
        int buf = cc & 1;
        if (cc + 1 < nchunk) {
            issue(cc + 1, buf ^ 1);
            asm volatile("cp.async.wait_group 1;");
        } else {
            asm volatile("cp.async.wait_group 0;");
        }
        __syncthreads();
        uint32_t base = sb + (uint32_t)buf * 98304u;

        int lr = (lane & 7) + ((lane >> 3) & 1) * 8;
        int kb = (lane >> 4) * 8;
#pragma unroll
        for (int kt = 0; kt < 4; ++kt) {
            uint32_t ah[4][4], al[4][4];
#pragma unroll
            for (int mt = 0; mt < 4; ++mt) {
                int row = wm * 64 + mt * 16 + lr;
                uint32_t a = base + SWZ((uint32_t)(row * 128 + (kt * 16 + kb) * 2));
                LDSM4(ah[mt], a);
                LDSM4(al[mt], a + 16384u);
            }
            uint32_t bh[8][2], bl[8][2];
#pragma unroll
            for (int np = 0; np < 4; ++np) {
                int row = wn * 64 + np * 16 + lr;
                uint32_t a = base + 32768u + SWZ((uint32_t)(row * 128 + (kt * 16 + kb) * 2));
                uint32_t r[4], rl[4];
                LDSM4(r, a);
                LDSM4(rl, a + 32768u);
                bh[np * 2][0] = r[0]; bh[np * 2][1] = r[2];
                bh[np * 2 + 1][0] = r[1]; bh[np * 2 + 1][1] = r[3];
                bl[np * 2][0] = rl[0]; bl[np * 2][1] = rl[2];
                bl[np * 2 + 1][0] = rl[1]; bl[np * 2 + 1][1] = rl[3];
            }
#pragma unroll
            for (int mt = 0; mt < 4; ++mt)
#pragma unroll
                for (int nt = 0; nt < 8; ++nt) {
                    MMA16816(acc[mt][nt], ah[mt], bh[nt]);
                    MMA16816(acc[mt][nt], ah[mt], bl[nt]);
                    MMA16816(acc[mt][nt], al[mt], bh[nt]);
                }
        }
        __syncthreads();
    }

    int mrow = (lane >> 2);
    int ncol = (lane & 3) * 2;
    if (TRANS == 0) {
#pragma unroll
        for (int mt = 0; mt < 4; ++mt) {
            int o = m0 + wm * 64 + mt * 16 + mrow;
            float bv0 = (o < O && bias) ? bias[o] : 0.f;
            float bv1 = (o + 8 < O && bias) ? bias[o + 8] : 0.f;
            float* yp0 = Y + ((size_t)bb * O + o) * 4096 + l0 + wn * 64;
            float* yp1 = Y + ((size_t)bb * O + o + 8) * 4096 + l0 + wn * 64;
#pragma unroll
            for (int nt = 0; nt < 8; ++nt) {
                if (o < O)
                    *(float2*)(yp0 + nt * 8 + ncol) = make_float2(acc[mt][nt][0] + bv0, acc[mt][nt][1] + bv0);
                if (o + 8 < O)
                    *(float2*)(yp1 + nt * 8 + ncol) = make_float2(acc[mt][nt][2] + bv1, acc[mt][nt][3] + bv1);
            }
        }
    } else {
        float* st = (float*)dsm;
#pragma unroll
        for (int mt = 0; mt < 4; ++mt) {
            int ob = wm * 64 + mt * 16 + mrow;
#pragma unroll
            for (int nt = 0; nt < 8; ++nt) {
                int pxb = wn * 64 + nt * 8 + ncol;
                st[(size_t)pxb * 132 + ob] = acc[mt][nt][0];
                st[(size_t)(pxb + 1) * 132 + ob] = acc[mt][nt][1];
                st[(size_t)pxb * 132 + ob + 8] = acc[mt][nt][2];
                st[(size_t)(pxb + 1) * 132 + ob + 8] = acc[mt][nt][3];
            }
        }
        __syncthreads();
        int px = tid;
        float* dst = Y + (rowb + px) * (size_t)O + m0;
        const float* src = st + (size_t)px * 132;
#pragma unroll
        for (int j = 0; j < 32; ++j)
            *(float4*)(dst + j * 4) = *(const float4*)(src + j * 4);
    }
}

// ---------------- transpose + bf16 hi/lo split ----------------
__global__ __launch_bounds__(256) void convt_kernel(
    const float* __restrict__ in, __nv_bfloat16* __restrict__ oh,
    __nv_bfloat16* __restrict__ ol, int C)
{
    __shared__ float s[64][33];
    int tid = threadIdx.x;
    int lx = tid & 31, cy = tid >> 5;
    int l0 = blockIdx.x * 32;
    int c0 = blockIdx.y * 64;
    int b = blockIdx.z;
    const float* ip = in + ((size_t)b * C + c0) * L + l0;
#pragma unroll
    for (int i = 0; i < 8; ++i)
        s[cy + i * 8][lx] = ip[(size_t)(cy + i * 8) * L + lx];
    __syncthreads();
    int cp = tid & 31, ly = tid >> 5;
#pragma unroll
    for (int i = 0; i < 4; ++i) {
        int lrow = ly + i * 8;
        float f0 = s[2 * cp][lrow], f1 = s[2 * cp + 1][lrow];
        __nv_bfloat16 h0 = __float2bfloat16(f0);
        __nv_bfloat16 h1 = __float2bfloat16(f1);
        __nv_bfloat16 e0 = __float2bfloat16(f0 - __bfloat162float(h0));
        __nv_bfloat16 e1 = __float2bfloat16(f1 - __bfloat162float(h1));
        uint32_t hp = (uint32_t)__bfloat16_as_ushort(h0) | ((uint32_t)__bfloat16_as_ushort(h1) << 16);
        uint32_t lp = (uint32_t)__bfloat16_as_ushort(e0) | ((uint32_t)__bfloat16_as_ushort(e1) << 16);
        size_t o32 = (((size_t)b * L + l0 + lrow) * C + c0) / 2 + cp;
        ((uint32_t*)oh)[o32] = hp;
        ((uint32_t*)ol)[o32] = lp;
    }
}

// ---------------- fused LN(1024) + SiLU + bf16 hi/lo split ----------------
__global__ __launch_bounds__(256) void ln_silu_split_kernel(
    const float* __restrict__ f1t, __nv_bfloat16* __restrict__ oh, __nv_bfloat16* __restrict__ ol,
    const float* __restrict__ lnw, const float* __restrict__ lnb)
{
    int warp = threadIdx.x >> 5, lane = threadIdx.x & 31;
    size_t px = (size_t)blockIdx.x * 8 + warp;
    const float4* row = (const float4*)(f1t + px * 1024);
    const float4* w4 = (const float4*)lnw;
    const float4* b4 = (const float4*)lnb;

    float4 v[8];
    float s1 = 0.f, s2 = 0.f;
#pragma unroll
    for (int i = 0; i < 8; ++i) {
        v[i] = row[lane + i * 32];
        s1 += v[i].x + v[i].y + v[i].z + v[i].w;
        s2 += v[i].x * v[i].x + v[i].y * v[i].y + v[i].z * v[i].z + v[i].w * v[i].w;
    }
#pragma unroll
    for (int st = 16; st; st >>= 1) {
        s1 += __shfl_xor_sync(0xFFFFFFFF, s1, st);
        s2 += __shfl_xor_sync(0xFFFFFFFF, s2, st);
    }
    float u = s1 * (1.f / 1024.f);
    float rs = rsqrtf(s2 * (1.f / 1024.f) - u * u + 1e-5f);

    uint2* oh2 = (uint2*)(oh + px * 1024);
    uint2* ol2 = (uint2*)(ol + px * 1024);
#pragma unroll
    for (int i = 0; i < 8; ++i) {
        int c4 = lane + i * 32;
        float4 wv = w4[c4], bv = b4[c4];
        float g[4];
        g[0] = wv.x * (v[i].x - u) * rs + bv.x;
        g[1] = wv.y * (v[i].y - u) * rs + bv.y;
        g[2] = wv.z * (v[i].z - u) * rs + bv.z;
        g[3] = wv.w * (v[i].w - u) * rs + bv.w;
#pragma unroll
        for (int j = 0; j < 4; ++j) g[j] = g[j] * sigm(g[j]);
        __nv_bfloat16 h0 = __float2bfloat16(g[0]), h1 = __float2bfloat16(g[1]);
        __nv_bfloat16 h2 = __float2bfloat16(g[2]), h3 = __float2bfloat16(g[3]);
        uint2 hp, lp;
        hp.x = (uint32_t)__bfloat16_as_ushort(h0) | ((uint32_t)__bfloat16_as_ushort(h1) << 16);
        hp.y = (uint32_t)__bfloat16_as_ushort(h2) | ((uint32_t)__bfloat16_as_ushort(h3) << 16);
        __nv_bfloat16 e0 = __float2bfloat16(g[0] - __bfloat162float(h0));
        __nv_bfloat16 e1 = __float2bfloat16(g[1] - __bfloat162float(h1));
        __nv_bfloat16 e2 = __float2bfloat16(g[2] - __bfloat162float(h2));
        __nv_bfloat16 e3 = __float2bfloat16(g[3] - __bfloat162float(h3));
        lp.x = (uint32_t)__bfloat16_as_ushort(e0) | ((uint32_t)__bfloat16_as_ushort(e1) << 16);
        lp.y = (uint32_t)__bfloat16_as_ushort(e2) | ((uint32_t)__bfloat16_as_ushort(e3) << 16);
        oh2[c4] = hp;
        ol2[c4] = lp;
    }
}

__global__ __launch_bounds__(256) void wsplit_kernel(
    const float* __restrict__ w, __nv_bfloat16* __restrict__ wh, __nv_bfloat16* __restrict__ wl)
{
    int i = blockIdx.x * 256 + threadIdx.x;
    float f = w[i];
    __nv_bfloat16 h = __float2bfloat16(f);
    wh[i] = h;
    wl[i] = __float2bfloat16(f - __bfloat162float(h));
}

__global__ __launch_bounds__(256) void wsplit_pad_kernel(
    const float* __restrict__ w, __nv_bfloat16* __restrict__ wh, __nv_bfloat16* __restrict__ wl)
{
    int i = blockIdx.x * 256 + threadIdx.x;
    int row = i >> 8;
    float f = (row < 192) ? w[i] : 0.f;
    __nv_bfloat16 h = __float2bfloat16(f);
    wh[i] = h;
    wl[i] = __float2bfloat16(f - __bfloat162float(h));
}

// ---------------- depthwise 3x3 conv ----------------
__global__ __launch_bounds__(256) void dwconv8_kernel(
    const float* __restrict__ in, const float* __restrict__ w,
    const float* __restrict__ bias, float* __restrict__ out, int C)
{
    int t = blockIdx.x * 256 + threadIdx.x;
    int x0 = (t & 7) * 8;
    int r = t >> 3;
    int hh = r & 63;
    int bc = r >> 6;
    int c = bc - (bc / C) * C;
    const float* wp = w + c * 9;
    float wr[9];
#pragma unroll
    for (int i = 0; i < 9; ++i) wr[i] = wp[i];
    const float* ip = in + (long)bc * 4096;
    float bv = bias ? bias[c] : 0.f;
    float acc[8];
#pragma unroll
    for (int j = 0; j < 8; ++j) acc[j] = bv;
#pragma unroll
    for (int ky = 0; ky < 3; ++ky) {
        int y = hh + ky - 1;
        if ((unsigned)y < 64u) {
            const float* rp = ip + y * 64 + x0;
            float4 a = *(const float4*)rp;
            float4 b4 = *(const float4*)(rp + 4);
            float v[10];
            v[0] = (x0 > 0) ? rp[-1] : 0.f;
            v[1] = a.x; v[2] = a.y; v[3] = a.z; v[4] = a.w;
            v[5] = b4.x; v[6] = b4.y; v[7] = b4.z; v[8] = b4.w;
            v[9] = (x0 < 56) ? rp[8] : 0.f;
            float k0 = wr[ky * 3 + 0], k1 = wr[ky * 3 + 1], k2 = wr[ky * 3 + 2];
#pragma unroll
            for (int j = 0; j < 8; ++j)
                acc[j] += k0 * v[j] + k1 * v[j + 1] + k2 * v[j + 2];
        }
    }
    float* op = out + (long)bc * 4096 + hh * 64 + x0;
    *(float4*)op = make_float4(acc[0], acc[1], acc[2], acc[3]);
    *(float4*)(op + 4) = make_float4(acc[4], acc[5], acc[6], acc[7]);
}

// ---------------- fused channel-LN + gated residual (+optional 2nd LN), float4 over px -------
template<bool HAS2>
__global__ __launch_bounds__(256) void ln_gate_kernel(
    const float* __restrict__ t, const float* __restrict__ prev,
    const float* __restrict__ lnw, const float* __restrict__ lnb,
    const float* __restrict__ alpha_row, float* __restrict__ out,
    const float* __restrict__ lnw2, const float* __restrict__ lnb2,
    float* __restrict__ out2)
{
    __shared__ float4 r1[4][64], r2[4][64];
    int qx = threadIdx.x, cg = threadIdx.y;
    int Pg = blockIdx.x * 256;
    int b = Pg >> 12, l0 = Pg & 4095;
    size_t base = ((size_t)(b * DIM) * L + l0 + qx * 4) >> 2;

    const float4* t4 = (const float4*)t;
    const float4* p4 = (const float4*)prev;
    float4* o4 = (float4*)out;
    float4* o24 = (float4*)out2;
    const size_t L4 = L / 4;

    float4 s1 = make_float4(0.f, 0.f, 0.f, 0.f), s2 = s1;
#pragma unroll 8
    for (int c = 0; c < 64; ++c) {
        float4 v = t4[base + (size_t)(cg * 64 + c) * L4];
        s1 = f4add(s1, v);
        s2 = f4add(s2, make_float4(v.x * v.x, v.y * v.y, v.z * v.z, v.w * v.w));
    }
    r1[cg][qx] = s1; r2[cg][qx] = s2;
    __syncthreads();
    float4 ts1 = f4add(f4add(r1[0][qx], r1[1][qx]), f4add(r1[2][qx], r1[3][qx]));
    float4 ts2 = f4add(f4add(r2[0][qx], r2[1][qx]), f4add(r2[2][qx], r2[3][qx]));
    float4 u = make_float4(ts1.x * (1.f / 256.f), ts1.y * (1.f / 256.f),
                           ts1.z * (1.f / 256.f), ts1.w * (1.f / 256.f));
    float4 rs = make_float4(
        rsqrtf(ts2.x * (1.f / 256.f) - u.x * u.x + 1e-5f),
        rsqrtf(ts2.y * (1.f / 256.f) - u.y * u.y + 1e-5f),
        rsqrtf(ts2.z * (1.f / 256.f) - u.z * u.z + 1e-5f),
        rsqrtf(ts2.w * (1.f / 256.f) - u.w * u.w + 1e-5f));

    float4 b1 = make_float4(0.f, 0.f, 0.f, 0.f), b2 = b1;
#pragma unroll 8
    for (int c = 0; c < 64; ++c) {
        int ch = cg * 64 + c;
        size_t idx = base + (size_t)ch * L4;
        float4 v = t4[idx];
        float4 p = p4[idx];
        float w = lnw[ch], bb = lnb[ch];
        float a = sigm(alpha_row[ch]);
        float4 xv;
        xv.x = fmaf(a, fmaf(w, (v.x - u.x) * rs.x, bb) - p.x, p.x);
        xv.y = fmaf(a, fmaf(w, (v.y - u.y) * rs.y, bb) - p.y, p.y);
        xv.z = fmaf(a, fmaf(w, (v.z - u.z) * rs.z, bb) - p.z, p.z);
        xv.w = fmaf(a, fmaf(w, (v.w - u.w) * rs.w, bb) - p.w, p.w);
        o4[idx] = xv;
        if (HAS2) {
            b1 = f4add(b1, xv);
            b2 = f4add(b2, make_float4(xv.x * xv.x, xv.y * xv.y, xv.z * xv.z, xv.w * xv.w));
        }
    }
    if (HAS2) {
        __syncthreads();
        r1[cg][qx] = b1; r2[cg][qx] = b2;
        __syncthreads();
        float4 q1 = f4add(f4add(r1[0][qx], r1[1][qx]), f4add(r1[2][qx], r1[3][qx]));
        float4 q2 = f4add(f4add(r2[0][qx], r2[1][qx]), f4add(r2[2][qx], r2[3][qx]));
        float4 u1 = make_float4(q1.x * (1.f / 256.f), q1.y * (1.f / 256.f),
                                q1.z * (1.f / 256.f), q1.w * (1.f / 256.f));
        float4 rs2 = make_float4(
            rsqrtf(q2.x * (1.f / 256.f) - u1.x * u1.x + 1e-5f),
            rsqrtf(q2.y * (1.f / 256.f) - u1.y * u1.y + 1e-5f),
            rsqrtf(q2.z * (1.f / 256.f) - u1.z * u1.z + 1e-5f),
            rsqrtf(q2.w * (1.f / 256.f) - u1.w * u1.w + 1e-5f));
#pragma unroll 8
        for (int c = 0; c < 64; ++c) {
            int ch = cg * 64 + c;
            size_t idx = base + (size_t)ch * L4;
            float4 xv = o4[idx];
            float w = lnw2[ch], bb = lnb2[ch];
            float4 nv;
            nv.x = fmaf(w, (xv.x - u1.x) * rs2.x, bb);
            nv.y = fmaf(w, (xv.y - u1.y) * rs2.y, bb);
            nv.z = fmaf(w, (xv.z - u1.z) * rs2.z, bb);
            nv.w = fmaf(w, (xv.w - u1.w) * rs2.w, bb);
            o24[idx] = nv;
        }
    }
}

// ---------------- small GEMM for Ld=64 ----------------
template<int OT>
__global__ __launch_bounds__(256) void gemm1x1_kernel(
    const float* __restrict__ W, const float* __restrict__ bias,
    const float* __restrict__ X, float* __restrict__ Y,
    int O, int C, int Ld)
{
    constexpr int PT = OT / 8;
    constexpr int KC = 32;
    __shared__ float Ws[OT * KC];
    int tid = threadIdx.x;
    int pxl = tid & 31;
    int og = tid >> 5;
    int b = (blockIdx.x * 64) / Ld;
    int l0 = (blockIdx.x * 64) % Ld;
    int ob = blockIdx.y * OT;
    const float* Xb = X + (b * C) * Ld + l0 + pxl * 2;

    float2 acc[PT];
#pragma unroll
    for (int i = 0; i < PT; ++i) acc[i] = make_float2(0.f, 0.f);

    for (int c0 = 0; c0 < C; c0 += KC) {
        __syncthreads();
#pragma unroll
        for (int e = tid; e < OT * KC; e += 256) {
            int ol = e >> 5, k = e & 31;
            Ws[e] = W[(ob + ol) * C + c0 + k];
        }
        __syncthreads();
#pragma unroll 4
        for (int k = 0; k < KC; ++k) {
            float2 xv = *reinterpret_cast<const float2*>(Xb + (c0 + k) * Ld);
#pragma unroll
            for (int i = 0; i < PT; ++i) {
                float wv = Ws[(og * PT + i) * KC + k];
                acc[i] = ffma2(make_float2(wv, wv), xv, acc[i]);
            }
        }
    }
#pragma unroll
    for (int i = 0; i < PT; ++i) {
        int o = ob + og * PT + i;
        float bv = bias ? bias[o] : 0.f;
        float2 r = make_float2(acc[i].x + bv, acc[i].y + bv);
        *reinterpret_cast<float2*>(Y + (b * O + o) * Ld + l0 + pxl * 2) = r;
    }
}

// ---------------- softmax over L, AB = softmax(dt)*Bm ----------------
__global__ __launch_bounds__(256) void softmax_ab_kernel(
    const float* __restrict__ bcdt2, float* __restrict__ AB)
{
    int bs = blockIdx.x;
    int b = bs >> 6, s = bs & 63;
    const float* dt = bcdt2 + (b * 192 + 128 + s) * L;
    const float* Bm = bcdt2 + (b * 192 + s) * L;
    float* out = AB + (b * 64 + s) * L;
    __shared__ float e[L];
    __shared__ float red[256];
    int tid = threadIdx.x;

    float m = -1e30f;
    for (int l = tid; l < L; l += 256) { float v = dt[l]; e[l] = v; m = fmaxf(m, v); }
    red[tid] = m; __syncthreads();
    for (int st = 128; st; st >>= 1) { if (tid < st) red[tid] = fmaxf(red[tid], red[tid + st]); __syncthreads(); }
    m = red[0];
    __syncthreads();

    float sm = 0.f;
    for (int l = tid; l < L; l += 256) { float ev = __expf(e[l] - m); e[l] = ev; sm += ev; }
    red[tid] = sm; __syncthreads();
    for (int st = 128; st; st >>= 1) { if (tid < st) red[tid] += red[tid + st]; __syncthreads(); }
    float inv = 1.f / red[0];

    for (int l = tid; l < L; l += 256) out[l] = e[l] * inv * Bm[l];
}

// ---------------- h partials: k-major smem tiles, ffma2 inner ----------------
__global__ __launch_bounds__(256) void hgemm_kernel(
    const float* __restrict__ xn, const float* __restrict__ AB, float* __restrict__ hpart)
{
    int b = blockIdx.x, dtile = blockIdx.y, seg = blockIdx.z;
    int d0 = dtile * 64;
    int lb = seg * (L / NSEG);
    __shared__ float xs[16][66], as[16][66];   // [k][row], pad 66 (float2-aligned)
    int tid = threadIdx.x, tx = tid & 15, ty = tid >> 4;
    float2 acc[4][2];
#pragma unroll
    for (int i = 0; i < 4; ++i) {
        acc[i][0] = make_float2(0.f, 0.f);
        acc[i][1] = make_float2(0.f, 0.f);
    }

    const float* xp = xn + (b * DIM + d0) * L + lb;
    const float* ap = AB + (b * 64) * L + lb;

    for (int k0 = 0; k0 < L / NSEG; k0 += 16) {
        __syncthreads();
#pragma unroll
        for (int e = tid; e < 1024; e += 256) {
            int r = e >> 4, c = e & 15;
            xs[c][r] = xp[r * L + k0 + c];
            as[c][r] = ap[r * L + k0 + c];
        }
        __syncthreads();
#pragma unroll
        for (int k = 0; k < 16; ++k) {
            float2 bb0 = *(const float2*)&as[k][tx * 4];
            float2 bb1 = *(const float2*)&as[k][tx * 4 + 2];
#pragma unroll
            for (int i = 0; i < 4; ++i) {
                float xa = xs[k][ty * 4 + i];
                float2 xa2 = make_float2(xa, xa);
                acc[i][0] = ffma2(xa2, bb0, acc[i][0]);
                acc[i][1] = ffma2(xa2, bb1, acc[i][1]);
            }
        }
    }
    float* hp = hpart + seg * (BATCH * DIM * STATE);
#pragma unroll
    for (int i = 0; i < 4; ++i) {
        float* row = hp + (b * DIM + d0 + ty * 4 + i) * STATE + tx * 4;
        *(float2*)row = acc[i][0];
        *(float2*)(row + 2) = acc[i][1];
    }
}

__global__ __launch_bounds__(256) void hreduce_kernel(
    const float* __restrict__ hpart, float* __restrict__ h)
{
    int idx = blockIdx.x * 256 + threadIdx.x;
    float s = 0.f;
#pragma unroll
    for (int g = 0; g < NSEG; ++g) s += hpart[g * (BATCH * DIM * STATE) + idx];
    h[idx] = s;
}

__global__ __launch_bounds__(256) void gate_kernel(
    const float* __restrict__ hz, float* __restrict__ hg)
{
    int idx = blockIdx.x * 256 + threadIdx.x;
    int s = idx & 63;
    int c = (idx >> 6) & 255;
    int b = idx >> 14;
    float hp = hz[(b * 512 + c) * 64 + s];
    float z = hz[(b * 512 + 256 + c) * 64 + s];
    hg[idx] = hp * z * sigm(z);
}

// ---------------- y = ho @ Cm ; x2  (ffma2 over px pairs) ----------------
__global__ __launch_bounds__(256) void y_fuse_kernel(
    const float* __restrict__ ho, const float* __restrict__ bcdt2,
    const float* __restrict__ xn, const float* __restrict__ x1,
    const float* __restrict__ Dp, const float* __restrict__ alpha1,
    float* __restrict__ x2)
{
    __shared__ float hos[16][257];
    int tid = threadIdx.x;
    int pxp = tid & 31, dg = tid >> 5;     // 32 px-pairs x 8 d-groups (32 d each)
    int Pg = blockIdx.x * 64;
    int b = Pg >> 12, l0 = Pg & 4095;
    const float* hob = ho + b * DIM * STATE;
    const float* cm = bcdt2 + (b * 192 + 64) * L + l0 + pxp * 2;

    float2 acc[32];
#pragma unroll
    for (int j = 0; j < 32; ++j) acc[j] = make_float2(0.f, 0.f);

    for (int sc = 0; sc < 4; ++sc) {
        __syncthreads();
#pragma unroll
        for (int e = tid; e < 4096; e += 256) {
            int d = e >> 4, s = e & 15;
            hos[s][d] = hob[d * 64 + sc * 16 + s];
        }
        __syncthreads();
#pragma unroll
        for (int s = 0; s < 16; ++s) {
            float2 cmv = *(const float2*)(cm + (size_t)(sc * 16 + s) * L);
#pragma unroll
            for (int j = 0; j < 32; ++j) {
                float w = hos[s][dg * 32 + j];
                acc[j] = ffma2(make_float2(w, w), cmv, acc[j]);
            }
        }
    }
#pragma unroll
    for (int j = 0; j < 32; ++j) {
        int d = dg * 32 + j;
        size_t idx = (size_t)(b * DIM + d) * L + l0 + pxp * 2;
        float2 xnv = *(const float2*)(xn + idx);
        float2 p = *(const float2*)(x1 + idx);
        float dp = Dp[d];
        float a = sigm(alpha1[d]);
        float2 r;
        r.x = fmaf(a, (acc[j].x + xnv.x * dp) - p.x, p.x);
        r.y = fmaf(a, (acc[j].y + xnv.y * dp) - p.y, p.y);
        *(float2*)(x2 + idx) = r;
    }
}

__global__ __launch_bounds__(256) void copy_kernel(
    const float* __restrict__ src, float* __restrict__ dst)
{
    int idx = blockIdx.x * 256 + threadIdx.x;
    dst[idx] = src[idx];
}

// ---------------- host launcher ----------------
extern "C" void kernel_launch(void* const* d_in, const int* in_sizes, int n_in,
                              void* d_out, int out_size)
{
    const float* x        = (const float*)d_in[0];
    const float* alpha    = (const float*)d_in[1];
    const float* ln_w     = (const float*)d_in[2];
    const float* ln_b     = (const float*)d_in[3];
    const float* dw1_w    = (const float*)d_in[4];
    const float* dw1_ln_w = (const float*)d_in[5];
    const float* dw1_ln_b = (const float*)d_in[6];
    const float* dw2_w    = (const float*)d_in[7];
    const float* dw2_ln_w = (const float*)d_in[8];
    const float* dw2_ln_b = (const float*)d_in[9];
    const float* bcdt_w   = (const float*)d_in[10];
    const float* bcdt_b   = (const float*)d_in[11];
    const float* dwm_w    = (const float*)d_in[12];
    const float* dwm_b    = (const float*)d_in[13];
    const float* hz_w     = (const float*)d_in[14];
    const float* hz_b     = (const float*)d_in[15];
    const float* outp_w   = (const float*)d_in[16];
    const float* outp_b   = (const float*)d_in[17];
    const float* Dp       = (const float*)d_in[19];
    const float* fc1_w    = (const float*)d_in[20];
    const float* fc1_ln_w = (const float*)d_in[21];
    const float* fc1_ln_b = (const float*)d_in[22];
    const float* fc2_w    = (const float*)d_in[23];
    const float* fc2_ln_w = (const float*)d_in[24];
    const float* fc2_ln_b = (const float*)d_in[25];
    float* out = (float*)d_out;

    float *t0, *x1, *xn, *x2, *x3, *bc, *bc2, *ab, *hpart, *h, *hz, *hg, *ho, *f1t;
    __nv_bfloat16 *x3th, *x3tl, *xnth, *xntl, *f1th, *f1tl, *w1h, *w1l, *w2h, *w2l, *wbch, *wbcl;
    cudaGetSymbolAddress((void**)&t0, g_t0);
    cudaGetSymbolAddress((void**)&x1, g_x1);
    cudaGetSymbolAddress((void**)&xn, g_xn);
    cudaGetSymbolAddress((void**)&x2, g_x2);
    cudaGetSymbolAddress((void**)&x3, g_x3);
    cudaGetSymbolAddress((void**)&bc, g_bcdt);
    cudaGetSymbolAddress((void**)&bc2, g_bcdt2);
    cudaGetSymbolAddress((void**)&ab, g_AB);
    cudaGetSymbolAddress((void**)&hpart, g_hpart);
    cudaGetSymbolAddress((void**)&h, g_h);
    cudaGetSymbolAddress((void**)&hz, g_hz);
    cudaGetSymbolAddress((void**)&hg, g_hg);
    cudaGetSymbolAddress((void**)&ho, g_ho);
    cudaGetSymbolAddress((void**)&f1t, g_f1t);
    cudaGetSymbolAddress((void**)&x3th, g_x3th);
    cudaGetSymbolAddress((void**)&x3tl, g_x3tl);
    cudaGetSymbolAddress((void**)&xnth, g_xnth);
    cudaGetSymbolAddress((void**)&xntl, g_xntl);
    cudaGetSymbolAddress((void**)&f1th, g_f1th);
    cudaGetSymbolAddress((void**)&f1tl, g_f1tl);
    cudaGetSymbolAddress((void**)&w1h, g_w1h);
    cudaGetSymbolAddress((void**)&w1l, g_w1l);
    cudaGetSymbolAddress((void**)&w2h, g_w2h);
    cudaGetSymbolAddress((void**)&w2l, g_w2l);
    cudaGetSymbolAddress((void**)&wbch, g_wbch);
    cudaGetSymbolAddress((void**)&wbcl, g_wbcl);

    cudaFuncSetAttribute(gemm_mma_kernel<0>, cudaFuncAttributeMaxDynamicSharedMemorySize, GSMEM);
    cudaFuncSetAttribute(gemm_mma_kernel<1>, cudaFuncAttributeMaxDynamicSharedMemorySize, GSMEM);

    dim3 blk2(64, 4);

    // weight splits
    wsplit_kernel<<<HIDDEN * DIM / 256, 256>>>(fc1_w, w1h, w1l);
    wsplit_kernel<<<DIM * HIDDEN / 256, 256>>>(fc2_w, w2h, w2l);
    wsplit_pad_kernel<<<256 * DIM / 256, 256>>>(bcdt_w, wbch, wbcl);

    // sub-layer 1: dwconv + LN+gate (+2nd LN), then transpose+split xn
    dwconv8_kernel<<<BATCH * DIM * L / 8 / 256, 256>>>(x, dw1_w, nullptr, t0, DIM);
    ln_gate_kernel<true><<<NPIX / 256, blk2>>>(t0, x, dw1_ln_w, dw1_ln_b, alpha, x1,
                                               ln_w, ln_b, xn);
    convt_kernel<<<dim3(L / 32, DIM / 64, BATCH), 256>>>(xn, xnth, xntl, DIM);

    // HSMSSD mixer
    gemm_mma_kernel<0><<<dim3(NPIX / 256, 2), 256, GSMEM>>>(wbch, wbcl, xnth, xntl, bc, bcdt_b, 192, 256);
    dwconv8_kernel<<<BATCH * 192 * L / 8 / 256, 256>>>(bc, dwm_w, dwm_b, bc2, 192);
    softmax_ab_kernel<<<BATCH * 64, 256>>>(bc2, ab);
    hgemm_kernel<<<dim3(BATCH, 4, NSEG), 256>>>(xn, ab, hpart);
    hreduce_kernel<<<BATCH * DIM * STATE / 256, 256>>>(hpart, h);
    gemm1x1_kernel<128><<<dim3(BATCH, 4), 256>>>(hz_w, hz_b, h, hz, 512, 256, 64);
    gate_kernel<<<BATCH * DIM * STATE / 256, 256>>>(hz, hg);
    gemm1x1_kernel<128><<<dim3(BATCH, 2), 256>>>(outp_w, outp_b, hg, ho, 256, 256, 64);
    y_fuse_kernel<<<PIXBLK, 256>>>(ho, bc2, xn, x1, Dp, alpha + 256, x2);

    // sub-layer 3: dwconv + LN+gate, then transpose+split x3
    dwconv8_kernel<<<BATCH * DIM * L / 8 / 256, 256>>>(x2, dw2_w, nullptr, t0, DIM);
    ln_gate_kernel<false><<<NPIX / 256, blk2>>>(t0, x2, dw2_ln_w, dw2_ln_b, alpha + 512, x3,
                                                nullptr, nullptr, nullptr);
    convt_kernel<<<dim3(L / 32, DIM / 64, BATCH), 256>>>(x3, x3th, x3tl, DIM);

    // FFN
    gemm_mma_kernel<1><<<dim3(NPIX / 256, HIDDEN / 128), 256, GSMEM>>>(w1h, w1l, x3th, x3tl, f1t, nullptr, HIDDEN, 256);
    ln_silu_split_kernel<<<NPIX / 8, 256>>>(f1t, f1th, f1tl, fc1_ln_w, fc1_ln_b);
    gemm_mma_kernel<0><<<dim3(NPIX / 256, 2), 256, GSMEM>>>(w2h, w2l, f1th, f1tl, t0, nullptr, 256, 1024);
    ln_gate_kernel<false><<<NPIX / 256, blk2>>>(t0, x3, fc2_ln_w, fc2_ln_b, alpha + 768, out,
                                                nullptr, nullptr, nullptr);

    // second output: h
    if (out_size >= BATCH * DIM * L + BATCH * DIM * STATE)
        copy_kernel<<<BATCH * DIM * STATE / 256, 256>>>(h, out + BATCH * DIM * L);
}

// round 13
// speedup vs baseline: 1.7698x; 1.0935x over previous
#include <cuda_runtime.h>
#include <cuda_bf16.h>
#include <cstdint>
#include <math.h>

#define BATCH 16
#define DIM 256
#define STATE 64
#define HIDDEN 1024
#define L 4096
#define NPIX (BATCH*L)
#define PIXBLK (NPIX/64)
#define NSEG 8

// ---------------- scratch ----------------
__device__ float g_t0[BATCH*DIM*L];
__device__ float g_x1[BATCH*DIM*L];
__device__ float g_xn[BATCH*DIM*L];
__device__ float g_x2[BATCH*DIM*L];
__device__ float g_x3[BATCH*DIM*L];
__device__ float g_bcdt[BATCH*192*L];
__device__ float g_bcdt2[BATCH*192*L];
__device__ float g_AB[BATCH*STATE*L];
__device__ float g_hpart[NSEG*BATCH*DIM*STATE];
__device__ float g_h[BATCH*DIM*STATE];
__device__ float g_hz[BATCH*2*DIM*STATE];
__device__ float g_hg[BATCH*DIM*STATE];
__device__ float g_ho[BATCH*DIM*STATE];
__device__ float g_f1t[(size_t)BATCH*L*HIDDEN];
__device__ __nv_bfloat16 g_x3th[BATCH*L*DIM];
__device__ __nv_bfloat16 g_x3tl[BATCH*L*DIM];
__device__ __nv_bfloat16 g_xnth[BATCH*L*DIM];
__device__ __nv_bfloat16 g_xntl[BATCH*L*DIM];
__device__ __nv_bfloat16 g_f1th[(size_t)BATCH*L*HIDDEN];
__device__ __nv_bfloat16 g_f1tl[(size_t)BATCH*L*HIDDEN];
__device__ __nv_bfloat16 g_w1h[HIDDEN*DIM];
__device__ __nv_bfloat16 g_w1l[HIDDEN*DIM];
__device__ __nv_bfloat16 g_w2h[DIM*HIDDEN];
__device__ __nv_bfloat16 g_w2l[DIM*HIDDEN];
__device__ __nv_bfloat16 g_wbch[256*DIM];
__device__ __nv_bfloat16 g_wbcl[256*DIM];

// ---------------- helpers ----------------
__device__ __forceinline__ float2 ffma2(float2 a, float2 b, float2 c) {
    float2 d;
    asm("{\n\t.reg .b64 ra, rb, rc, rd;\n\t"
        "mov.b64 ra, {%2, %3};\n\tmov.b64 rb, {%4, %5};\n\tmov.b64 rc, {%6, %7};\n\t"
        "fma.rn.f32x2 rd, ra, rb, rc;\n\tmov.b64 {%0, %1}, rd;\n\t}"
        : "=f"(d.x), "=f"(d.y)
        : "f"(a.x), "f"(a.y), "f"(b.x), "f"(b.y), "f"(c.x), "f"(c.y));
    return d;
}
__device__ __forceinline__ float sigm(float v) { return 1.f / (1.f + __expf(-v)); }
__device__ __forceinline__ float4 f4add(float4 a, float4 b) {
    return make_float4(a.x + b.x, a.y + b.y, a.z + b.z, a.w + b.w);
}

#define CPA16(dst, src) asm volatile("cp.async.cg.shared.global [%0], [%1], 16;" :: "r"(dst), "l"(src))
#define SWZ(o) ((o) ^ (((o) >> 3) & 0x70u))

__device__ __forceinline__ uint32_t s2u(const void* p) {
    uint32_t a;
    asm("{ .reg .u64 t; cvta.to.shared.u64 t, %1; cvt.u32.u64 %0, t; }" : "=r"(a) : "l"(p));
    return a;
}

#define LDSM4(r, a) \
    asm volatile("ldmatrix.sync.aligned.m8n8.x4.shared.b16 {%0,%1,%2,%3}, [%4];" \
        : "=r"((r)[0]), "=r"((r)[1]), "=r"((r)[2]), "=r"((r)[3]) : "r"(a))

#define MMA16816(d, a, b) \
    asm volatile("mma.sync.aligned.m16n8k16.row.col.f32.bf16.bf16.f32 " \
        "{%0,%1,%2,%3},{%4,%5,%6,%7},{%8,%9},{%0,%1,%2,%3};" \
        : "+f"((d)[0]), "+f"((d)[1]), "+f"((d)[2]), "+f"((d)[3]) \
        : "r"((a)[0]), "r"((a)[1]), "r"((a)[2]), "r"((a)[3]), "r"((b)[0]), "r"((b)[1]))

// ---------------- tensor-core GEMM (mma.sync bf16 hi/lo), tile M64 x N128, 2 CTA/SM ----------
// Per buffer: A hi 8K @0, A lo 8K @8192, B hi 16K @16384, B lo 16K @32768 (49152 total).
#define GSMEM 98304
template<int TRANS>
__global__ __launch_bounds__(256) void gemm_mma_kernel(
    const __nv_bfloat16* __restrict__ Wh, const __nv_bfloat16* __restrict__ Wl,
    const __nv_bfloat16* __restrict__ Xh, const __nv_bfloat16* __restrict__ Xl,
    float* __restrict__ Y, const float* __restrict__ bias, int O, int C)
{
    extern __shared__ char dsm[];
    uint32_t sb = s2u(dsm);
    int tid = threadIdx.x, warp = tid >> 5, lane = tid & 31;
    int wm = warp >> 2, wn = warp & 3;       // 2(M) x 4(N) warps; warp tile 32M x 32N
    int bb = blockIdx.x >> 5;
    int l0 = (blockIdx.x & 31) << 7;
    int m0 = blockIdx.y << 6;
    int nchunk = C >> 6;
    size_t rowb = (size_t)bb * 4096 + l0;

    float acc[2][4][4];
#pragma unroll
    for (int i = 0; i < 2; ++i)
#pragma unroll
        for (int j = 0; j < 4; ++j)
#pragma unroll
            for (int q = 0; q < 4; ++q) acc[i][j][q] = 0.f;

    auto issue = [&](int cc, int buf) {
        int c0 = cc << 6;
        uint32_t base = sb + (uint32_t)buf * 49152u;
#pragma unroll
        for (int i = 0; i < 2; ++i) {                 // A: 64 rows x 8 sectors
            int e = tid + i * 256;
            int row = e >> 3, c16 = e & 7;
            uint32_t sw = SWZ((uint32_t)(row * 128 + c16 * 16));
            CPA16(base + sw,          Wh + (size_t)(m0 + row) * C + c0 + c16 * 8);
            CPA16(base + 8192u + sw,  Wl + (size_t)(m0 + row) * C + c0 + c16 * 8);
        }
#pragma unroll
        for (int i = 0; i < 4; ++i) {                 // B: 128 rows x 8 sectors
            int e = tid + i * 256;
            int row = e >> 3, c16 = e & 7;
            uint32_t sw = SWZ((uint32_t)(row * 128 + c16 * 16));
            CPA16(base + 16384u + sw,  Xh + (rowb + row) * (size_t)C + c0 + c16 * 8);
            CPA16(base + 32768u + sw,  Xl + (rowb + row) * (size_t)C + c0 + c16 * 8);
        }
        asm volatile("cp.async.commit_group;");
    };

    issue(0, 0);
    for (int cc = 0; cc < nchunk; ++cc) {
        int buf = cc & 1;
        if (cc + 1 < nchunk) {
            issue(cc + 1, buf ^ 1);
            asm volatile("cp.async.wait_group 1;");
        } else {
            asm volatile("cp.async.wait_group 0;");
        }
        __syncthreads();
        uint32_t base = sb + (uint32_t)buf * 49152u;

        int lr = (lane & 7) + ((lane >> 3) & 1) * 8;
        int kb = (lane >> 4) * 8;
#pragma unroll
        for (int kt = 0; kt < 4; ++kt) {
            uint32_t ah[2][4], al[2][4];
#pragma unroll
            for (int mt = 0; mt < 2; ++mt) {
                int row = wm * 32 + mt * 16 + lr;
                uint32_t a = base + SWZ((uint32_t)(row * 128 + (kt * 16 + kb) * 2));
                LDSM4(ah[mt], a);
                LDSM4(al[mt], a + 8192u);
            }
            uint32_t bh[4][2], bl[4][2];
#pragma unroll
            for (int np = 0; np < 2; ++np) {
                int row = wn * 32 + np * 16 + lr;
                uint32_t a = base + 16384u + SWZ((uint32_t)(row * 128 + (kt * 16 + kb) * 2));
                uint32_t r[4], rl[4];
                LDSM4(r, a);
                LDSM4(rl, a + 16384u);
                bh[np * 2][0] = r[0]; bh[np * 2][1] = r[2];
                bh[np * 2 + 1][0] = r[1]; bh[np * 2 + 1][1] = r[3];
                bl[np * 2][0] = rl[0]; bl[np * 2][1] = rl[2];
                bl[np * 2 + 1][0] = rl[1]; bl[np * 2 + 1][1] = rl[3];
            }
#pragma unroll
            for (int mt = 0; mt < 2; ++mt)
#pragma unroll
                for (int nt = 0; nt < 4; ++nt) {
                    MMA16816(acc[mt][nt], ah[mt], bh[nt]);
                    MMA16816(acc[mt][nt], ah[mt], bl[nt]);
                    MMA16816(acc[mt][nt], al[mt], bh[nt]);
                }
        }
        __syncthreads();
    }

    int mrow = (lane >> 2);
    int ncol = (lane & 3) * 2;
    if (TRANS == 0) {
#pragma unroll
        for (int mt = 0; mt < 2; ++mt) {
            int o = m0 + wm * 32 + mt * 16 + mrow;
            float bv0 = (o < O && bias) ? bias[o] : 0.f;
            float bv1 = (o + 8 < O && bias) ? bias[o + 8] : 0.f;
            float* yp0 = Y + ((size_t)bb * O + o) * 4096 + l0 + wn * 32;
            float* yp1 = Y + ((size_t)bb * O + o + 8) * 4096 + l0 + wn * 32;
#pragma unroll
            for (int nt = 0; nt < 4; ++nt) {
                if (o < O)
                    *(float2*)(yp0 + nt * 8 + ncol) = make_float2(acc[mt][nt][0] + bv0, acc[mt][nt][1] + bv0);
                if (o + 8 < O)
                    *(float2*)(yp1 + nt * 8 + ncol) = make_float2(acc[mt][nt][2] + bv1, acc[mt][nt][3] + bv1);
            }
        }
    } else {
        // stage [128 px][64 o] (stride 68) then row-major writeout
        float* st = (float*)dsm;
#pragma unroll
        for (int mt = 0; mt < 2; ++mt) {
            int ob = wm * 32 + mt * 16 + mrow;
#pragma unroll
            for (int nt = 0; nt < 4; ++nt) {
                int pxb = wn * 32 + nt * 8 + ncol;
                st[pxb * 68 + ob] = acc[mt][nt][0];
                st[(pxb + 1) * 68 + ob] = acc[mt][nt][1];
                st[pxb * 68 + ob + 8] = acc[mt][nt][2];
                st[(pxb + 1) * 68 + ob + 8] = acc[mt][nt][3];
            }
        }
        __syncthreads();
        int px = tid >> 1, hf = (tid & 1) * 32;
        float* dst = Y + (rowb + px) * (size_t)O + m0 + hf;
        const float* src = st + px * 68 + hf;
#pragma unroll
        for (int j = 0; j < 8; ++j)
            *(float4*)(dst + j * 4) = *(const float4*)(src + j * 4);
    }
}

// ---------------- transpose + bf16 hi/lo split ----------------
__global__ __launch_bounds__(256) void convt_kernel(
    const float* __restrict__ in, __nv_bfloat16* __restrict__ oh,
    __nv_bfloat16* __restrict__ ol, int C)
{
    __shared__ float s[64][33];
    int tid = threadIdx.x;
    int lx = tid & 31, cy = tid >> 5;
    int l0 = blockIdx.x * 32;
    int c0 = blockIdx.y * 64;
    int b = blockIdx.z;
    const float* ip = in + ((size_t)b * C + c0) * L + l0;
#pragma unroll
    for (int i = 0; i < 8; ++i)
        s[cy + i * 8][lx] = ip[(size_t)(cy + i * 8) * L + lx];
    __syncthreads();
    int cp = tid & 31, ly = tid >> 5;
#pragma unroll
    for (int i = 0; i < 4; ++i) {
        int lrow = ly + i * 8;
        float f0 = s[2 * cp][lrow], f1 = s[2 * cp + 1][lrow];
        __nv_bfloat16 h0 = __float2bfloat16(f0);
        __nv_bfloat16 h1 = __float2bfloat16(f1);
        __nv_bfloat16 e0 = __float2bfloat16(f0 - __bfloat162float(h0));
        __nv_bfloat16 e1 = __float2bfloat16(f1 - __bfloat162float(h1));
        uint32_t hp = (uint32_t)__bfloat16_as_ushort(h0) | ((uint32_t)__bfloat16_as_ushort(h1) << 16);
        uint32_t lp = (uint32_t)__bfloat16_as_ushort(e0) | ((uint32_t)__bfloat16_as_ushort(e1) << 16);
        size_t o32 = (((size_t)b * L + l0 + lrow) * C + c0) / 2 + cp;
        ((uint32_t*)oh)[o32] = hp;
        ((uint32_t*)ol)[o32] = lp;
    }
}

// ---------------- fused LN(1024) + SiLU + bf16 hi/lo split ----------------
__global__ __launch_bounds__(256) void ln_silu_split_kernel(
    const float* __restrict__ f1t, __nv_bfloat16* __restrict__ oh, __nv_bfloat16* __restrict__ ol,
    const float* __restrict__ lnw, const float* __restrict__ lnb)
{
    int warp = threadIdx.x >> 5, lane = threadIdx.x & 31;
    size_t px = (size_t)blockIdx.x * 8 + warp;
    const float4* row = (const float4*)(f1t + px * 1024);
    const float4* w4 = (const float4*)lnw;
    const float4* b4 = (const float4*)lnb;

    float4 v[8];
    float s1 = 0.f, s2 = 0.f;
#pragma unroll
    for (int i = 0; i < 8; ++i) {
        v[i] = row[lane + i * 32];
        s1 += v[i].x + v[i].y + v[i].z + v[i].w;
        s2 += v[i].x * v[i].x + v[i].y * v[i].y + v[i].z * v[i].z + v[i].w * v[i].w;
    }
#pragma unroll
    for (int st = 16; st; st >>= 1) {
        s1 += __shfl_xor_sync(0xFFFFFFFF, s1, st);
        s2 += __shfl_xor_sync(0xFFFFFFFF, s2, st);
    }
    float u = s1 * (1.f / 1024.f);
    float rs = rsqrtf(s2 * (1.f / 1024.f) - u * u + 1e-5f);

    uint2* oh2 = (uint2*)(oh + px * 1024);
    uint2* ol2 = (uint2*)(ol + px * 1024);
#pragma unroll
    for (int i = 0; i < 8; ++i) {
        int c4 = lane + i * 32;
        float4 wv = w4[c4], bv = b4[c4];
        float g[4];
        g[0] = wv.x * (v[i].x - u) * rs + bv.x;
        g[1] = wv.y * (v[i].y - u) * rs + bv.y;
        g[2] = wv.z * (v[i].z - u) * rs + bv.z;
        g[3] = wv.w * (v[i].w - u) * rs + bv.w;
#pragma unroll
        for (int j = 0; j < 4; ++j) g[j] = g[j] * sigm(g[j]);
        __nv_bfloat16 h0 = __float2bfloat16(g[0]), h1 = __float2bfloat16(g[1]);
        __nv_bfloat16 h2 = __float2bfloat16(g[2]), h3 = __float2bfloat16(g[3]);
        uint2 hp, lp;
        hp.x = (uint32_t)__bfloat16_as_ushort(h0) | ((uint32_t)__bfloat16_as_ushort(h1) << 16);
        hp.y = (uint32_t)__bfloat16_as_ushort(h2) | ((uint32_t)__bfloat16_as_ushort(h3) << 16);
        __nv_bfloat16 e0 = __float2bfloat16(g[0] - __bfloat162float(h0));
        __nv_bfloat16 e1 = __float2bfloat16(g[1] - __bfloat162float(h1));
        __nv_bfloat16 e2 = __float2bfloat16(g[2] - __bfloat162float(h2));
        __nv_bfloat16 e3 = __float2bfloat16(g[3] - __bfloat162float(h3));
        lp.x = (uint32_t)__bfloat16_as_ushort(e0) | ((uint32_t)__bfloat16_as_ushort(e1) << 16);
        lp.y = (uint32_t)__bfloat16_as_ushort(e2) | ((uint32_t)__bfloat16_as_ushort(e3) << 16);
        oh2[c4] = hp;
        ol2[c4] = lp;
    }
}

__global__ __launch_bounds__(256) void wsplit_kernel(
    const float* __restrict__ w, __nv_bfloat16* __restrict__ wh, __nv_bfloat16* __restrict__ wl)
{
    int i = blockIdx.x * 256 + threadIdx.x;
    float f = w[i];
    __nv_bfloat16 h = __float2bfloat16(f);
    wh[i] = h;
    wl[i] = __float2bfloat16(f - __bfloat162float(h));
}

__global__ __launch_bounds__(256) void wsplit_pad_kernel(
    const float* __restrict__ w, __nv_bfloat16* __restrict__ wh, __nv_bfloat16* __restrict__ wl)
{
    int i = blockIdx.x * 256 + threadIdx.x;
    int row = i >> 8;
    float f = (row < 192) ? w[i] : 0.f;
    __nv_bfloat16 h = __float2bfloat16(f);
    wh[i] = h;
    wl[i] = __float2bfloat16(f - __bfloat162float(h));
}

// ---------------- depthwise 3x3 conv ----------------
__global__ __launch_bounds__(256) void dwconv8_kernel(
    const float* __restrict__ in, const float* __restrict__ w,
    const float* __restrict__ bias, float* __restrict__ out, int C)
{
    int t = blockIdx.x * 256 + threadIdx.x;
    int x0 = (t & 7) * 8;
    int r = t >> 3;
    int hh = r & 63;
    int bc = r >> 6;
    int c = bc - (bc / C) * C;
    const float* wp = w + c * 9;
    float wr[9];
#pragma unroll
    for (int i = 0; i < 9; ++i) wr[i] = wp[i];
    const float* ip = in + (long)bc * 4096;
    float bv = bias ? bias[c] : 0.f;
    float acc[8];
#pragma unroll
    for (int j = 0; j < 8; ++j) acc[j] = bv;
#pragma unroll
    for (int ky = 0; ky < 3; ++ky) {
        int y = hh + ky - 1;
        if ((unsigned)y < 64u) {
            const float* rp = ip + y * 64 + x0;
            float4 a = *(const float4*)rp;
            float4 b4 = *(const float4*)(rp + 4);
            float v[10];
            v[0] = (x0 > 0) ? rp[-1] : 0.f;
            v[1] = a.x; v[2] = a.y; v[3] = a.z; v[4] = a.w;
            v[5] = b4.x; v[6] = b4.y; v[7] = b4.z; v[8] = b4.w;
            v[9] = (x0 < 56) ? rp[8] : 0.f;
            float k0 = wr[ky * 3 + 0], k1 = wr[ky * 3 + 1], k2 = wr[ky * 3 + 2];
#pragma unroll
            for (int j = 0; j < 8; ++j)
                acc[j] += k0 * v[j] + k1 * v[j + 1] + k2 * v[j + 2];
        }
    }
    float* op = out + (long)bc * 4096 + hh * 64 + x0;
    *(float4*)op = make_float4(acc[0], acc[1], acc[2], acc[3]);
    *(float4*)(op + 4) = make_float4(acc[4], acc[5], acc[6], acc[7]);
}

// ---------------- fused channel-LN + gated residual (+optional 2nd LN), float4 over px -------
template<bool HAS2>
__global__ __launch_bounds__(256) void ln_gate_kernel(
    const float* __restrict__ t, const float* __restrict__ prev,
    const float* __restrict__ lnw, const float* __restrict__ lnb,
    const float* __restrict__ alpha_row, float* __restrict__ out,
    const float* __restrict__ lnw2, const float* __restrict__ lnb2,
    float* __restrict__ out2)
{
    __shared__ float4 r1[4][64], r2[4][64];
    int qx = threadIdx.x, cg = threadIdx.y;
    int Pg = blockIdx.x * 256;
    int b = Pg >> 12, l0 = Pg & 4095;
    size_t base = ((size_t)(b * DIM) * L + l0 + qx * 4) >> 2;

    const float4* t4 = (const float4*)t;
    const float4* p4 = (const float4*)prev;
    float4* o4 = (float4*)out;
    float4* o24 = (float4*)out2;
    const size_t L4 = L / 4;

    float4 s1 = make_float4(0.f, 0.f, 0.f, 0.f), s2 = s1;
#pragma unroll 8
    for (int c = 0; c < 64; ++c) {
        float4 v = t4[base + (size_t)(cg * 64 + c) * L4];
        s1 = f4add(s1, v);
        s2 = f4add(s2, make_float4(v.x * v.x, v.y * v.y, v.z * v.z, v.w * v.w));
    }
    r1[cg][qx] = s1; r2[cg][qx] = s2;
    __syncthreads();
    float4 ts1 = f4add(f4add(r1[0][qx], r1[1][qx]), f4add(r1[2][qx], r1[3][qx]));
    float4 ts2 = f4add(f4add(r2[0][qx], r2[1][qx]), f4add(r2[2][qx], r2[3][qx]));
    float4 u = make_float4(ts1.x * (1.f / 256.f), ts1.y * (1.f / 256.f),
                           ts1.z * (1.f / 256.f), ts1.w * (1.f / 256.f));
    float4 rs = make_float4(
        rsqrtf(ts2.x * (1.f / 256.f) - u.x * u.x + 1e-5f),
        rsqrtf(ts2.y * (1.f / 256.f) - u.y * u.y + 1e-5f),
        rsqrtf(ts2.z * (1.f / 256.f) - u.z * u.z + 1e-5f),
        rsqrtf(ts2.w * (1.f / 256.f) - u.w * u.w + 1e-5f));

    float4 b1 = make_float4(0.f, 0.f, 0.f, 0.f), b2 = b1;
#pragma unroll 8
    for (int c = 0; c < 64; ++c) {
        int ch = cg * 64 + c;
        size_t idx = base + (size_t)ch * L4;
        float4 v = t4[idx];
        float4 p = p4[idx];
        float w = lnw[ch], bb = lnb[ch];
        float a = sigm(alpha_row[ch]);
        float4 xv;
        xv.x = fmaf(a, fmaf(w, (v.x - u.x) * rs.x, bb) - p.x, p.x);
        xv.y = fmaf(a, fmaf(w, (v.y - u.y) * rs.y, bb) - p.y, p.y);
        xv.z = fmaf(a, fmaf(w, (v.z - u.z) * rs.z, bb) - p.z, p.z);
        xv.w = fmaf(a, fmaf(w, (v.w - u.w) * rs.w, bb) - p.w, p.w);
        o4[idx] = xv;
        if (HAS2) {
            b1 = f4add(b1, xv);
            b2 = f4add(b2, make_float4(xv.x * xv.x, xv.y * xv.y, xv.z * xv.z, xv.w * xv.w));
        }
    }
    if (HAS2) {
        __syncthreads();
        r1[cg][qx] = b1; r2[cg][qx] = b2;
        __syncthreads();
        float4 q1 = f4add(f4add(r1[0][qx], r1[1][qx]), f4add(r1[2][qx], r1[3][qx]));
        float4 q2 = f4add(f4add(r2[0][qx], r2[1][qx]), f4add(r2[2][qx], r2[3][qx]));
        float4 u1 = make_float4(q1.x * (1.f / 256.f), q1.y * (1.f / 256.f),
                                q1.z * (1.f / 256.f), q1.w * (1.f / 256.f));
        float4 rs2 = make_float4(
            rsqrtf(q2.x * (1.f / 256.f) - u1.x * u1.x + 1e-5f),
            rsqrtf(q2.y * (1.f / 256.f) - u1.y * u1.y + 1e-5f),
            rsqrtf(q2.z * (1.f / 256.f) - u1.z * u1.z + 1e-5f),
            rsqrtf(q2.w * (1.f / 256.f) - u1.w * u1.w + 1e-5f));
#pragma unroll 8
        for (int c = 0; c < 64; ++c) {
            int ch = cg * 64 + c;
            size_t idx = base + (size_t)ch * L4;
            float4 xv = o4[idx];
            float w = lnw2[ch], bb = lnb2[ch];
            float4 nv;
            nv.x = fmaf(w, (xv.x - u1.x) * rs2.x, bb);
            nv.y = fmaf(w, (xv.y - u1.y) * rs2.y, bb);
            nv.z = fmaf(w, (xv.z - u1.z) * rs2.z, bb);
            nv.w = fmaf(w, (xv.w - u1.w) * rs2.w, bb);
            o24[idx] = nv;
        }
    }
}

// ---------------- small GEMM for Ld=64 ----------------
template<int OT>
__global__ __launch_bounds__(256) void gemm1x1_kernel(
    const float* __restrict__ W, const float* __restrict__ bias,
    const float* __restrict__ X, float* __restrict__ Y,
    int O, int C, int Ld)
{
    constexpr int PT = OT / 8;
    constexpr int KC = 32;
    __shared__ float Ws[OT * KC];
    int tid = threadIdx.x;
    int pxl = tid & 31;
    int og = tid >> 5;
    int b = (blockIdx.x * 64) / Ld;
    int l0 = (blockIdx.x * 64) % Ld;
    int ob = blockIdx.y * OT;
    const float* Xb = X + (b * C) * Ld + l0 + pxl * 2;

    float2 acc[PT];
#pragma unroll
    for (int i = 0; i < PT; ++i) acc[i] = make_float2(0.f, 0.f);

    for (int c0 = 0; c0 < C; c0 += KC) {
        __syncthreads();
#pragma unroll
        for (int e = tid; e < OT * KC; e += 256) {
            int ol = e >> 5, k = e & 31;
            Ws[e] = W[(ob + ol) * C + c0 + k];
        }
        __syncthreads();
#pragma unroll 4
        for (int k = 0; k < KC; ++k) {
            float2 xv = *reinterpret_cast<const float2*>(Xb + (c0 + k) * Ld);
#pragma unroll
            for (int i = 0; i < PT; ++i) {
                float wv = Ws[(og * PT + i) * KC + k];
                acc[i] = ffma2(make_float2(wv, wv), xv, acc[i]);
            }
        }
    }
#pragma unroll
    for (int i = 0; i < PT; ++i) {
        int o = ob + og * PT + i;
        float bv = bias ? bias[o] : 0.f;
        float2 r = make_float2(acc[i].x + bv, acc[i].y + bv);
        *reinterpret_cast<float2*>(Y + (b * O + o) * Ld + l0 + pxl * 2) = r;
    }
}

// ---------------- softmax over L (register-resident, float4) ----------------
__global__ __launch_bounds__(256) void softmax_ab_kernel(
    const float* __restrict__ bcdt2, float* __restrict__ AB)
{
    int bs = blockIdx.x;
    int b = bs >> 6, s = bs & 63;
    const float4* dt = (const float4*)(bcdt2 + (size_t)(b * 192 + 128 + s) * L);
    const float4* Bm = (const float4*)(bcdt2 + (size_t)(b * 192 + s) * L);
    float4* out = (float4*)(AB + (size_t)(b * 64 + s) * L);
    __shared__ float red[256];
    int tid = threadIdx.x;

    float4 v[4];
    float m = -1e30f;
#pragma unroll
    for (int i = 0; i < 4; ++i) {
        v[i] = dt[tid + i * 256];
        m = fmaxf(m, fmaxf(fmaxf(v[i].x, v[i].y), fmaxf(v[i].z, v[i].w)));
    }
    red[tid] = m; __syncthreads();
    for (int st = 128; st; st >>= 1) { if (tid < st) red[tid] = fmaxf(red[tid], red[tid + st]); __syncthreads(); }
    m = red[0];
    __syncthreads();

    float sm = 0.f;
#pragma unroll
    for (int i = 0; i < 4; ++i) {
        v[i].x = __expf(v[i].x - m);
        v[i].y = __expf(v[i].y - m);
        v[i].z = __expf(v[i].z - m);
        v[i].w = __expf(v[i].w - m);
        sm += v[i].x + v[i].y + v[i].z + v[i].w;
    }
    red[tid] = sm; __syncthreads();
    for (int st = 128; st; st >>= 1) { if (tid < st) red[tid] += red[tid + st]; __syncthreads(); }
    float inv = 1.f / red[0];

#pragma unroll
    for (int i = 0; i < 4; ++i) {
        float4 bm = Bm[tid + i * 256];
        out[tid + i * 256] = make_float4(v[i].x * inv * bm.x, v[i].y * inv * bm.y,
                                         v[i].z * inv * bm.z, v[i].w * inv * bm.w);
    }
}

// ---------------- h partials: k-major smem tiles, ffma2 inner ----------------
__global__ __launch_bounds__(256) void hgemm_kernel(
    const float* __restrict__ xn, const float* __restrict__ AB, float* __restrict__ hpart)
{
    int b = blockIdx.x, dtile = blockIdx.y, seg = blockIdx.z;
    int d0 = dtile * 64;
    int lb = seg * (L / NSEG);
    __shared__ float xs[16][66], as[16][66];
    int tid = threadIdx.x, tx = tid & 15, ty = tid >> 4;
    float2 acc[4][2];
#pragma unroll
    for (int i = 0; i < 4; ++i) {
        acc[i][0] = make_float2(0.f, 0.f);
        acc[i][1] = make_float2(0.f, 0.f);
    }

    const float* xp = xn + (b * DIM + d0) * L + lb;
    const float* ap = AB + (b * 64) * L + lb;

    for (int k0 = 0; k0 < L / NSEG; k0 += 16) {
        __syncthreads();
#pragma unroll
        for (int e = tid; e < 1024; e += 256) {
            int r = e >> 4, c = e & 15;
            xs[c][r] = xp[r * L + k0 + c];
            as[c][r] = ap[r * L + k0 + c];
        }
        __syncthreads();
#pragma unroll
        for (int k = 0; k < 16; ++k) {
            float2 bb0 = *(const float2*)&as[k][tx * 4];
            float2 bb1 = *(const float2*)&as[k][tx * 4 + 2];
#pragma unroll
            for (int i = 0; i < 4; ++i) {
                float xa = xs[k][ty * 4 + i];
                float2 xa2 = make_float2(xa, xa);
                acc[i][0] = ffma2(xa2, bb0, acc[i][0]);
                acc[i][1] = ffma2(xa2, bb1, acc[i][1]);
            }
        }
    }
    float* hp = hpart + seg * (BATCH * DIM * STATE);
#pragma unroll
    for (int i = 0; i < 4; ++i) {
        float* row = hp + (b * DIM + d0 + ty * 4 + i) * STATE + tx * 4;
        *(float2*)row = acc[i][0];
        *(float2*)(row + 2) = acc[i][1];
    }
}

__global__ __launch_bounds__(256) void hreduce_kernel(
    const float* __restrict__ hpart, float* __restrict__ h)
{
    int idx = blockIdx.x * 256 + threadIdx.x;
    float s = 0.f;
#pragma unroll
    for (int g = 0; g < NSEG; ++g) s += hpart[g * (BATCH * DIM * STATE) + idx];
    h[idx] = s;
}

__global__ __launch_bounds__(256) void gate_kernel(
    const float* __restrict__ hz, float* __restrict__ hg)
{
    int idx = blockIdx.x * 256 + threadIdx.x;
    int s = idx & 63;
    int c = (idx >> 6) & 255;
    int b = idx >> 14;
    float hp = hz[(b * 512 + c) * 64 + s];
    float z = hz[(b * 512 + 256 + c) * 64 + s];
    hg[idx] = hp * z * sigm(z);
}

// ---------------- y = ho @ Cm ; x2  (ffma2 over px pairs) ----------------
__global__ __launch_bounds__(256) void y_fuse_kernel(
    const float* __restrict__ ho, const float* __restrict__ bcdt2,
    const float* __restrict__ xn, const float* __restrict__ x1,
    const float* __restrict__ Dp, const float* __restrict__ alpha1,
    float* __restrict__ x2)
{
    __shared__ float hos[16][257];
    int tid = threadIdx.x;
    int pxp = tid & 31, dg = tid >> 5;
    int Pg = blockIdx.x * 64;
    int b = Pg >> 12, l0 = Pg & 4095;
    const float* hob = ho + b * DIM * STATE;
    const float* cm = bcdt2 + (b * 192 + 64) * L + l0 + pxp * 2;

    float2 acc[32];
#pragma unroll
    for (int j = 0; j < 32; ++j) acc[j] = make_float2(0.f, 0.f);

    for (int sc = 0; sc < 4; ++sc) {
        __syncthreads();
#pragma unroll
        for (int e = tid; e < 4096; e += 256) {
            int d = e >> 4, s = e & 15;
            hos[s][d] = hob[d * 64 + sc * 16 + s];
        }
        __syncthreads();
#pragma unroll
        for (int s = 0; s < 16; ++s) {
            float2 cmv = *(const float2*)(cm + (size_t)(sc * 16 + s) * L);
#pragma unroll
            for (int j = 0; j < 32; ++j) {
                float w = hos[s][dg * 32 + j];
                acc[j] = ffma2(make_float2(w, w), cmv, acc[j]);
            }
        }
    }
#pragma unroll
    for (int j = 0; j < 32; ++j) {
        int d = dg * 32 + j;
        size_t idx = (size_t)(b * DIM + d) * L + l0 + pxp * 2;
        float2 xnv = *(const float2*)(xn + idx);
        float2 p = *(const float2*)(x1 + idx);
        float dp = Dp[d];
        float a = sigm(alpha1[d]);
        float2 r;
        r.x = fmaf(a, (acc[j].x + xnv.x * dp) - p.x, p.x);
        r.y = fmaf(a, (acc[j].y + xnv.y * dp) - p.y, p.y);
        *(float2*)(x2 + idx) = r;
    }
}

__global__ __launch_bounds__(256) void copy_kernel(
    const float* __restrict__ src, float* __restrict__ dst)
{
    int idx = blockIdx.x * 256 + threadIdx.x;
    dst[idx] = src[idx];
}

// ---------------- host launcher ----------------
extern "C" void kernel_launch(void* const* d_in, const int* in_sizes, int n_in,
                              void* d_out, int out_size)
{
    const float* x        = (const float*)d_in[0];
    const float* alpha    = (const float*)d_in[1];
    const float* ln_w     = (const float*)d_in[2];
    const float* ln_b     = (const float*)d_in[3];
    const float* dw1_w    = (const float*)d_in[4];
    const float* dw1_ln_w = (const float*)d_in[5];
    const float* dw1_ln_b = (const float*)d_in[6];
    const float* dw2_w    = (const float*)d_in[7];
    const float* dw2_ln_w = (const float*)d_in[8];
    const float* dw2_ln_b = (const float*)d_in[9];
    const float* bcdt_w   = (const float*)d_in[10];
    const float* bcdt_b   = (const float*)d_in[11];
    const float* dwm_w    = (const float*)d_in[12];
    const float* dwm_b    = (const float*)d_in[13];
    const float* hz_w     = (const float*)d_in[14];
    const float* hz_b     = (const float*)d_in[15];
    const float* outp_w   = (const float*)d_in[16];
    const float* outp_b   = (const float*)d_in[17];
    const float* Dp       = (const float*)d_in[19];
    const float* fc1_w    = (const float*)d_in[20];
    const float* fc1_ln_w = (const float*)d_in[21];
    const float* fc1_ln_b = (const float*)d_in[22];
    const float* fc2_w    = (const float*)d_in[23];
    const float* fc2_ln_w = (const float*)d_in[24];
    const float* fc2_ln_b = (const float*)d_in[25];
    float* out = (float*)d_out;

    float *t0, *x1, *xn, *x2, *x3, *bc, *bc2, *ab, *hpart, *h, *hz, *hg, *ho, *f1t;
    __nv_bfloat16 *x3th, *x3tl, *xnth, *xntl, *f1th, *f1tl, *w1h, *w1l, *w2h, *w2l, *wbch, *wbcl;
    cudaGetSymbolAddress((void**)&t0, g_t0);
    cudaGetSymbolAddress((void**)&x1, g_x1);
    cudaGetSymbolAddress((void**)&xn, g_xn);
    cudaGetSymbolAddress((void**)&x2, g_x2);
    cudaGetSymbolAddress((void**)&x3, g_x3);
    cudaGetSymbolAddress((void**)&bc, g_bcdt);
    cudaGetSymbolAddress((void**)&bc2, g_bcdt2);
    cudaGetSymbolAddress((void**)&ab, g_AB);
    cudaGetSymbolAddress((void**)&hpart, g_hpart);
    cudaGetSymbolAddress((void**)&h, g_h);
    cudaGetSymbolAddress((void**)&hz, g_hz);
    cudaGetSymbolAddress((void**)&hg, g_hg);
    cudaGetSymbolAddress((void**)&ho, g_ho);
    cudaGetSymbolAddress((void**)&f1t, g_f1t);
    cudaGetSymbolAddress((void**)&x3th, g_x3th);
    cudaGetSymbolAddress((void**)&x3tl, g_x3tl);
    cudaGetSymbolAddress((void**)&xnth, g_xnth);
    cudaGetSymbolAddress((void**)&xntl, g_xntl);
    cudaGetSymbolAddress((void**)&f1th, g_f1th);
    cudaGetSymbolAddress((void**)&f1tl, g_f1tl);
    cudaGetSymbolAddress((void**)&w1h, g_w1h);
    cudaGetSymbolAddress((void**)&w1l, g_w1l);
    cudaGetSymbolAddress((void**)&w2h, g_w2h);
    cudaGetSymbolAddress((void**)&w2l, g_w2l);
    cudaGetSymbolAddress((void**)&wbch, g_wbch);
    cudaGetSymbolAddress((void**)&wbcl, g_wbcl);

    cudaFuncSetAttribute(gemm_mma_kernel<0>, cudaFuncAttributeMaxDynamicSharedMemorySize, GSMEM);
    cudaFuncSetAttribute(gemm_mma_kernel<1>, cudaFuncAttributeMaxDynamicSharedMemorySize, GSMEM);

    dim3 blk2(64, 4);

    // weight splits
    wsplit_kernel<<<HIDDEN * DIM / 256, 256>>>(fc1_w, w1h, w1l);
    wsplit_kernel<<<DIM * HIDDEN / 256, 256>>>(fc2_w, w2h, w2l);
    wsplit_pad_kernel<<<256 * DIM / 256, 256>>>(bcdt_w, wbch, wbcl);

    // sub-layer 1: dwconv + LN+gate (+2nd LN), then transpose+split xn
    dwconv8_kernel<<<BATCH * DIM * L / 8 / 256, 256>>>(x, dw1_w, nullptr, t0, DIM);
    ln_gate_kernel<true><<<NPIX / 256, blk2>>>(t0, x, dw1_ln_w, dw1_ln_b, alpha, x1,
                                               ln_w, ln_b, xn);
    convt_kernel<<<dim3(L / 32, DIM / 64, BATCH), 256>>>(xn, xnth, xntl, DIM);

    // HSMSSD mixer (bcdt: 192 = 3 x 64 exact M-tiles)
    gemm_mma_kernel<0><<<dim3(NPIX / 128, 3), 256, GSMEM>>>(wbch, wbcl, xnth, xntl, bc, bcdt_b, 192, 256);
    dwconv8_kernel<<<BATCH * 192 * L / 8 / 256, 256>>>(bc, dwm_w, dwm_b, bc2, 192);
    softmax_ab_kernel<<<BATCH * 64, 256>>>(bc2, ab);
    hgemm_kernel<<<dim3(BATCH, 4, NSEG), 256>>>(xn, ab, hpart);
    hreduce_kernel<<<BATCH * DIM * STATE / 256, 256>>>(hpart, h);
    gemm1x1_kernel<128><<<dim3(BATCH, 4), 256>>>(hz_w, hz_b, h, hz, 512, 256, 64);
    gate_kernel<<<BATCH * DIM * STATE / 256, 256>>>(hz, hg);
    gemm1x1_kernel<128><<<dim3(BATCH, 2), 256>>>(outp_w, outp_b, hg, ho, 256, 256, 64);
    y_fuse_kernel<<<PIXBLK, 256>>>(ho, bc2, xn, x1, Dp, alpha + 256, x2);

    // sub-layer 3: dwconv + LN+gate, then transpose+split x3
    dwconv8_kernel<<<BATCH * DIM * L / 8 / 256, 256>>>(x2, dw2_w, nullptr, t0, DIM);
    ln_gate_kernel<false><<<NPIX / 256, blk2>>>(t0, x2, dw2_ln_w, dw2_ln_b, alpha + 512, x3,
                                                nullptr, nullptr, nullptr);
    convt_kernel<<<dim3(L / 32, DIM / 64, BATCH), 256>>>(x3, x3th, x3tl, DIM);

    // FFN
    gemm_mma_kernel<1><<<dim3(NPIX / 128, HIDDEN / 64), 256, GSMEM>>>(w1h, w1l, x3th, x3tl, f1t, nullptr, HIDDEN, 256);
    ln_silu_split_kernel<<<NPIX / 8, 256>>>(f1t, f1th, f1tl, fc1_ln_w, fc1_ln_b);
    gemm_mma_kernel<0><<<dim3(NPIX / 128, 4), 256, GSMEM>>>(w2h, w2l, f1th, f1tl, t0, nullptr, 256, 1024);
    ln_gate_kernel<false><<<NPIX / 256, blk2>>>(t0, x3, fc2_ln_w, fc2_ln_b, alpha + 768, out,
                                                nullptr, nullptr, nullptr);

    // second output: h
    if (out_size >= BATCH * DIM * L + BATCH * DIM * STATE)
        copy_kernel<<<BATCH * DIM * STATE / 256, 256>>>(h, out + BATCH * DIM * L);
}

// round 14
// speedup vs baseline: 1.8006x; 1.0174x over previous
#include <cuda_runtime.h>
#include <cuda_bf16.h>
#include <cstdint>
#include <math.h>

#define BATCH 16
#define DIM 256
#define STATE 64
#define HIDDEN 1024
#define L 4096
#define NPIX (BATCH*L)
#define PIXBLK (NPIX/64)
#define NSEG 8

// ---------------- scratch ----------------
__device__ float g_t0[BATCH*DIM*L];
__device__ float g_x1[BATCH*DIM*L];
__device__ float g_xn[BATCH*DIM*L];
__device__ float g_x2[BATCH*DIM*L];
__device__ float g_x3[BATCH*DIM*L];
__device__ float g_bcdt[BATCH*192*L];
__device__ float g_bcdt2[BATCH*192*L];
__device__ float g_AB[BATCH*STATE*L];
__device__ float g_hpart[NSEG*BATCH*DIM*STATE];
__device__ float g_h[BATCH*DIM*STATE];
__device__ float g_hz[BATCH*2*DIM*STATE];
__device__ float g_hg[BATCH*DIM*STATE];
__device__ float g_ho[BATCH*DIM*STATE];
__device__ float g_f1t[(size_t)BATCH*L*HIDDEN];
__device__ __nv_bfloat16 g_x3th[BATCH*L*DIM];
__device__ __nv_bfloat16 g_x3tl[BATCH*L*DIM];
__device__ __nv_bfloat16 g_xnth[BATCH*L*DIM];
__device__ __nv_bfloat16 g_xntl[BATCH*L*DIM];
__device__ __nv_bfloat16 g_f1th[(size_t)BATCH*L*HIDDEN];
__device__ __nv_bfloat16 g_f1tl[(size_t)BATCH*L*HIDDEN];
__device__ __nv_bfloat16 g_w1h[HIDDEN*DIM];
__device__ __nv_bfloat16 g_w1l[HIDDEN*DIM];
__device__ __nv_bfloat16 g_w2h[DIM*HIDDEN];
__device__ __nv_bfloat16 g_w2l[DIM*HIDDEN];
__device__ __nv_bfloat16 g_wbch[256*DIM];
__device__ __nv_bfloat16 g_wbcl[256*DIM];

// ---------------- helpers ----------------
__device__ __forceinline__ float2 ffma2(float2 a, float2 b, float2 c) {
    float2 d;
    asm("{\n\t.reg .b64 ra, rb, rc, rd;\n\t"
        "mov.b64 ra, {%2, %3};\n\tmov.b64 rb, {%4, %5};\n\tmov.b64 rc, {%6, %7};\n\t"
        "fma.rn.f32x2 rd, ra, rb, rc;\n\tmov.b64 {%0, %1}, rd;\n\t}"
        : "=f"(d.x), "=f"(d.y)
        : "f"(a.x), "f"(a.y), "f"(b.x), "f"(b.y), "f"(c.x), "f"(c.y));
    return d;
}
__device__ __forceinline__ float sigm(float v) { return 1.f / (1.f + __expf(-v)); }
__device__ __forceinline__ float4 f4add(float4 a, float4 b) {
    return make_float4(a.x + b.x, a.y + b.y, a.z + b.z, a.w + b.w);
}

#define CPA16(dst, src) asm volatile("cp.async.cg.shared.global [%0], [%1], 16;" :: "r"(dst), "l"(src))
#define SWZ(o) ((o) ^ (((o) >> 3) & 0x70u))

__device__ __forceinline__ uint32_t s2u(const void* p) {
    uint32_t a;
    asm("{ .reg .u64 t; cvta.to.shared.u64 t, %1; cvt.u32.u64 %0, t; }" : "=r"(a) : "l"(p));
    return a;
}

#define LDSM4(r, a) \
    asm volatile("ldmatrix.sync.aligned.m8n8.x4.shared.b16 {%0,%1,%2,%3}, [%4];" \
        : "=r"((r)[0]), "=r"((r)[1]), "=r"((r)[2]), "=r"((r)[3]) : "r"(a))

#define MMA16816(d, a, b) \
    asm volatile("mma.sync.aligned.m16n8k16.row.col.f32.bf16.bf16.f32 " \
        "{%0,%1,%2,%3},{%4,%5,%6,%7},{%8,%9},{%0,%1,%2,%3};" \
        : "+f"((d)[0]), "+f"((d)[1]), "+f"((d)[2]), "+f"((d)[3]) \
        : "r"((a)[0]), "r"((a)[1]), "r"((a)[2]), "r"((a)[3]), "r"((b)[0]), "r"((b)[1]))

// ---------------- tensor-core GEMM (mma.sync bf16 hi/lo), tile M64 x N64, 3 CTA/SM ----------
// Per buffer: A hi 8K @0, A lo 8K @8192, B hi 8K @16384, B lo 8K @24576 (32768 total).
// 128 threads = 4 warps = 2(M) x 2(N); warp tile 32M x 32N (same ratio as R13).
#define GSMEM 65536
template<int TRANS>
__global__ __launch_bounds__(128) void gemm_mma_kernel(
    const __nv_bfloat16* __restrict__ Wh, const __nv_bfloat16* __restrict__ Wl,
    const __nv_bfloat16* __restrict__ Xh, const __nv_bfloat16* __restrict__ Xl,
    float* __restrict__ Y, const float* __restrict__ bias, int O, int C)
{
    extern __shared__ char dsm[];
    uint32_t sb = s2u(dsm);
    int tid = threadIdx.x, warp = tid >> 5, lane = tid & 31;
    int wm = warp >> 1, wn = warp & 1;
    int bb = blockIdx.x >> 6;
    int l0 = (blockIdx.x & 63) << 6;
    int m0 = blockIdx.y << 6;
    int nchunk = C >> 6;
    size_t rowb = (size_t)bb * 4096 + l0;

    float acc[2][4][4];
#pragma unroll
    for (int i = 0; i < 2; ++i)
#pragma unroll
        for (int j = 0; j < 4; ++j)
#pragma unroll
            for (int q = 0; q < 4; ++q) acc[i][j][q] = 0.f;

    auto issue = [&](int cc, int buf) {
        int c0 = cc << 6;
        uint32_t base = sb + (uint32_t)buf * 32768u;
#pragma unroll
        for (int i = 0; i < 4; ++i) {                 // A: 64 rows x 8 sectors / 128 thr
            int e = tid + i * 128;
            int row = e >> 3, c16 = e & 7;
            uint32_t sw = SWZ((uint32_t)(row * 128 + c16 * 16));
            CPA16(base + sw,          Wh + (size_t)(m0 + row) * C + c0 + c16 * 8);
            CPA16(base + 8192u + sw,  Wl + (size_t)(m0 + row) * C + c0 + c16 * 8);
        }
#pragma unroll
        for (int i = 0; i < 4; ++i) {                 // B: 64 rows x 8 sectors / 128 thr
            int e = tid + i * 128;
            int row = e >> 3, c16 = e & 7;
            uint32_t sw = SWZ((uint32_t)(row * 128 + c16 * 16));
            CPA16(base + 16384u + sw,  Xh + (rowb + row) * (size_t)C + c0 + c16 * 8);
            CPA16(base + 24576u + sw,  Xl + (rowb + row) * (size_t)C + c0 + c16 * 8);
        }
        asm volatile("cp.async.commit_group;");
    };

    issue(0, 0);
    for (int cc = 0; cc < nchunk; ++cc) {
        int buf = cc & 1;
        if (cc + 1 < nchunk) {
            issue(cc + 1, buf ^ 1);
            asm volatile("cp.async.wait_group 1;");
        } else {
            asm volatile("cp.async.wait_group 0;");
        }
        __syncthreads();
        uint32_t base = sb + (uint32_t)buf * 32768u;

        int lr = (lane & 7) + ((lane >> 3) & 1) * 8;
        int kb = (lane >> 4) * 8;
#pragma unroll
        for (int kt = 0; kt < 4; ++kt) {
            uint32_t ah[2][4], al[2][4];
#pragma unroll
            for (int mt = 0; mt < 2; ++mt) {
                int row = wm * 32 + mt * 16 + lr;
                uint32_t a = base + SWZ((uint32_t)(row * 128 + (kt * 16 + kb) * 2));
                LDSM4(ah[mt], a);
                LDSM4(al[mt], a + 8192u);
            }
            uint32_t bh[4][2], bl[4][2];
#pragma unroll
            for (int np = 0; np < 2; ++np) {
                int row = wn * 32 + np * 16 + lr;
                uint32_t a = base + 16384u + SWZ((uint32_t)(row * 128 + (kt * 16 + kb) * 2));
                uint32_t r[4], rl[4];
                LDSM4(r, a);
                LDSM4(rl, a + 8192u);
                bh[np * 2][0] = r[0]; bh[np * 2][1] = r[2];
                bh[np * 2 + 1][0] = r[1]; bh[np * 2 + 1][1] = r[3];
                bl[np * 2][0] = rl[0]; bl[np * 2][1] = rl[2];
                bl[np * 2 + 1][0] = rl[1]; bl[np * 2 + 1][1] = rl[3];
            }
#pragma unroll
            for (int mt = 0; mt < 2; ++mt)
#pragma unroll
                for (int nt = 0; nt < 4; ++nt) {
                    MMA16816(acc[mt][nt], ah[mt], bh[nt]);
                    MMA16816(acc[mt][nt], ah[mt], bl[nt]);
                    MMA16816(acc[mt][nt], al[mt], bh[nt]);
                }
        }
        __syncthreads();
    }

    int mrow = (lane >> 2);
    int ncol = (lane & 3) * 2;
    if (TRANS == 0) {
#pragma unroll
        for (int mt = 0; mt < 2; ++mt) {
            int o = m0 + wm * 32 + mt * 16 + mrow;
            float bv0 = (o < O && bias) ? bias[o] : 0.f;
            float bv1 = (o + 8 < O && bias) ? bias[o + 8] : 0.f;
            float* yp0 = Y + ((size_t)bb * O + o) * 4096 + l0 + wn * 32;
            float* yp1 = Y + ((size_t)bb * O + o + 8) * 4096 + l0 + wn * 32;
#pragma unroll
            for (int nt = 0; nt < 4; ++nt) {
                if (o < O)
                    *(float2*)(yp0 + nt * 8 + ncol) = make_float2(acc[mt][nt][0] + bv0, acc[mt][nt][1] + bv0);
                if (o + 8 < O)
                    *(float2*)(yp1 + nt * 8 + ncol) = make_float2(acc[mt][nt][2] + bv1, acc[mt][nt][3] + bv1);
            }
        }
    } else {
        // stage [64 px][64 o] (stride 68) then row-major writeout
        float* st = (float*)dsm;
#pragma unroll
        for (int mt = 0; mt < 2; ++mt) {
            int ob = wm * 32 + mt * 16 + mrow;
#pragma unroll
            for (int nt = 0; nt < 4; ++nt) {
                int pxb = wn * 32 + nt * 8 + ncol;
                st[pxb * 68 + ob] = acc[mt][nt][0];
                st[(pxb + 1) * 68 + ob] = acc[mt][nt][1];
                st[pxb * 68 + ob + 8] = acc[mt][nt][2];
                st[(pxb + 1) * 68 + ob + 8] = acc[mt][nt][3];
            }
        }
        __syncthreads();
        int px = tid >> 1, hf = (tid & 1) * 32;
        float* dst = Y + (rowb + px) * (size_t)O + m0 + hf;
        const float* src = st + px * 68 + hf;
#pragma unroll
        for (int j = 0; j < 8; ++j)
            *(float4*)(dst + j * 4) = *(const float4*)(src + j * 4);
    }
}

// ---------------- transpose + bf16 hi/lo split ----------------
__global__ __launch_bounds__(256) void convt_kernel(
    const float* __restrict__ in, __nv_bfloat16* __restrict__ oh,
    __nv_bfloat16* __restrict__ ol, int C)
{
    __shared__ float s[64][33];
    int tid = threadIdx.x;
    int lx = tid & 31, cy = tid >> 5;
    int l0 = blockIdx.x * 32;
    int c0 = blockIdx.y * 64;
    int b = blockIdx.z;
    const float* ip = in + ((size_t)b * C + c0) * L + l0;
#pragma unroll
    for (int i = 0; i < 8; ++i)
        s[cy + i * 8][lx] = ip[(size_t)(cy + i * 8) * L + lx];
    __syncthreads();
    int cp = tid & 31, ly = tid >> 5;
#pragma unroll
    for (int i = 0; i < 4; ++i) {
        int lrow = ly + i * 8;
        float f0 = s[2 * cp][lrow], f1 = s[2 * cp + 1][lrow];
        __nv_bfloat16 h0 = __float2bfloat16(f0);
        __nv_bfloat16 h1 = __float2bfloat16(f1);
        __nv_bfloat16 e0 = __float2bfloat16(f0 - __bfloat162float(h0));
        __nv_bfloat16 e1 = __float2bfloat16(f1 - __bfloat162float(h1));
        uint32_t hp = (uint32_t)__bfloat16_as_ushort(h0) | ((uint32_t)__bfloat16_as_ushort(h1) << 16);
        uint32_t lp = (uint32_t)__bfloat16_as_ushort(e0) | ((uint32_t)__bfloat16_as_ushort(e1) << 16);
        size_t o32 = (((size_t)b * L + l0 + lrow) * C + c0) / 2 + cp;
        ((uint32_t*)oh)[o32] = hp;
        ((uint32_t*)ol)[o32] = lp;
    }
}

// ---------------- fused LN(1024) + SiLU + bf16 hi/lo split ----------------
__global__ __launch_bounds__(256) void ln_silu_split_kernel(
    const float* __restrict__ f1t, __nv_bfloat16* __restrict__ oh, __nv_bfloat16* __restrict__ ol,
    const float* __restrict__ lnw, const float* __restrict__ lnb)
{
    int warp = threadIdx.x >> 5, lane = threadIdx.x & 31;
    size_t px = (size_t)blockIdx.x * 8 + warp;
    const float4* row = (const float4*)(f1t + px * 1024);
    const float4* w4 = (const float4*)lnw;
    const float4* b4 = (const float4*)lnb;

    float4 v[8];
    float s1 = 0.f, s2 = 0.f;
#pragma unroll
    for (int i = 0; i < 8; ++i) {
        v[i] = row[lane + i * 32];
        s1 += v[i].x + v[i].y + v[i].z + v[i].w;
        s2 += v[i].x * v[i].x + v[i].y * v[i].y + v[i].z * v[i].z + v[i].w * v[i].w;
    }
#pragma unroll
    for (int st = 16; st; st >>= 1) {
        s1 += __shfl_xor_sync(0xFFFFFFFF, s1, st);
        s2 += __shfl_xor_sync(0xFFFFFFFF, s2, st);
    }
    float u = s1 * (1.f / 1024.f);
    float rs = rsqrtf(s2 * (1.f / 1024.f) - u * u + 1e-5f);

    uint2* oh2 = (uint2*)(oh + px * 1024);
    uint2* ol2 = (uint2*)(ol + px * 1024);
#pragma unroll
    for (int i = 0; i < 8; ++i) {
        int c4 = lane + i * 32;
        float4 wv = w4[c4], bv = b4[c4];
        float g[4];
        g[0] = wv.x * (v[i].x - u) * rs + bv.x;
        g[1] = wv.y * (v[i].y - u) * rs + bv.y;
        g[2] = wv.z * (v[i].z - u) * rs + bv.z;
        g[3] = wv.w * (v[i].w - u) * rs + bv.w;
#pragma unroll
        for (int j = 0; j < 4; ++j) g[j] = g[j] * sigm(g[j]);
        __nv_bfloat16 h0 = __float2bfloat16(g[0]), h1 = __float2bfloat16(g[1]);
        __nv_bfloat16 h2 = __float2bfloat16(g[2]), h3 = __float2bfloat16(g[3]);
        uint2 hp, lp;
        hp.x = (uint32_t)__bfloat16_as_ushort(h0) | ((uint32_t)__bfloat16_as_ushort(h1) << 16);
        hp.y = (uint32_t)__bfloat16_as_ushort(h2) | ((uint32_t)__bfloat16_as_ushort(h3) << 16);
        __nv_bfloat16 e0 = __float2bfloat16(g[0] - __bfloat162float(h0));
        __nv_bfloat16 e1 = __float2bfloat16(g[1] - __bfloat162float(h1));
        __nv_bfloat16 e2 = __float2bfloat16(g[2] - __bfloat162float(h2));
        __nv_bfloat16 e3 = __float2bfloat16(g[3] - __bfloat162float(h3));
        lp.x = (uint32_t)__bfloat16_as_ushort(e0) | ((uint32_t)__bfloat16_as_ushort(e1) << 16);
        lp.y = (uint32_t)__bfloat16_as_ushort(e2) | ((uint32_t)__bfloat16_as_ushort(e3) << 16);
        oh2[c4] = hp;
        ol2[c4] = lp;
    }
}

__global__ __launch_bounds__(256) void wsplit_kernel(
    const float* __restrict__ w, __nv_bfloat16* __restrict__ wh, __nv_bfloat16* __restrict__ wl)
{
    int i = blockIdx.x * 256 + threadIdx.x;
    float f = w[i];
    __nv_bfloat16 h = __float2bfloat16(f);
    wh[i] = h;
    wl[i] = __float2bfloat16(f - __bfloat162float(h));
}

__global__ __launch_bounds__(256) void wsplit_pad_kernel(
    const float* __restrict__ w, __nv_bfloat16* __restrict__ wh, __nv_bfloat16* __restrict__ wl)
{
    int i = blockIdx.x * 256 + threadIdx.x;
    int row = i >> 8;
    float f = (row < 192) ? w[i] : 0.f;
    __nv_bfloat16 h = __float2bfloat16(f);
    wh[i] = h;
    wl[i] = __float2bfloat16(f - __bfloat162float(h));
}

// ---------------- depthwise 3x3 conv ----------------
__global__ __launch_bounds__(256) void dwconv8_kernel(
    const float* __restrict__ in, const float* __restrict__ w,
    const float* __restrict__ bias, float* __restrict__ out, int C)
{
    int t = blockIdx.x * 256 + threadIdx.x;
    int x0 = (t & 7) * 8;
    int r = t >> 3;
    int hh = r & 63;
    int bc = r >> 6;
    int c = bc - (bc / C) * C;
    const float* wp = w + c * 9;
    float wr[9];
#pragma unroll
    for (int i = 0; i < 9; ++i) wr[i] = wp[i];
    const float* ip = in + (long)bc * 4096;
    float bv = bias ? bias[c] : 0.f;
    float acc[8];
#pragma unroll
    for (int j = 0; j < 8; ++j) acc[j] = bv;
#pragma unroll
    for (int ky = 0; ky < 3; ++ky) {
        int y = hh + ky - 1;
        if ((unsigned)y < 64u) {
            const float* rp = ip + y * 64 + x0;
            float4 a = *(const float4*)rp;
            float4 b4 = *(const float4*)(rp + 4);
            float v[10];
            v[0] = (x0 > 0) ? rp[-1] : 0.f;
            v[1] = a.x; v[2] = a.y; v[3] = a.z; v[4] = a.w;
            v[5] = b4.x; v[6] = b4.y; v[7] = b4.z; v[8] = b4.w;
            v[9] = (x0 < 56) ? rp[8] : 0.f;
            float k0 = wr[ky * 3 + 0], k1 = wr[ky * 3 + 1], k2 = wr[ky * 3 + 2];
#pragma unroll
            for (int j = 0; j < 8; ++j)
                acc[j] += k0 * v[j] + k1 * v[j + 1] + k2 * v[j + 2];
        }
    }
    float* op = out + (long)bc * 4096 + hh * 64 + x0;
    *(float4*)op = make_float4(acc[0], acc[1], acc[2], acc[3]);
    *(float4*)(op + 4) = make_float4(acc[4], acc[5], acc[6], acc[7]);
}

// ---------------- fused channel-LN + gated residual (+optional 2nd LN), float4 over px -------
template<bool HAS2>
__global__ __launch_bounds__(256) void ln_gate_kernel(
    const float* __restrict__ t, const float* __restrict__ prev,
    const float* __restrict__ lnw, const float* __restrict__ lnb,
    const float* __restrict__ alpha_row, float* __restrict__ out,
    const float* __restrict__ lnw2, const float* __restrict__ lnb2,
    float* __restrict__ out2)
{
    __shared__ float4 r1[4][64], r2[4][64];
    int qx = threadIdx.x, cg = threadIdx.y;
    int Pg = blockIdx.x * 256;
    int b = Pg >> 12, l0 = Pg & 4095;
    size_t base = ((size_t)(b * DIM) * L + l0 + qx * 4) >> 2;

    const float4* t4 = (const float4*)t;
    const float4* p4 = (const float4*)prev;
    float4* o4 = (float4*)out;
    float4* o24 = (float4*)out2;
    const size_t L4 = L / 4;

    float4 s1 = make_float4(0.f, 0.f, 0.f, 0.f), s2 = s1;
#pragma unroll 8
    for (int c = 0; c < 64; ++c) {
        float4 v = t4[base + (size_t)(cg * 64 + c) * L4];
        s1 = f4add(s1, v);
        s2 = f4add(s2, make_float4(v.x * v.x, v.y * v.y, v.z * v.z, v.w * v.w));
    }
    r1[cg][qx] = s1; r2[cg][qx] = s2;
    __syncthreads();
    float4 ts1 = f4add(f4add(r1[0][qx], r1[1][qx]), f4add(r1[2][qx], r1[3][qx]));
    float4 ts2 = f4add(f4add(r2[0][qx], r2[1][qx]), f4add(r2[2][qx], r2[3][qx]));
    float4 u = make_float4(ts1.x * (1.f / 256.f), ts1.y * (1.f / 256.f),
                           ts1.z * (1.f / 256.f), ts1.w * (1.f / 256.f));
    float4 rs = make_float4(
        rsqrtf(ts2.x * (1.f / 256.f) - u.x * u.x + 1e-5f),
        rsqrtf(ts2.y * (1.f / 256.f) - u.y * u.y + 1e-5f),
        rsqrtf(ts2.z * (1.f / 256.f) - u.z * u.z + 1e-5f),
        rsqrtf(ts2.w * (1.f / 256.f) - u.w * u.w + 1e-5f));

    float4 b1 = make_float4(0.f, 0.f, 0.f, 0.f), b2 = b1;
#pragma unroll 8
    for (int c = 0; c < 64; ++c) {
        int ch = cg * 64 + c;
        size_t idx = base + (size_t)ch * L4;
        float4 v = t4[idx];
        float4 p = p4[idx];
        float w = lnw[ch], bb = lnb[ch];
        float a = sigm(alpha_row[ch]);
        float4 xv;
        xv.x = fmaf(a, fmaf(w, (v.x - u.x) * rs.x, bb) - p.x, p.x);
        xv.y = fmaf(a, fmaf(w, (v.y - u.y) * rs.y, bb) - p.y, p.y);
        xv.z = fmaf(a, fmaf(w, (v.z - u.z) * rs.z, bb) - p.z, p.z);
        xv.w = fmaf(a, fmaf(w, (v.w - u.w) * rs.w, bb) - p.w, p.w);
        o4[idx] = xv;
        if (HAS2) {
            b1 = f4add(b1, xv);
            b2 = f4add(b2, make_float4(xv.x * xv.x, xv.y * xv.y, xv.z * xv.z, xv.w * xv.w));
        }
    }
    if (HAS2) {
        __syncthreads();
        r1[cg][qx] = b1; r2[cg][qx] = b2;
        __syncthreads();
        float4 q1 = f4add(f4add(r1[0][qx], r1[1][qx]), f4add(r1[2][qx], r1[3][qx]));
        float4 q2 = f4add(f4add(r2[0][qx], r2[1][qx]), f4add(r2[2][qx], r2[3][qx]));
        float4 u1 = make_float4(q1.x * (1.f / 256.f), q1.y * (1.f / 256.f),
                                q1.z * (1.f / 256.f), q1.w * (1.f / 256.f));
        float4 rs2 = make_float4(
            rsqrtf(q2.x * (1.f / 256.f) - u1.x * u1.x + 1e-5f),
            rsqrtf(q2.y * (1.f / 256.f) - u1.y * u1.y + 1e-5f),
            rsqrtf(q2.z * (1.f / 256.f) - u1.z * u1.z + 1e-5f),
            rsqrtf(q2.w * (1.f / 256.f) - u1.w * u1.w + 1e-5f));
#pragma unroll 8
        for (int c = 0; c < 64; ++c) {
            int ch = cg * 64 + c;
            size_t idx = base + (size_t)ch * L4;
            float4 xv = o4[idx];
            float w = lnw2[ch], bb = lnb2[ch];
            float4 nv;
            nv.x = fmaf(w, (xv.x - u1.x) * rs2.x, bb);
            nv.y = fmaf(w, (xv.y - u1.y) * rs2.y, bb);
            nv.z = fmaf(w, (xv.z - u1.z) * rs2.z, bb);
            nv.w = fmaf(w, (xv.w - u1.w) * rs2.w, bb);
            o24[idx] = nv;
        }
    }
}

// ---------------- small GEMM for Ld=64 ----------------
template<int OT>
__global__ __launch_bounds__(256) void gemm1x1_kernel(
    const float* __restrict__ W, const float* __restrict__ bias,
    const float* __restrict__ X, float* __restrict__ Y,
    int O, int C, int Ld)
{
    constexpr int PT = OT / 8;
    constexpr int KC = 32;
    __shared__ float Ws[OT * KC];
    int tid = threadIdx.x;
    int pxl = tid & 31;
    int og = tid >> 5;
    int b = (blockIdx.x * 64) / Ld;
    int l0 = (blockIdx.x * 64) % Ld;
    int ob = blockIdx.y * OT;
    const float* Xb = X + (b * C) * Ld + l0 + pxl * 2;

    float2 acc[PT];
#pragma unroll
    for (int i = 0; i < PT; ++i) acc[i] = make_float2(0.f, 0.f);

    for (int c0 = 0; c0 < C; c0 += KC) {
        __syncthreads();
#pragma unroll
        for (int e = tid; e < OT * KC; e += 256) {
            int ol = e >> 5, k = e & 31;
            Ws[e] = W[(ob + ol) * C + c0 + k];
        }
        __syncthreads();
#pragma unroll 4
        for (int k = 0; k < KC; ++k) {
            float2 xv = *reinterpret_cast<const float2*>(Xb + (c0 + k) * Ld);
#pragma unroll
            for (int i = 0; i < PT; ++i) {
                float wv = Ws[(og * PT + i) * KC + k];
                acc[i] = ffma2(make_float2(wv, wv), xv, acc[i]);
            }
        }
    }
#pragma unroll
    for (int i = 0; i < PT; ++i) {
        int o = ob + og * PT + i;
        float bv = bias ? bias[o] : 0.f;
        float2 r = make_float2(acc[i].x + bv, acc[i].y + bv);
        *reinterpret_cast<float2*>(Y + (b * O + o) * Ld + l0 + pxl * 2) = r;
    }
}

// ---------------- softmax over L (register-resident, float4) ----------------
__global__ __launch_bounds__(256) void softmax_ab_kernel(
    const float* __restrict__ bcdt2, float* __restrict__ AB)
{
    int bs = blockIdx.x;
    int b = bs >> 6, s = bs & 63;
    const float4* dt = (const float4*)(bcdt2 + (size_t)(b * 192 + 128 + s) * L);
    const float4* Bm = (const float4*)(bcdt2 + (size_t)(b * 192 + s) * L);
    float4* out = (float4*)(AB + (size_t)(b * 64 + s) * L);
    __shared__ float red[256];
    int tid = threadIdx.x;

    float4 v[4];
    float m = -1e30f;
#pragma unroll
    for (int i = 0; i < 4; ++i) {
        v[i] = dt[tid + i * 256];
        m = fmaxf(m, fmaxf(fmaxf(v[i].x, v[i].y), fmaxf(v[i].z, v[i].w)));
    }
    red[tid] = m; __syncthreads();
    for (int st = 128; st; st >>= 1) { if (tid < st) red[tid] = fmaxf(red[tid], red[tid + st]); __syncthreads(); }
    m = red[0];
    __syncthreads();

    float sm = 0.f;
#pragma unroll
    for (int i = 0; i < 4; ++i) {
        v[i].x = __expf(v[i].x - m);
        v[i].y = __expf(v[i].y - m);
        v[i].z = __expf(v[i].z - m);
        v[i].w = __expf(v[i].w - m);
        sm += v[i].x + v[i].y + v[i].z + v[i].w;
    }
    red[tid] = sm; __syncthreads();
    for (int st = 128; st; st >>= 1) { if (tid < st) red[tid] += red[tid + st]; __syncthreads(); }
    float inv = 1.f / red[0];

#pragma unroll
    for (int i = 0; i < 4; ++i) {
        float4 bm = Bm[tid + i * 256];
        out[tid + i * 256] = make_float4(v[i].x * inv * bm.x, v[i].y * inv * bm.y,
                                         v[i].z * inv * bm.z, v[i].w * inv * bm.w);
    }
}

// ---------------- h partials: k-major smem tiles, ffma2 inner ----------------
__global__ __launch_bounds__(256) void hgemm_kernel(
    const float* __restrict__ xn, const float* __restrict__ AB, float* __restrict__ hpart)
{
    int b = blockIdx.x, dtile = blockIdx.y, seg = blockIdx.z;
    int d0 = dtile * 64;
    int lb = seg * (L / NSEG);
    __shared__ float xs[16][66], as[16][66];
    int tid = threadIdx.x, tx = tid & 15, ty = tid >> 4;
    float2 acc[4][2];
#pragma unroll
    for (int i = 0; i < 4; ++i) {
        acc[i][0] = make_float2(0.f, 0.f);
        acc[i][1] = make_float2(0.f, 0.f);
    }

    const float* xp = xn + (b * DIM + d0) * L + lb;
    const float* ap = AB + (b * 64) * L + lb;

    for (int k0 = 0; k0 < L / NSEG; k0 += 16) {
        __syncthreads();
#pragma unroll
        for (int e = tid; e < 1024; e += 256) {
            int r = e >> 4, c = e & 15;
            xs[c][r] = xp[r * L + k0 + c];
            as[c][r] = ap[r * L + k0 + c];
        }
        __syncthreads();
#pragma unroll
        for (int k = 0; k < 16; ++k) {
            float2 bb0 = *(const float2*)&as[k][tx * 4];
            float2 bb1 = *(const float2*)&as[k][tx * 4 + 2];
#pragma unroll
            for (int i = 0; i < 4; ++i) {
                float xa = xs[k][ty * 4 + i];
                float2 xa2 = make_float2(xa, xa);
                acc[i][0] = ffma2(xa2, bb0, acc[i][0]);
                acc[i][1] = ffma2(xa2, bb1, acc[i][1]);
            }
        }
    }
    float* hp = hpart + seg * (BATCH * DIM * STATE);
#pragma unroll
    for (int i = 0; i < 4; ++i) {
        float* row = hp + (b * DIM + d0 + ty * 4 + i) * STATE + tx * 4;
        *(float2*)row = acc[i][0];
        *(float2*)(row + 2) = acc[i][1];
    }
}

__global__ __launch_bounds__(256) void hreduce_kernel(
    const float* __restrict__ hpart, float* __restrict__ h)
{
    int idx = blockIdx.x * 256 + threadIdx.x;
    float s = 0.f;
#pragma unroll
    for (int g = 0; g < NSEG; ++g) s += hpart[g * (BATCH * DIM * STATE) + idx];
    h[idx] = s;
}

__global__ __launch_bounds__(256) void gate_kernel(
    const float* __restrict__ hz, float* __restrict__ hg)
{
    int idx = blockIdx.x * 256 + threadIdx.x;
    int s = idx & 63;
    int c = (idx >> 6) & 255;
    int b = idx >> 14;
    float hp = hz[(b * 512 + c) * 64 + s];
    float z = hz[(b * 512 + 256 + c) * 64 + s];
    hg[idx] = hp * z * sigm(z);
}

// ---------------- y = ho @ Cm ; x2  (ffma2 over px pairs) ----------------
__global__ __launch_bounds__(256) void y_fuse_kernel(
    const float* __restrict__ ho, const float* __restrict__ bcdt2,
    const float* __restrict__ xn, const float* __restrict__ x1,
    const float* __restrict__ Dp, const float* __restrict__ alpha1,
    float* __restrict__ x2)
{
    __shared__ float hos[16][257];
    int tid = threadIdx.x;
    int pxp = tid & 31, dg = tid >> 5;
    int Pg = blockIdx.x * 64;
    int b = Pg >> 12, l0 = Pg & 4095;
    const float* hob = ho + b * DIM * STATE;
    const float* cm = bcdt2 + (b * 192 + 64) * L + l0 + pxp * 2;

    float2 acc[32];
#pragma unroll
    for (int j = 0; j < 32; ++j) acc[j] = make_float2(0.f, 0.f);

    for (int sc = 0; sc < 4; ++sc) {
        __syncthreads();
#pragma unroll
        for (int e = tid; e < 4096; e += 256) {
            int d = e >> 4, s = e & 15;
            hos[s][d] = hob[d * 64 + sc * 16 + s];
        }
        __syncthreads();
#pragma unroll
        for (int s = 0; s < 16; ++s) {
            float2 cmv = *(const float2*)(cm + (size_t)(sc * 16 + s) * L);
#pragma unroll
            for (int j = 0; j < 32; ++j) {
                float w = hos[s][dg * 32 + j];
                acc[j] = ffma2(make_float2(w, w), cmv, acc[j]);
            }
        }
    }
#pragma unroll
    for (int j = 0; j < 32; ++j) {
        int d = dg * 32 + j;
        size_t idx = (size_t)(b * DIM + d) * L + l0 + pxp * 2;
        float2 xnv = *(const float2*)(xn + idx);
        float2 p = *(const float2*)(x1 + idx);
        float dp = Dp[d];
        float a = sigm(alpha1[d]);
        float2 r;
        r.x = fmaf(a, (acc[j].x + xnv.x * dp) - p.x, p.x);
        r.y = fmaf(a, (acc[j].y + xnv.y * dp) - p.y, p.y);
        *(float2*)(x2 + idx) = r;
    }
}

__global__ __launch_bounds__(256) void copy_kernel(
    const float* __restrict__ src, float* __restrict__ dst)
{
    int idx = blockIdx.x * 256 + threadIdx.x;
    dst[idx] = src[idx];
}

// ---------------- host launcher ----------------
extern "C" void kernel_launch(void* const* d_in, const int* in_sizes, int n_in,
                              void* d_out, int out_size)
{
    const float* x        = (const float*)d_in[0];
    const float* alpha    = (const float*)d_in[1];
    const float* ln_w     = (const float*)d_in[2];
    const float* ln_b     = (const float*)d_in[3];
    const float* dw1_w    = (const float*)d_in[4];
    const float* dw1_ln_w = (const float*)d_in[5];
    const float* dw1_ln_b = (const float*)d_in[6];
    const float* dw2_w    = (const float*)d_in[7];
    const float* dw2_ln_w = (const float*)d_in[8];
    const float* dw2_ln_b = (const float*)d_in[9];
    const float* bcdt_w   = (const float*)d_in[10];
    const float* bcdt_b   = (const float*)d_in[11];
    const float* dwm_w    = (const float*)d_in[12];
    const float* dwm_b    = (const float*)d_in[13];
    const float* hz_w     = (const float*)d_in[14];
    const float* hz_b     = (const float*)d_in[15];
    const float* outp_w   = (const float*)d_in[16];
    const float* outp_b   = (const float*)d_in[17];
    const float* Dp       = (const float*)d_in[19];
    const float* fc1_w    = (const float*)d_in[20];
    const float* fc1_ln_w = (const float*)d_in[21];
    const float* fc1_ln_b = (const float*)d_in[22];
    const float* fc2_w    = (const float*)d_in[23];
    const float* fc2_ln_w = (const float*)d_in[24];
    const float* fc2_ln_b = (const float*)d_in[25];
    float* out = (float*)d_out;

    float *t0, *x1, *xn, *x2, *x3, *bc, *bc2, *ab, *hpart, *h, *hz, *hg, *ho, *f1t;
    __nv_bfloat16 *x3th, *x3tl, *xnth, *xntl, *f1th, *f1tl, *w1h, *w1l, *w2h, *w2l, *wbch, *wbcl;
    cudaGetSymbolAddress((void**)&t0, g_t0);
    cudaGetSymbolAddress((void**)&x1, g_x1);
    cudaGetSymbolAddress((void**)&xn, g_xn);
    cudaGetSymbolAddress((void**)&x2, g_x2);
    cudaGetSymbolAddress((void**)&x3, g_x3);
    cudaGetSymbolAddress((void**)&bc, g_bcdt);
    cudaGetSymbolAddress((void**)&bc2, g_bcdt2);
    cudaGetSymbolAddress((void**)&ab, g_AB);
    cudaGetSymbolAddress((void**)&hpart, g_hpart);
    cudaGetSymbolAddress((void**)&h, g_h);
    cudaGetSymbolAddress((void**)&hz, g_hz);
    cudaGetSymbolAddress((void**)&hg, g_hg);
    cudaGetSymbolAddress((void**)&ho, g_ho);
    cudaGetSymbolAddress((void**)&f1t, g_f1t);
    cudaGetSymbolAddress((void**)&x3th, g_x3th);
    cudaGetSymbolAddress((void**)&x3tl, g_x3tl);
    cudaGetSymbolAddress((void**)&xnth, g_xnth);
    cudaGetSymbolAddress((void**)&xntl, g_xntl);
    cudaGetSymbolAddress((void**)&f1th, g_f1th);
    cudaGetSymbolAddress((void**)&f1tl, g_f1tl);
    cudaGetSymbolAddress((void**)&w1h, g_w1h);
    cudaGetSymbolAddress((void**)&w1l, g_w1l);
    cudaGetSymbolAddress((void**)&w2h, g_w2h);
    cudaGetSymbolAddress((void**)&w2l, g_w2l);
    cudaGetSymbolAddress((void**)&wbch, g_wbch);
    cudaGetSymbolAddress((void**)&wbcl, g_wbcl);

    cudaFuncSetAttribute(gemm_mma_kernel<0>, cudaFuncAttributeMaxDynamicSharedMemorySize, GSMEM);
    cudaFuncSetAttribute(gemm_mma_kernel<1>, cudaFuncAttributeMaxDynamicSharedMemorySize, GSMEM);

    dim3 blk2(64, 4);

    // weight splits
    wsplit_kernel<<<HIDDEN * DIM / 256, 256>>>(fc1_w, w1h, w1l);
    wsplit_kernel<<<DIM * HIDDEN / 256, 256>>>(fc2_w, w2h, w2l);
    wsplit_pad_kernel<<<256 * DIM / 256, 256>>>(bcdt_w, wbch, wbcl);

    // sub-layer 1: dwconv + LN+gate (+2nd LN), then transpose+split xn
    dwconv8_kernel<<<BATCH * DIM * L / 8 / 256, 256>>>(x, dw1_w, nullptr, t0, DIM);
    ln_gate_kernel<true><<<NPIX / 256, blk2>>>(t0, x, dw1_ln_w, dw1_ln_b, alpha, x1,
                                               ln_w, ln_b, xn);
    convt_kernel<<<dim3(L / 32, DIM / 64, BATCH), 256>>>(xn, xnth, xntl, DIM);

    // HSMSSD mixer
    gemm_mma_kernel<0><<<dim3(NPIX / 64, 3), 128, GSMEM>>>(wbch, wbcl, xnth, xntl, bc, bcdt_b, 192, 256);
    dwconv8_kernel<<<BATCH * 192 * L / 8 / 256, 256>>>(bc, dwm_w, dwm_b, bc2, 192);
    softmax_ab_kernel<<<BATCH * 64, 256>>>(bc2, ab);
    hgemm_kernel<<<dim3(BATCH, 4, NSEG), 256>>>(xn, ab, hpart);
    hreduce_kernel<<<BATCH * DIM * STATE / 256, 256>>>(hpart, h);
    gemm1x1_kernel<128><<<dim3(BATCH, 4), 256>>>(hz_w, hz_b, h, hz, 512, 256, 64);
    gate_kernel<<<BATCH * DIM * STATE / 256, 256>>>(hz, hg);
    gemm1x1_kernel<128><<<dim3(BATCH, 2), 256>>>(outp_w, outp_b, hg, ho, 256, 256, 64);
    y_fuse_kernel<<<PIXBLK, 256>>>(ho, bc2, xn, x1, Dp, alpha + 256, x2);

    // sub-layer 3: dwconv + LN+gate, then transpose+split x3
    dwconv8_kernel<<<BATCH * DIM * L / 8 / 256, 256>>>(x2, dw2_w, nullptr, t0, DIM);
    ln_gate_kernel<false><<<NPIX / 256, blk2>>>(t0, x2, dw2_ln_w, dw2_ln_b, alpha + 512, x3,
                                                nullptr, nullptr, nullptr);
    convt_kernel<<<dim3(L / 32, DIM / 64, BATCH), 256>>>(x3, x3th, x3tl, DIM);

    // FFN
    gemm_mma_kernel<1><<<dim3(NPIX / 64, HIDDEN / 64), 128, GSMEM>>>(w1h, w1l, x3th, x3tl, f1t, nullptr, HIDDEN, 256);
    ln_silu_split_kernel<<<NPIX / 8, 256>>>(f1t, f1th, f1tl, fc1_ln_w, fc1_ln_b);
    gemm_mma_kernel<0><<<dim3(NPIX / 64, 4), 128, GSMEM>>>(w2h, w2l, f1th, f1tl, t0, nullptr, 256, 1024);
    ln_gate_kernel<false><<<NPIX / 256, blk2>>>(t0, x3, fc2_ln_w, fc2_ln_b, alpha + 768, out,
                                                nullptr, nullptr, nullptr);

    // second output: h
    if (out_size >= BATCH * DIM * L + BATCH * DIM * STATE)
        copy_kernel<<<BATCH * DIM * STATE / 256, 256>>>(h, out + BATCH * DIM * L);
}

// round 15
// speedup vs baseline: 1.8085x; 1.0044x over previous
#include <cuda_runtime.h>
#include <cuda_bf16.h>
#include <cstdint>
#include <math.h>

#define BATCH 16
#define DIM 256
#define STATE 64
#define HIDDEN 1024
#define L 4096
#define NPIX (BATCH*L)
#define PIXBLK (NPIX/64)
#define NSEG 8

// ---------------- scratch ----------------
__device__ float g_t0[BATCH*DIM*L];
__device__ float g_x1[BATCH*DIM*L];
__device__ float g_xn[BATCH*DIM*L];
__device__ float g_x2[BATCH*DIM*L];
__device__ float g_x3[BATCH*DIM*L];
__device__ float g_bcdt[BATCH*192*L];
__device__ float g_bcdt2[BATCH*192*L];
__device__ float g_AB[BATCH*STATE*L];
__device__ float g_hpart[NSEG*BATCH*DIM*STATE];
__device__ float g_h[BATCH*DIM*STATE];
__device__ float g_hz[BATCH*2*DIM*STATE];
__device__ float g_hg[BATCH*DIM*STATE];
__device__ float g_ho[BATCH*DIM*STATE];
__device__ float g_f1t[(size_t)BATCH*L*HIDDEN];
__device__ __nv_bfloat16 g_x3th[BATCH*L*DIM];
__device__ __nv_bfloat16 g_x3tl[BATCH*L*DIM];
__device__ __nv_bfloat16 g_xnth[BATCH*L*DIM];
__device__ __nv_bfloat16 g_xntl[BATCH*L*DIM];
__device__ __nv_bfloat16 g_f1th[(size_t)BATCH*L*HIDDEN];
__device__ __nv_bfloat16 g_f1tl[(size_t)BATCH*L*HIDDEN];
__device__ __nv_bfloat16 g_w1h[HIDDEN*DIM];
__device__ __nv_bfloat16 g_w1l[HIDDEN*DIM];
__device__ __nv_bfloat16 g_w2h[DIM*HIDDEN];
__device__ __nv_bfloat16 g_w2l[DIM*HIDDEN];
__device__ __nv_bfloat16 g_wbch[256*DIM];
__device__ __nv_bfloat16 g_wbcl[256*DIM];

// ---------------- helpers ----------------
__device__ __forceinline__ float2 ffma2(float2 a, float2 b, float2 c) {
    float2 d;
    asm("{\n\t.reg .b64 ra, rb, rc, rd;\n\t"
        "mov.b64 ra, {%2, %3};\n\tmov.b64 rb, {%4, %5};\n\tmov.b64 rc, {%6, %7};\n\t"
        "fma.rn.f32x2 rd, ra, rb, rc;\n\tmov.b64 {%0, %1}, rd;\n\t}"
        : "=f"(d.x), "=f"(d.y)
        : "f"(a.x), "f"(a.y), "f"(b.x), "f"(b.y), "f"(c.x), "f"(c.y));
    return d;
}
__device__ __forceinline__ float sigm(float v) { return 1.f / (1.f + __expf(-v)); }
__device__ __forceinline__ float4 f4add(float4 a, float4 b) {
    return make_float4(a.x + b.x, a.y + b.y, a.z + b.z, a.w + b.w);
}

#define CPA16(dst, src) asm volatile("cp.async.cg.shared.global [%0], [%1], 16;" :: "r"(dst), "l"(src))
#define SWZ(o) ((o) ^ (((o) >> 3) & 0x70u))

__device__ __forceinline__ uint32_t s2u(const void* p) {
    uint32_t a;
    asm("{ .reg .u64 t; cvta.to.shared.u64 t, %1; cvt.u32.u64 %0, t; }" : "=r"(a) : "l"(p));
    return a;
}

#define LDSM4(r, a) \
    asm volatile("ldmatrix.sync.aligned.m8n8.x4.shared.b16 {%0,%1,%2,%3}, [%4];" \
        : "=r"((r)[0]), "=r"((r)[1]), "=r"((r)[2]), "=r"((r)[3]) : "r"(a))

#define MMA16816(d, a, b) \
    asm volatile("mma.sync.aligned.m16n8k16.row.col.f32.bf16.bf16.f32 " \
        "{%0,%1,%2,%3},{%4,%5,%6,%7},{%8,%9},{%0,%1,%2,%3};" \
        : "+f"((d)[0]), "+f"((d)[1]), "+f"((d)[2]), "+f"((d)[3]) \
        : "r"((a)[0]), "r"((a)[1]), "r"((a)[2]), "r"((a)[3]), "r"((b)[0]), "r"((b)[1]))

// ---------------- tensor-core GEMM (mma.sync bf16 hi/lo), tile M64 x N64, 3 CTA/SM ----------
#define GSMEM 65536
template<int TRANS>
__global__ __launch_bounds__(128) void gemm_mma_kernel(
    const __nv_bfloat16* __restrict__ Wh, const __nv_bfloat16* __restrict__ Wl,
    const __nv_bfloat16* __restrict__ Xh, const __nv_bfloat16* __restrict__ Xl,
    float* __restrict__ Y, const float* __restrict__ bias, int O, int C)
{
    extern __shared__ char dsm[];
    uint32_t sb = s2u(dsm);
    int tid = threadIdx.x, warp = tid >> 5, lane = tid & 31;
    int wm = warp >> 1, wn = warp & 1;
    int bb = blockIdx.x >> 6;
    int l0 = (blockIdx.x & 63) << 6;
    int m0 = blockIdx.y << 6;
    int nchunk = C >> 6;
    size_t rowb = (size_t)bb * 4096 + l0;

    float acc[2][4][4];
#pragma unroll
    for (int i = 0; i < 2; ++i)
#pragma unroll
        for (int j = 0; j < 4; ++j)
#pragma unroll
            for (int q = 0; q < 4; ++q) acc[i][j][q] = 0.f;

    auto issue = [&](int cc, int buf) {
        int c0 = cc << 6;
        uint32_t base = sb + (uint32_t)buf * 32768u;
#pragma unroll
        for (int i = 0; i < 4; ++i) {
            int e = tid + i * 128;
            int row = e >> 3, c16 = e & 7;
            uint32_t sw = SWZ((uint32_t)(row * 128 + c16 * 16));
            CPA16(base + sw,          Wh + (size_t)(m0 + row) * C + c0 + c16 * 8);
            CPA16(base + 8192u + sw,  Wl + (size_t)(m0 + row) * C + c0 + c16 * 8);
        }
#pragma unroll
        for (int i = 0; i < 4; ++i) {
            int e = tid + i * 128;
            int row = e >> 3, c16 = e & 7;
            uint32_t sw = SWZ((uint32_t)(row * 128 + c16 * 16));
            CPA16(base + 16384u + sw,  Xh + (rowb + row) * (size_t)C + c0 + c16 * 8);
            CPA16(base + 24576u + sw,  Xl + (rowb + row) * (size_t)C + c0 + c16 * 8);
        }
        asm volatile("cp.async.commit_group;");
    };

    issue(0, 0);
    for (int cc = 0; cc < nchunk; ++cc) {
        int buf = cc & 1;
        if (cc + 1 < nchunk) {
            issue(cc + 1, buf ^ 1);
            asm volatile("cp.async.wait_group 1;");
        } else {
            asm volatile("cp.async.wait_group 0;");
        }
        __syncthreads();
        uint32_t base = sb + (uint32_t)buf * 32768u;

        int lr = (lane & 7) + ((lane >> 3) & 1) * 8;
        int kb = (lane >> 4) * 8;
#pragma unroll
        for (int kt = 0; kt < 4; ++kt) {
            uint32_t ah[2][4], al[2][4];
#pragma unroll
            for (int mt = 0; mt < 2; ++mt) {
                int row = wm * 32 + mt * 16 + lr;
                uint32_t a = base + SWZ((uint32_t)(row * 128 + (kt * 16 + kb) * 2));
                LDSM4(ah[mt], a);
                LDSM4(al[mt], a + 8192u);
            }
            uint32_t bh[4][2], bl[4][2];
#pragma unroll
            for (int np = 0; np < 2; ++np) {
                int row = wn * 32 + np * 16 + lr;
                uint32_t a = base + 16384u + SWZ((uint32_t)(row * 128 + (kt * 16 + kb) * 2));
                uint32_t r[4], rl[4];
                LDSM4(r, a);
                LDSM4(rl, a + 8192u);
                bh[np * 2][0] = r[0]; bh[np * 2][1] = r[2];
                bh[np * 2 + 1][0] = r[1]; bh[np * 2 + 1][1] = r[3];
                bl[np * 2][0] = rl[0]; bl[np * 2][1] = rl[2];
                bl[np * 2 + 1][0] = rl[1]; bl[np * 2 + 1][1] = rl[3];
            }
#pragma unroll
            for (int mt = 0; mt < 2; ++mt)
#pragma unroll
                for (int nt = 0; nt < 4; ++nt) {
                    MMA16816(acc[mt][nt], ah[mt], bh[nt]);
                    MMA16816(acc[mt][nt], ah[mt], bl[nt]);
                    MMA16816(acc[mt][nt], al[mt], bh[nt]);
                }
        }
        __syncthreads();
    }

    int mrow = (lane >> 2);
    int ncol = (lane & 3) * 2;
    if (TRANS == 0) {
#pragma unroll
        for (int mt = 0; mt < 2; ++mt) {
            int o = m0 + wm * 32 + mt * 16 + mrow;
            float bv0 = (o < O && bias) ? bias[o] : 0.f;
            float bv1 = (o + 8 < O && bias) ? bias[o + 8] : 0.f;
            float* yp0 = Y + ((size_t)bb * O + o) * 4096 + l0 + wn * 32;
            float* yp1 = Y + ((size_t)bb * O + o + 8) * 4096 + l0 + wn * 32;
#pragma unroll
            for (int nt = 0; nt < 4; ++nt) {
                if (o < O)
                    *(float2*)(yp0 + nt * 8 + ncol) = make_float2(acc[mt][nt][0] + bv0, acc[mt][nt][1] + bv0);
                if (o + 8 < O)
                    *(float2*)(yp1 + nt * 8 + ncol) = make_float2(acc[mt][nt][2] + bv1, acc[mt][nt][3] + bv1);
            }
        }
    } else {
        float* st = (float*)dsm;
#pragma unroll
        for (int mt = 0; mt < 2; ++mt) {
            int ob = wm * 32 + mt * 16 + mrow;
#pragma unroll
            for (int nt = 0; nt < 4; ++nt) {
                int pxb = wn * 32 + nt * 8 + ncol;
                st[pxb * 68 + ob] = acc[mt][nt][0];
                st[(pxb + 1) * 68 + ob] = acc[mt][nt][1];
                st[pxb * 68 + ob + 8] = acc[mt][nt][2];
                st[(pxb + 1) * 68 + ob + 8] = acc[mt][nt][3];
            }
        }
        __syncthreads();
        int px = tid >> 1, hf = (tid & 1) * 32;
        float* dst = Y + (rowb + px) * (size_t)O + m0 + hf;
        const float* src = st + px * 68 + hf;
#pragma unroll
        for (int j = 0; j < 8; ++j)
            *(float4*)(dst + j * 4) = *(const float4*)(src + j * 4);
    }
}

// ---------------- transpose + bf16 hi/lo split ----------------
__global__ __launch_bounds__(256) void convt_kernel(
    const float* __restrict__ in, __nv_bfloat16* __restrict__ oh,
    __nv_bfloat16* __restrict__ ol, int C)
{
    __shared__ float s[64][33];
    int tid = threadIdx.x;
    int lx = tid & 31, cy = tid >> 5;
    int l0 = blockIdx.x * 32;
    int c0 = blockIdx.y * 64;
    int b = blockIdx.z;
    const float* ip = in + ((size_t)b * C + c0) * L + l0;
#pragma unroll
    for (int i = 0; i < 8; ++i)
        s[cy + i * 8][lx] = ip[(size_t)(cy + i * 8) * L + lx];
    __syncthreads();
    int cp = tid & 31, ly = tid >> 5;
#pragma unroll
    for (int i = 0; i < 4; ++i) {
        int lrow = ly + i * 8;
        float f0 = s[2 * cp][lrow], f1 = s[2 * cp + 1][lrow];
        __nv_bfloat16 h0 = __float2bfloat16(f0);
        __nv_bfloat16 h1 = __float2bfloat16(f1);
        __nv_bfloat16 e0 = __float2bfloat16(f0 - __bfloat162float(h0));
        __nv_bfloat16 e1 = __float2bfloat16(f1 - __bfloat162float(h1));
        uint32_t hp = (uint32_t)__bfloat16_as_ushort(h0) | ((uint32_t)__bfloat16_as_ushort(h1) << 16);
        uint32_t lp = (uint32_t)__bfloat16_as_ushort(e0) | ((uint32_t)__bfloat16_as_ushort(e1) << 16);
        size_t o32 = (((size_t)b * L + l0 + lrow) * C + c0) / 2 + cp;
        ((uint32_t*)oh)[o32] = hp;
        ((uint32_t*)ol)[o32] = lp;
    }
}

// ---------------- fused LN(1024) + SiLU + bf16 hi/lo split ----------------
__global__ __launch_bounds__(256) void ln_silu_split_kernel(
    const float* __restrict__ f1t, __nv_bfloat16* __restrict__ oh, __nv_bfloat16* __restrict__ ol,
    const float* __restrict__ lnw, const float* __restrict__ lnb)
{
    int warp = threadIdx.x >> 5, lane = threadIdx.x & 31;
    size_t px = (size_t)blockIdx.x * 8 + warp;
    const float4* row = (const float4*)(f1t + px * 1024);
    const float4* w4 = (const float4*)lnw;
    const float4* b4 = (const float4*)lnb;

    float4 v[8];
    float s1 = 0.f, s2 = 0.f;
#pragma unroll
    for (int i = 0; i < 8; ++i) {
        v[i] = row[lane + i * 32];
        s1 += v[i].x + v[i].y + v[i].z + v[i].w;
        s2 += v[i].x * v[i].x + v[i].y * v[i].y + v[i].z * v[i].z + v[i].w * v[i].w;
    }
#pragma unroll
    for (int st = 16; st; st >>= 1) {
        s1 += __shfl_xor_sync(0xFFFFFFFF, s1, st);
        s2 += __shfl_xor_sync(0xFFFFFFFF, s2, st);
    }
    float u = s1 * (1.f / 1024.f);
    float rs = rsqrtf(s2 * (1.f / 1024.f) - u * u + 1e-5f);

    uint2* oh2 = (uint2*)(oh + px * 1024);
    uint2* ol2 = (uint2*)(ol + px * 1024);
#pragma unroll
    for (int i = 0; i < 8; ++i) {
        int c4 = lane + i * 32;
        float4 wv = w4[c4], bv = b4[c4];
        float g[4];
        g[0] = wv.x * (v[i].x - u) * rs + bv.x;
        g[1] = wv.y * (v[i].y - u) * rs + bv.y;
        g[2] = wv.z * (v[i].z - u) * rs + bv.z;
        g[3] = wv.w * (v[i].w - u) * rs + bv.w;
#pragma unroll
        for (int j = 0; j < 4; ++j) g[j] = g[j] * sigm(g[j]);
        __nv_bfloat16 h0 = __float2bfloat16(g[0]), h1 = __float2bfloat16(g[1]);
        __nv_bfloat16 h2 = __float2bfloat16(g[2]), h3 = __float2bfloat16(g[3]);
        uint2 hp, lp;
        hp.x = (uint32_t)__bfloat16_as_ushort(h0) | ((uint32_t)__bfloat16_as_ushort(h1) << 16);
        hp.y = (uint32_t)__bfloat16_as_ushort(h2) | ((uint32_t)__bfloat16_as_ushort(h3) << 16);
        __nv_bfloat16 e0 = __float2bfloat16(g[0] - __bfloat162float(h0));
        __nv_bfloat16 e1 = __float2bfloat16(g[1] - __bfloat162float(h1));
        __nv_bfloat16 e2 = __float2bfloat16(g[2] - __bfloat162float(h2));
        __nv_bfloat16 e3 = __float2bfloat16(g[3] - __bfloat162float(h3));
        lp.x = (uint32_t)__bfloat16_as_ushort(e0) | ((uint32_t)__bfloat16_as_ushort(e1) << 16);
        lp.y = (uint32_t)__bfloat16_as_ushort(e2) | ((uint32_t)__bfloat16_as_ushort(e3) << 16);
        oh2[c4] = hp;
        ol2[c4] = lp;
    }
}

__global__ __launch_bounds__(256) void wsplit_kernel(
    const float* __restrict__ w, __nv_bfloat16* __restrict__ wh, __nv_bfloat16* __restrict__ wl)
{
    int i = blockIdx.x * 256 + threadIdx.x;
    float f = w[i];
    __nv_bfloat16 h = __float2bfloat16(f);
    wh[i] = h;
    wl[i] = __float2bfloat16(f - __bfloat162float(h));
}

__global__ __launch_bounds__(256) void wsplit_pad_kernel(
    const float* __restrict__ w, __nv_bfloat16* __restrict__ wh, __nv_bfloat16* __restrict__ wl)
{
    int i = blockIdx.x * 256 + threadIdx.x;
    int row = i >> 8;
    float f = (row < 192) ? w[i] : 0.f;
    __nv_bfloat16 h = __float2bfloat16(f);
    wh[i] = h;
    wl[i] = __float2bfloat16(f - __bfloat162float(h));
}

// ---------------- depthwise 3x3 conv: 2 output rows x 8 px per thread ----------------
__global__ __launch_bounds__(256) void dwconv16_kernel(
    const float* __restrict__ in, const float* __restrict__ w,
    const float* __restrict__ bias, float* __restrict__ out, int C)
{
    int t = blockIdx.x * 256 + threadIdx.x;
    int x0 = (t & 7) * 8;
    int r = t >> 3;
    int hh = (r & 31) * 2;
    int bc = r >> 5;
    int c = bc - (bc / C) * C;
    const float* wp = w + c * 9;
    float wr[9];
#pragma unroll
    for (int i = 0; i < 9; ++i) wr[i] = wp[i];
    const float* ip = in + (long)bc * 4096;
    float bv = bias ? bias[c] : 0.f;
    float acc0[8], acc1[8];
#pragma unroll
    for (int j = 0; j < 8; ++j) { acc0[j] = bv; acc1[j] = bv; }
#pragma unroll
    for (int ky = 0; ky < 4; ++ky) {
        int y = hh + ky - 1;
        if ((unsigned)y < 64u) {
            const float* rp = ip + y * 64 + x0;
            float4 a = *(const float4*)rp;
            float4 b4 = *(const float4*)(rp + 4);
            float v[10];
            v[0] = (x0 > 0) ? rp[-1] : 0.f;
            v[1] = a.x; v[2] = a.y; v[3] = a.z; v[4] = a.w;
            v[5] = b4.x; v[6] = b4.y; v[7] = b4.z; v[8] = b4.w;
            v[9] = (x0 < 56) ? rp[8] : 0.f;
            if (ky < 3) {
                float k0 = wr[ky * 3], k1 = wr[ky * 3 + 1], k2 = wr[ky * 3 + 2];
#pragma unroll
                for (int j = 0; j < 8; ++j)
                    acc0[j] += k0 * v[j] + k1 * v[j + 1] + k2 * v[j + 2];
            }
            if (ky >= 1) {
                float k0 = wr[(ky - 1) * 3], k1 = wr[(ky - 1) * 3 + 1], k2 = wr[(ky - 1) * 3 + 2];
#pragma unroll
                for (int j = 0; j < 8; ++j)
                    acc1[j] += k0 * v[j] + k1 * v[j + 1] + k2 * v[j + 2];
            }
        }
    }
    float* op = out + (long)bc * 4096 + hh * 64 + x0;
    *(float4*)op = make_float4(acc0[0], acc0[1], acc0[2], acc0[3]);
    *(float4*)(op + 4) = make_float4(acc0[4], acc0[5], acc0[6], acc0[7]);
    *(float4*)(op + 64) = make_float4(acc1[0], acc1[1], acc1[2], acc1[3]);
    *(float4*)(op + 68) = make_float4(acc1[4], acc1[5], acc1[6], acc1[7]);
}

// ---------------- fused channel-LN + gated residual (+optional 2nd LN), float4 over px -------
template<bool HAS2>
__global__ __launch_bounds__(256) void ln_gate_kernel(
    const float* __restrict__ t, const float* __restrict__ prev,
    const float* __restrict__ lnw, const float* __restrict__ lnb,
    const float* __restrict__ alpha_row, float* __restrict__ out,
    const float* __restrict__ lnw2, const float* __restrict__ lnb2,
    float* __restrict__ out2)
{
    __shared__ float4 r1[4][64], r2[4][64];
    int qx = threadIdx.x, cg = threadIdx.y;
    int Pg = blockIdx.x * 256;
    int b = Pg >> 12, l0 = Pg & 4095;
    size_t base = ((size_t)(b * DIM) * L + l0 + qx * 4) >> 2;

    const float4* t4 = (const float4*)t;
    const float4* p4 = (const float4*)prev;
    float4* o4 = (float4*)out;
    float4* o24 = (float4*)out2;
    const size_t L4 = L / 4;

    float4 s1 = make_float4(0.f, 0.f, 0.f, 0.f), s2 = s1;
#pragma unroll 8
    for (int c = 0; c < 64; ++c) {
        float4 v = t4[base + (size_t)(cg * 64 + c) * L4];
        s1 = f4add(s1, v);
        s2 = f4add(s2, make_float4(v.x * v.x, v.y * v.y, v.z * v.z, v.w * v.w));
    }
    r1[cg][qx] = s1; r2[cg][qx] = s2;
    __syncthreads();
    float4 ts1 = f4add(f4add(r1[0][qx], r1[1][qx]), f4add(r1[2][qx], r1[3][qx]));
    float4 ts2 = f4add(f4add(r2[0][qx], r2[1][qx]), f4add(r2[2][qx], r2[3][qx]));
    float4 u = make_float4(ts1.x * (1.f / 256.f), ts1.y * (1.f / 256.f),
                           ts1.z * (1.f / 256.f), ts1.w * (1.f / 256.f));
    float4 rs = make_float4(
        rsqrtf(ts2.x * (1.f / 256.f) - u.x * u.x + 1e-5f),
        rsqrtf(ts2.y * (1.f / 256.f) - u.y * u.y + 1e-5f),
        rsqrtf(ts2.z * (1.f / 256.f) - u.z * u.z + 1e-5f),
        rsqrtf(ts2.w * (1.f / 256.f) - u.w * u.w + 1e-5f));

    float4 b1 = make_float4(0.f, 0.f, 0.f, 0.f), b2 = b1;
#pragma unroll 8
    for (int c = 0; c < 64; ++c) {
        int ch = cg * 64 + c;
        size_t idx = base + (size_t)ch * L4;
        float4 v = t4[idx];
        float4 p = p4[idx];
        float w = lnw[ch], bb = lnb[ch];
        float a = sigm(alpha_row[ch]);
        float4 xv;
        xv.x = fmaf(a, fmaf(w, (v.x - u.x) * rs.x, bb) - p.x, p.x);
        xv.y = fmaf(a, fmaf(w, (v.y - u.y) * rs.y, bb) - p.y, p.y);
        xv.z = fmaf(a, fmaf(w, (v.z - u.z) * rs.z, bb) - p.z, p.z);
        xv.w = fmaf(a, fmaf(w, (v.w - u.w) * rs.w, bb) - p.w, p.w);
        o4[idx] = xv;
        if (HAS2) {
            b1 = f4add(b1, xv);
            b2 = f4add(b2, make_float4(xv.x * xv.x, xv.y * xv.y, xv.z * xv.z, xv.w * xv.w));
        }
    }
    if (HAS2) {
        __syncthreads();
        r1[cg][qx] = b1; r2[cg][qx] = b2;
        __syncthreads();
        float4 q1 = f4add(f4add(r1[0][qx], r1[1][qx]), f4add(r1[2][qx], r1[3][qx]));
        float4 q2 = f4add(f4add(r2[0][qx], r2[1][qx]), f4add(r2[2][qx], r2[3][qx]));
        float4 u1 = make_float4(q1.x * (1.f / 256.f), q1.y * (1.f / 256.f),
                                q1.z * (1.f / 256.f), q1.w * (1.f / 256.f));
        float4 rs2 = make_float4(
            rsqrtf(q2.x * (1.f / 256.f) - u1.x * u1.x + 1e-5f),
            rsqrtf(q2.y * (1.f / 256.f) - u1.y * u1.y + 1e-5f),
            rsqrtf(q2.z * (1.f / 256.f) - u1.z * u1.z + 1e-5f),
            rsqrtf(q2.w * (1.f / 256.f) - u1.w * u1.w + 1e-5f));
#pragma unroll 8
        for (int c = 0; c < 64; ++c) {
            int ch = cg * 64 + c;
            size_t idx = base + (size_t)ch * L4;
            float4 xv = o4[idx];
            float w = lnw2[ch], bb = lnb2[ch];
            float4 nv;
            nv.x = fmaf(w, (xv.x - u1.x) * rs2.x, bb);
            nv.y = fmaf(w, (xv.y - u1.y) * rs2.y, bb);
            nv.z = fmaf(w, (xv.z - u1.z) * rs2.z, bb);
            nv.w = fmaf(w, (xv.w - u1.w) * rs2.w, bb);
            o24[idx] = nv;
        }
    }
}

// ---------------- small GEMM for Ld=64 ----------------
template<int OT>
__global__ __launch_bounds__(256) void gemm1x1_kernel(
    const float* __restrict__ W, const float* __restrict__ bias,
    const float* __restrict__ X, float* __restrict__ Y,
    int O, int C, int Ld)
{
    constexpr int PT = OT / 8;
    constexpr int KC = 32;
    __shared__ float Ws[OT * KC];
    int tid = threadIdx.x;
    int pxl = tid & 31;
    int og = tid >> 5;
    int b = (blockIdx.x * 64) / Ld;
    int l0 = (blockIdx.x * 64) % Ld;
    int ob = blockIdx.y * OT;
    const float* Xb = X + (b * C) * Ld + l0 + pxl * 2;

    float2 acc[PT];
#pragma unroll
    for (int i = 0; i < PT; ++i) acc[i] = make_float2(0.f, 0.f);

    for (int c0 = 0; c0 < C; c0 += KC) {
        __syncthreads();
#pragma unroll
        for (int e = tid; e < OT * KC; e += 256) {
            int ol = e >> 5, k = e & 31;
            Ws[e] = W[(ob + ol) * C + c0 + k];
        }
        __syncthreads();
#pragma unroll 4
        for (int k = 0; k < KC; ++k) {
            float2 xv = *reinterpret_cast<const float2*>(Xb + (c0 + k) * Ld);
#pragma unroll
            for (int i = 0; i < PT; ++i) {
                float wv = Ws[(og * PT + i) * KC + k];
                acc[i] = ffma2(make_float2(wv, wv), xv, acc[i]);
            }
        }
    }
#pragma unroll
    for (int i = 0; i < PT; ++i) {
        int o = ob + og * PT + i;
        float bv = bias ? bias[o] : 0.f;
        float2 r = make_float2(acc[i].x + bv, acc[i].y + bv);
        *reinterpret_cast<float2*>(Y + (b * O + o) * Ld + l0 + pxl * 2) = r;
    }
}

// ---------------- softmax over L (register-resident, float4) ----------------
__global__ __launch_bounds__(256) void softmax_ab_kernel(
    const float* __restrict__ bcdt2, float* __restrict__ AB)
{
    int bs = blockIdx.x;
    int b = bs >> 6, s = bs & 63;
    const float4* dt = (const float4*)(bcdt2 + (size_t)(b * 192 + 128 + s) * L);
    const float4* Bm = (const float4*)(bcdt2 + (size_t)(b * 192 + s) * L);
    float4* out = (float4*)(AB + (size_t)(b * 64 + s) * L);
    __shared__ float red[256];
    int tid = threadIdx.x;

    float4 v[4];
    float m = -1e30f;
#pragma unroll
    for (int i = 0; i < 4; ++i) {
        v[i] = dt[tid + i * 256];
        m = fmaxf(m, fmaxf(fmaxf(v[i].x, v[i].y), fmaxf(v[i].z, v[i].w)));
    }
    red[tid] = m; __syncthreads();
    for (int st = 128; st; st >>= 1) { if (tid < st) red[tid] = fmaxf(red[tid], red[tid + st]); __syncthreads(); }
    m = red[0];
    __syncthreads();

    float sm = 0.f;
#pragma unroll
    for (int i = 0; i < 4; ++i) {
        v[i].x = __expf(v[i].x - m);
        v[i].y = __expf(v[i].y - m);
        v[i].z = __expf(v[i].z - m);
        v[i].w = __expf(v[i].w - m);
        sm += v[i].x + v[i].y + v[i].z + v[i].w;
    }
    red[tid] = sm; __syncthreads();
    for (int st = 128; st; st >>= 1) { if (tid < st) red[tid] += red[tid + st]; __syncthreads(); }
    float inv = 1.f / red[0];

#pragma unroll
    for (int i = 0; i < 4; ++i) {
        float4 bm = Bm[tid + i * 256];
        out[tid + i * 256] = make_float4(v[i].x * inv * bm.x, v[i].y * inv * bm.y,
                                         v[i].z * inv * bm.z, v[i].w * inv * bm.w);
    }
}

// ---------------- h partials: k-major smem tiles, ffma2 inner ----------------
__global__ __launch_bounds__(256) void hgemm_kernel(
    const float* __restrict__ xn, const float* __restrict__ AB, float* __restrict__ hpart)
{
    int b = blockIdx.x, dtile = blockIdx.y, seg = blockIdx.z;
    int d0 = dtile * 64;
    int lb = seg * (L / NSEG);
    __shared__ float xs[16][66], as[16][66];
    int tid = threadIdx.x, tx = tid & 15, ty = tid >> 4;
    float2 acc[4][2];
#pragma unroll
    for (int i = 0; i < 4; ++i) {
        acc[i][0] = make_float2(0.f, 0.f);
        acc[i][1] = make_float2(0.f, 0.f);
    }

    const float* xp = xn + (b * DIM + d0) * L + lb;
    const float* ap = AB + (b * 64) * L + lb;

    for (int k0 = 0; k0 < L / NSEG; k0 += 16) {
        __syncthreads();
#pragma unroll
        for (int e = tid; e < 1024; e += 256) {
            int r = e >> 4, c = e & 15;
            xs[c][r] = xp[r * L + k0 + c];
            as[c][r] = ap[r * L + k0 + c];
        }
        __syncthreads();
#pragma unroll
        for (int k = 0; k < 16; ++k) {
            float2 bb0 = *(const float2*)&as[k][tx * 4];
            float2 bb1 = *(const float2*)&as[k][tx * 4 + 2];
#pragma unroll
            for (int i = 0; i < 4; ++i) {
                float xa = xs[k][ty * 4 + i];
                float2 xa2 = make_float2(xa, xa);
                acc[i][0] = ffma2(xa2, bb0, acc[i][0]);
                acc[i][1] = ffma2(xa2, bb1, acc[i][1]);
            }
        }
    }
    float* hp = hpart + seg * (BATCH * DIM * STATE);
#pragma unroll
    for (int i = 0; i < 4; ++i) {
        float* row = hp + (b * DIM + d0 + ty * 4 + i) * STATE + tx * 4;
        *(float2*)row = acc[i][0];
        *(float2*)(row + 2) = acc[i][1];
    }
}

__global__ __launch_bounds__(256) void hreduce_kernel(
    const float* __restrict__ hpart, float* __restrict__ h)
{
    int idx = blockIdx.x * 256 + threadIdx.x;
    float s = 0.f;
#pragma unroll
    for (int g = 0; g < NSEG; ++g) s += hpart[g * (BATCH * DIM * STATE) + idx];
    h[idx] = s;
}

__global__ __launch_bounds__(256) void gate_kernel(
    const float* __restrict__ hz, float* __restrict__ hg)
{
    int idx = blockIdx.x * 256 + threadIdx.x;
    int s = idx & 63;
    int c = (idx >> 6) & 255;
    int b = idx >> 14;
    float hp = hz[(b * 512 + c) * 64 + s];
    float z = hz[(b * 512 + 256 + c) * 64 + s];
    hg[idx] = hp * z * sigm(z);
}

// ---------------- y = ho @ Cm ; x2  (ffma2 over px pairs) ----------------
__global__ __launch_bounds__(256) void y_fuse_kernel(
    const float* __restrict__ ho, const float* __restrict__ bcdt2,
    const float* __restrict__ xn, const float* __restrict__ x1,
    const float* __restrict__ Dp, const float* __restrict__ alpha1,
    float* __restrict__ x2)
{
    __shared__ float hos[16][257];
    int tid = threadIdx.x;
    int pxp = tid & 31, dg = tid >> 5;
    int Pg = blockIdx.x * 64;
    int b = Pg >> 12, l0 = Pg & 4095;
    const float* hob = ho + b * DIM * STATE;
    const float* cm = bcdt2 + (b * 192 + 64) * L + l0 + pxp * 2;

    float2 acc[32];
#pragma unroll
    for (int j = 0; j < 32; ++j) acc[j] = make_float2(0.f, 0.f);

    for (int sc = 0; sc < 4; ++sc) {
        __syncthreads();
#pragma unroll
        for (int e = tid; e < 4096; e += 256) {
            int d = e >> 4, s = e & 15;
            hos[s][d] = hob[d * 64 + sc * 16 + s];
        }
        __syncthreads();
#pragma unroll
        for (int s = 0; s < 16; ++s) {
            float2 cmv = *(const float2*)(cm + (size_t)(sc * 16 + s) * L);
#pragma unroll
            for (int j = 0; j < 32; ++j) {
                float w = hos[s][dg * 32 + j];
                acc[j] = ffma2(make_float2(w, w), cmv, acc[j]);
            }
        }
    }
#pragma unroll
    for (int j = 0; j < 32; ++j) {
        int d = dg * 32 + j;
        size_t idx = (size_t)(b * DIM + d) * L + l0 + pxp * 2;
        float2 xnv = *(const float2*)(xn + idx);
        float2 p = *(const float2*)(x1 + idx);
        float dp = Dp[d];
        float a = sigm(alpha1[d]);
        float2 r;
        r.x = fmaf(a, (acc[j].x + xnv.x * dp) - p.x, p.x);
        r.y = fmaf(a, (acc[j].y + xnv.y * dp) - p.y, p.y);
        *(float2*)(x2 + idx) = r;
    }
}

__global__ __launch_bounds__(256) void copy_kernel(
    const float* __restrict__ src, float* __restrict__ dst)
{
    int idx = blockIdx.x * 256 + threadIdx.x;
    dst[idx] = src[idx];
}

// ---------------- host launcher ----------------
extern "C" void kernel_launch(void* const* d_in, const int* in_sizes, int n_in,
                              void* d_out, int out_size)
{
    const float* x        = (const float*)d_in[0];
    const float* alpha    = (const float*)d_in[1];
    const float* ln_w     = (const float*)d_in[2];
    const float* ln_b     = (const float*)d_in[3];
    const float* dw1_w    = (const float*)d_in[4];
    const float* dw1_ln_w = (const float*)d_in[5];
    const float* dw1_ln_b = (const float*)d_in[6];
    const float* dw2_w    = (const float*)d_in[7];
    const float* dw2_ln_w = (const float*)d_in[8];
    const float* dw2_ln_b = (const float*)d_in[9];
    const float* bcdt_w   = (const float*)d_in[10];
    const float* bcdt_b   = (const float*)d_in[11];
    const float* dwm_w    = (const float*)d_in[12];
    const float* dwm_b    = (const float*)d_in[13];
    const float* hz_w     = (const float*)d_in[14];
    const float* hz_b     = (const float*)d_in[15];
    const float* outp_w   = (const float*)d_in[16];
    const float* outp_b   = (const float*)d_in[17];
    const float* Dp       = (const float*)d_in[19];
    const float* fc1_w    = (const float*)d_in[20];
    const float* fc1_ln_w = (const float*)d_in[21];
    const float* fc1_ln_b = (const float*)d_in[22];
    const float* fc2_w    = (const float*)d_in[23];
    const float* fc2_ln_w = (const float*)d_in[24];
    const float* fc2_ln_b = (const float*)d_in[25];
    float* out = (float*)d_out;

    float *t0, *x1, *xn, *x2, *x3, *bc, *bc2, *ab, *hpart, *h, *hz, *hg, *ho, *f1t;
    __nv_bfloat16 *x3th, *x3tl, *xnth, *xntl, *f1th, *f1tl, *w1h, *w1l, *w2h, *w2l, *wbch, *wbcl;
    cudaGetSymbolAddress((void**)&t0, g_t0);
    cudaGetSymbolAddress((void**)&x1, g_x1);
    cudaGetSymbolAddress((void**)&xn, g_xn);
    cudaGetSymbolAddress((void**)&x2, g_x2);
    cudaGetSymbolAddress((void**)&x3, g_x3);
    cudaGetSymbolAddress((void**)&bc, g_bcdt);
    cudaGetSymbolAddress((void**)&bc2, g_bcdt2);
    cudaGetSymbolAddress((void**)&ab, g_AB);
    cudaGetSymbolAddress((void**)&hpart, g_hpart);
    cudaGetSymbolAddress((void**)&h, g_h);
    cudaGetSymbolAddress((void**)&hz, g_hz);
    cudaGetSymbolAddress((void**)&hg, g_hg);
    cudaGetSymbolAddress((void**)&ho, g_ho);
    cudaGetSymbolAddress((void**)&f1t, g_f1t);
    cudaGetSymbolAddress((void**)&x3th, g_x3th);
    cudaGetSymbolAddress((void**)&x3tl, g_x3tl);
    cudaGetSymbolAddress((void**)&xnth, g_xnth);
    cudaGetSymbolAddress((void**)&xntl, g_xntl);
    cudaGetSymbolAddress((void**)&f1th, g_f1th);
    cudaGetSymbolAddress((void**)&f1tl, g_f1tl);
    cudaGetSymbolAddress((void**)&w1h, g_w1h);
    cudaGetSymbolAddress((void**)&w1l, g_w1l);
    cudaGetSymbolAddress((void**)&w2h, g_w2h);
    cudaGetSymbolAddress((void**)&w2l, g_w2l);
    cudaGetSymbolAddress((void**)&wbch, g_wbch);
    cudaGetSymbolAddress((void**)&wbcl, g_wbcl);

    cudaFuncSetAttribute(gemm_mma_kernel<0>, cudaFuncAttributeMaxDynamicSharedMemorySize, GSMEM);
    cudaFuncSetAttribute(gemm_mma_kernel<1>, cudaFuncAttributeMaxDynamicSharedMemorySize, GSMEM);

    dim3 blk2(64, 4);

    // weight splits
    wsplit_kernel<<<HIDDEN * DIM / 256, 256>>>(fc1_w, w1h, w1l);
    wsplit_kernel<<<DIM * HIDDEN / 256, 256>>>(fc2_w, w2h, w2l);
    wsplit_pad_kernel<<<256 * DIM / 256, 256>>>(bcdt_w, wbch, wbcl);

    // sub-layer 1: dwconv + LN+gate (+2nd LN), then transpose+split xn
    dwconv16_kernel<<<BATCH * DIM * L / 16 / 256, 256>>>(x, dw1_w, nullptr, t0, DIM);
    ln_gate_kernel<true><<<NPIX / 256, blk2>>>(t0, x, dw1_ln_w, dw1_ln_b, alpha, x1,
                                               ln_w, ln_b, xn);
    convt_kernel<<<dim3(L / 32, DIM / 64, BATCH), 256>>>(xn, xnth, xntl, DIM);

    // HSMSSD mixer
    gemm_mma_kernel<0><<<dim3(NPIX / 64, 3), 128, GSMEM>>>(wbch, wbcl, xnth, xntl, bc, bcdt_b, 192, 256);
    dwconv16_kernel<<<BATCH * 192 * L / 16 / 256, 256>>>(bc, dwm_w, dwm_b, bc2, 192);
    softmax_ab_kernel<<<BATCH * 64, 256>>>(bc2, ab);
    hgemm_kernel<<<dim3(BATCH, 4, NSEG), 256>>>(xn, ab, hpart);
    hreduce_kernel<<<BATCH * DIM * STATE / 256, 256>>>(hpart, h);
    gemm1x1_kernel<128><<<dim3(BATCH, 4), 256>>>(hz_w, hz_b, h, hz, 512, 256, 64);
    gate_kernel<<<BATCH * DIM * STATE / 256, 256>>>(hz, hg);
    gemm1x1_kernel<128><<<dim3(BATCH, 2), 256>>>(outp_w, outp_b, hg, ho, 256, 256, 64);
    y_fuse_kernel<<<PIXBLK, 256>>>(ho, bc2, xn, x1, Dp, alpha + 256, x2);

    // sub-layer 3: dwconv + LN+gate, then transpose+split x3
    dwconv16_kernel<<<BATCH * DIM * L / 16 / 256, 256>>>(x2, dw2_w, nullptr, t0, DIM);
    ln_gate_kernel<false><<<NPIX / 256, blk2>>>(t0, x2, dw2_ln_w, dw2_ln_b, alpha + 512, x3,
                                                nullptr, nullptr, nullptr);
    convt_kernel<<<dim3(L / 32, DIM / 64, BATCH), 256>>>(x3, x3th, x3tl, DIM);

    // FFN
    gemm_mma_kernel<1><<<dim3(NPIX / 64, HIDDEN / 64), 128, GSMEM>>>(w1h, w1l, x3th, x3tl, f1t, nullptr, HIDDEN, 256);
    ln_silu_split_kernel<<<NPIX / 8, 256>>>(f1t, f1th, f1tl, fc1_ln_w, fc1_ln_b);
    gemm_mma_kernel<0><<<dim3(NPIX / 64, 4), 128, GSMEM>>>(w2h, w2l, f1th, f1tl, t0, nullptr, 256, 1024);
    ln_gate_kernel<false><<<NPIX / 256, blk2>>>(t0, x3, fc2_ln_w, fc2_ln_b, alpha + 768, out,
                                                nullptr, nullptr, nullptr);

    // second output: h
    if (out_size >= BATCH * DIM * L + BATCH * DIM * STATE)
        copy_kernel<<<BATCH * DIM * STATE / 256, 256>>>(h, out + BATCH * DIM * L);
}